// round 2
// baseline (speedup 1.0000x reference)
#include <cuda_runtime.h>
#include <mma.h>
#include <math.h>

using namespace nvcuda;

#define BATCH 2
#define N1 2048
#define N2 512
#define NTOT 2560
#define D1 1024
#define D2 768
#define HEADS 16
#define DH 64
#define DI 1024

// ------------------------- scratch (device globals; no mallocs allowed) ----
__device__ __align__(256) float g_qkv1[BATCH * N1 * 3 * DI];
__device__ __align__(256) float g_qkv2[BATCH * N2 * 3 * DI];
__device__ __align__(256) float g_q[BATCH * HEADS * NTOT * DH];
__device__ __align__(256) float g_k[BATCH * HEADS * NTOT * DH];
__device__ __align__(256) float g_v[BATCH * HEADS * NTOT * DH];
__device__ __align__(256) float g_ao[BATCH * NTOT * DI];

__device__ __forceinline__ float to_tf32(float x) {
    float y;
    asm("cvt.rna.tf32.f32 %0, %1;" : "=f"(y) : "f"(x));
    return y;
}

// ------------------------------------------------------- split-tf32 GEMM ---
// C[M,N] = A'[M,K] @ W[K,N] row-major, A row remap r -> r + off + (r/chunk)*pad.
// 128x128 block tile, 8 warps (4M x 2N), warp tile 32x64.
// Split compensation: A=Ah+Al, B=Bh+Bl; acc += Ah*Bh + Ah*Bl + Al*Bh.
__global__ __launch_bounds__(256) void gemm_tf32(
    const float* __restrict__ A, const float* __restrict__ W,
    float* __restrict__ C, int M, int K, int N,
    int chunk, int pad, int off)
{
    __shared__ __align__(32) float Ah[128 * 20];
    __shared__ __align__(32) float Al[128 * 20];
    __shared__ __align__(32) float Bh[16 * 132];
    __shared__ __align__(32) float Bl[16 * 132];

    const int tid = threadIdx.x;
    const int bx = blockIdx.x, by = blockIdx.y;
    const int warpId = tid >> 5;
    const int wm = warpId & 3;          // 4 warps along M (32 rows each)
    const int wn = warpId >> 2;         // 2 warps along N (64 cols each)

    wmma::fragment<wmma::accumulator, 16, 16, 8, float> acc[2][4];
#pragma unroll
    for (int i = 0; i < 2; i++)
#pragma unroll
        for (int j = 0; j < 4; j++) wmma::fill_fragment(acc[i][j], 0.0f);

    const int aRow0 = by * 128;

    for (int k0 = 0; k0 < K; k0 += 16) {
#pragma unroll
        for (int l = 0; l < 2; l++) {
            int idx = tid + l * 256;
            // A tile: 128 rows x 16 k
            int ar = idx >> 2;
            int ac = (idx & 3) << 2;
            int grow = aRow0 + ar;
            grow = grow + off + (grow / chunk) * pad;
            float4 av = *(const float4*)(A + (size_t)grow * K + k0 + ac);
            float4 h4, l4;
            h4.x = to_tf32(av.x); l4.x = to_tf32(av.x - h4.x);
            h4.y = to_tf32(av.y); l4.y = to_tf32(av.y - h4.y);
            h4.z = to_tf32(av.z); l4.z = to_tf32(av.z - h4.z);
            h4.w = to_tf32(av.w); l4.w = to_tf32(av.w - h4.w);
            *(float4*)&Ah[ar * 20 + ac] = h4;
            *(float4*)&Al[ar * 20 + ac] = l4;
            // B tile: 16 k x 128 cols
            int br = idx >> 5;
            int bc = (idx & 31) << 2;
            float4 bv = *(const float4*)(W + (size_t)(k0 + br) * N + bx * 128 + bc);
            float4 bh4, bl4;
            bh4.x = to_tf32(bv.x); bl4.x = to_tf32(bv.x - bh4.x);
            bh4.y = to_tf32(bv.y); bl4.y = to_tf32(bv.y - bh4.y);
            bh4.z = to_tf32(bv.z); bl4.z = to_tf32(bv.z - bh4.z);
            bh4.w = to_tf32(bv.w); bl4.w = to_tf32(bv.w - bh4.w);
            *(float4*)&Bh[br * 132 + bc] = bh4;
            *(float4*)&Bl[br * 132 + bc] = bl4;
        }
        __syncthreads();

#pragma unroll
        for (int ks = 0; ks < 16; ks += 8) {
            wmma::fragment<wmma::matrix_a, 16, 16, 8, wmma::precision::tf32, wmma::row_major> ah[2], al[2];
            wmma::fragment<wmma::matrix_b, 16, 16, 8, wmma::precision::tf32, wmma::row_major> bh[4], bl[4];
#pragma unroll
            for (int i = 0; i < 2; i++) {
                wmma::load_matrix_sync(ah[i], Ah + (wm * 32 + i * 16) * 20 + ks, 20);
                wmma::load_matrix_sync(al[i], Al + (wm * 32 + i * 16) * 20 + ks, 20);
            }
#pragma unroll
            for (int j = 0; j < 4; j++) {
                wmma::load_matrix_sync(bh[j], Bh + ks * 132 + wn * 64 + j * 16, 132);
                wmma::load_matrix_sync(bl[j], Bl + ks * 132 + wn * 64 + j * 16, 132);
            }
#pragma unroll
            for (int i = 0; i < 2; i++)
#pragma unroll
                for (int j = 0; j < 4; j++) {
                    wmma::mma_sync(acc[i][j], ah[i], bh[j], acc[i][j]);
                    wmma::mma_sync(acc[i][j], ah[i], bl[j], acc[i][j]);
                    wmma::mma_sync(acc[i][j], al[i], bh[j], acc[i][j]);
                }
        }
        __syncthreads();
    }

#pragma unroll
    for (int i = 0; i < 2; i++)
#pragma unroll
        for (int j = 0; j < 4; j++) {
            int r0 = by * 128 + wm * 32 + i * 16;
            int c0 = bx * 128 + wn * 64 + j * 16;
            wmma::store_matrix_sync(C + (size_t)r0 * N + c0, acc[i][j], N, wmma::mem_row_major);
        }
}

// ----------------------------------------------- RMSNorm + QKV scatter -----
// One warp per (b,h,n). q gets attention scale folded: ||q_out||=1, ||k_out||=8.
__global__ __launch_bounds__(128) void rmsnorm_scatter(
    const float* __restrict__ gq1, const float* __restrict__ gk1,
    const float* __restrict__ gq2, const float* __restrict__ gk2)
{
    int warp = (blockIdx.x * blockDim.x + threadIdx.x) >> 5;
    int lane = threadIdx.x & 31;
    if (warp >= BATCH * HEADS * NTOT) return;
    int n = warp % NTOT;
    int bh = warp / NTOT;
    int h = bh % HEADS;
    int b = bh / HEADS;

    const float* src;
    const float *gq, *gk;
    if (n < N1) { src = g_qkv1 + (size_t)(b * N1 + n) * (3 * DI); gq = gq1; gk = gk1; }
    else        { src = g_qkv2 + (size_t)(b * N2 + (n - N1)) * (3 * DI); gq = gq2; gk = gk2; }

    size_t dst = ((size_t)(b * HEADS + h) * NTOT + n) * DH;
    int c0 = h * DH + lane;
    int c1 = c0 + 32;

    float q0 = src[c0], q1 = src[c1];
    float ss = q0 * q0 + q1 * q1;
#pragma unroll
    for (int o = 16; o > 0; o >>= 1) ss += __shfl_xor_sync(0xffffffffu, ss, o);
    float rq = __fdividef(1.0f, fmaxf(sqrtf(ss), 1e-12f));
    g_q[dst + lane]      = q0 * rq * gq[c0];
    g_q[dst + lane + 32] = q1 * rq * gq[c1];

    float k0 = src[DI + c0], k1 = src[DI + c1];
    float sk = k0 * k0 + k1 * k1;
#pragma unroll
    for (int o = 16; o > 0; o >>= 1) sk += __shfl_xor_sync(0xffffffffu, sk, o);
    float rk = __fdividef(8.0f, fmaxf(sqrtf(sk), 1e-12f));
    g_k[dst + lane]      = k0 * rk * gk[c0];
    g_k[dst + lane + 32] = k1 * rk * gk[c1];

    g_v[dst + lane]      = src[2 * DI + c0];
    g_v[dst + lane + 32] = src[2 * DI + c1];
}

// ------------------------------------------------------ flash attention ----
// 128 threads (4 warps), 64 q-rows per block, 64-wide k tiles, DH=64.
// QK^T with split-tf32 (exact to ~2^-22), PV plain tf32.
// sim bounded in [-8,8] (norms folded) -> fixed softmax max = 8, no rescale.
#define LDP 68
#define ATTN_SMEM (6 * 64 * LDP * 4)

__global__ __launch_bounds__(128) void attn_tf32(float* __restrict__ Out)
{
    extern __shared__ __align__(128) float sm[];
    float* Qh = sm;
    float* Ql = Qh + 64 * LDP;
    float* Kh = Ql + 64 * LDP;
    float* Kl = Kh + 64 * LDP;
    float* Vt = Kl + 64 * LDP;
    float* Pt = Vt + 64 * LDP;

    const int tid = threadIdx.x;
    const int w = tid >> 5;
    const int qt = blockIdx.x, h = blockIdx.y, b = blockIdx.z;
    const size_t bhOff = ((size_t)(b * HEADS + h)) * NTOT * DH;
    const float* Qg = g_q + bhOff + (size_t)qt * 64 * DH;

    // load Q tile, split hi/lo
#pragma unroll
    for (int l = 0; l < 8; l++) {
        int idx = l * 128 + tid;
        int row = idx >> 4;
        int c4 = (idx & 15) << 2;
        float4 v = *(const float4*)(Qg + row * DH + c4);
        float4 h4, l4;
        h4.x = to_tf32(v.x); l4.x = to_tf32(v.x - h4.x);
        h4.y = to_tf32(v.y); l4.y = to_tf32(v.y - h4.y);
        h4.z = to_tf32(v.z); l4.z = to_tf32(v.z - h4.z);
        h4.w = to_tf32(v.w); l4.w = to_tf32(v.w - h4.w);
        *(float4*)&Qh[row * LDP + c4] = h4;
        *(float4*)&Ql[row * LDP + c4] = l4;
    }

    wmma::fragment<wmma::accumulator, 16, 16, 8, float> Oacc[4];
#pragma unroll
    for (int j = 0; j < 4; j++) wmma::fill_fragment(Oacc[j], 0.0f);

    float lreg = 0.0f;
    const int erow = tid >> 1;
    const int ecb = (tid & 1) << 5;

    for (int kt = 0; kt < NTOT / 64; kt++) {
        __syncthreads();
        const float* Kg = g_k + bhOff + (size_t)kt * 64 * DH;
        const float* Vg = g_v + bhOff + (size_t)kt * 64 * DH;
#pragma unroll
        for (int l = 0; l < 8; l++) {
            int idx = l * 128 + tid;
            int row = idx >> 4;
            int c4 = (idx & 15) << 2;
            float4 kv = *(const float4*)(Kg + row * DH + c4);
            float4 h4, l4;
            h4.x = to_tf32(kv.x); l4.x = to_tf32(kv.x - h4.x);
            h4.y = to_tf32(kv.y); l4.y = to_tf32(kv.y - h4.y);
            h4.z = to_tf32(kv.z); l4.z = to_tf32(kv.z - h4.z);
            h4.w = to_tf32(kv.w); l4.w = to_tf32(kv.w - h4.w);
            *(float4*)&Kh[row * LDP + c4] = h4;
            *(float4*)&Kl[row * LDP + c4] = l4;
            float4 vv = *(const float4*)(Vg + row * DH + c4);
            vv.x = to_tf32(vv.x); vv.y = to_tf32(vv.y);
            vv.z = to_tf32(vv.z); vv.w = to_tf32(vv.w);
            *(float4*)&Vt[row * LDP + c4] = vv;
        }
        __syncthreads();

        // S = Q @ K^T (split-tf32)
        wmma::fragment<wmma::accumulator, 16, 16, 8, float> S[4];
#pragma unroll
        for (int j = 0; j < 4; j++) wmma::fill_fragment(S[j], 0.0f);
#pragma unroll
        for (int ks = 0; ks < 8; ks++) {
            int k0 = ks * 8;
            wmma::fragment<wmma::matrix_a, 16, 16, 8, wmma::precision::tf32, wmma::row_major> ah, al;
            wmma::load_matrix_sync(ah, Qh + (w * 16) * LDP + k0, LDP);
            wmma::load_matrix_sync(al, Ql + (w * 16) * LDP + k0, LDP);
#pragma unroll
            for (int j = 0; j < 4; j++) {
                wmma::fragment<wmma::matrix_b, 16, 16, 8, wmma::precision::tf32, wmma::col_major> bh, bl;
                wmma::load_matrix_sync(bh, Kh + (j * 16) * LDP + k0, LDP);
                wmma::load_matrix_sync(bl, Kl + (j * 16) * LDP + k0, LDP);
                wmma::mma_sync(S[j], ah, bh, S[j]);
                wmma::mma_sync(S[j], ah, bl, S[j]);
                wmma::mma_sync(S[j], al, bh, S[j]);
            }
        }
#pragma unroll
        for (int j = 0; j < 4; j++)
            wmma::store_matrix_sync(Pt + (w * 16) * LDP + j * 16, S[j], LDP, wmma::mem_row_major);
        __syncthreads();

        // softclamp (tanh poly) + exp with fixed max 8; row sums
        {
            float rs = 0.0f;
            float* prow = Pt + erow * LDP + ecb;
#pragma unroll
            for (int c = 0; c < 32; c++) {
                float s = prow[c];
                float u = s * 0.02f;
                float u2 = u * u;
                float cl = s * (1.0f - u2 * 0.33333334f + u2 * u2 * 0.13333334f);
                float p = __expf(cl - 8.0f);
                rs += p;
                prow[c] = to_tf32(p);
            }
            lreg += rs;
        }
        __syncthreads();

        // O += P @ V (plain tf32)
#pragma unroll
        for (int ks = 0; ks < 8; ks++) {
            int j0 = ks * 8;
            wmma::fragment<wmma::matrix_a, 16, 16, 8, wmma::precision::tf32, wmma::row_major> pa;
            wmma::load_matrix_sync(pa, Pt + (w * 16) * LDP + j0, LDP);
#pragma unroll
            for (int n = 0; n < 4; n++) {
                wmma::fragment<wmma::matrix_b, 16, 16, 8, wmma::precision::tf32, wmma::row_major> vb;
                wmma::load_matrix_sync(vb, Vt + j0 * LDP + n * 16, LDP);
                wmma::mma_sync(Oacc[n], pa, vb, Oacc[n]);
            }
        }
    }

    // epilogue: normalize rows, write to [b][n][h*64+d]
    float lrow = lreg + __shfl_xor_sync(0xffffffffu, lreg, 1);
    float inv = 1.0f / lrow;

    __syncthreads();
#pragma unroll
    for (int n = 0; n < 4; n++)
        wmma::store_matrix_sync(Pt + (w * 16) * LDP + n * 16, Oacc[n], LDP, wmma::mem_row_major);
    __syncthreads();

    {
        int ng = qt * 64 + erow;
        float* dst = Out + ((size_t)(b * NTOT + ng)) * DI + h * DH + ecb;
        const float* prow = Pt + erow * LDP + ecb;
#pragma unroll
        for (int c = 0; c < 32; c += 4) {
            float4 v;
            v.x = prow[c + 0] * inv;
            v.y = prow[c + 1] * inv;
            v.z = prow[c + 2] * inv;
            v.w = prow[c + 3] * inv;
            *(float4*)(dst + c) = v;
        }
    }
}

// ------------------------------------------------------------- launcher ----
extern "C" void kernel_launch(void* const* d_in, const int* in_sizes, int n_in,
                              void* d_out, int out_size)
{
    (void)in_sizes; (void)n_in; (void)out_size;
    const float* x1    = (const float*)d_in[0];
    const float* x2    = (const float*)d_in[1];
    const float* Wqkv1 = (const float*)d_in[4];
    const float* Wqkv2 = (const float*)d_in[5];
    const float* gq1   = (const float*)d_in[6];
    const float* gk1   = (const float*)d_in[7];
    const float* gq2   = (const float*)d_in[8];
    const float* gk2   = (const float*)d_in[9];
    const float* Wout1 = (const float*)d_in[10];
    const float* Wout2 = (const float*)d_in[11];
    float* out = (float*)d_out;

    float *qkv1, *qkv2, *ao;
    cudaGetSymbolAddress((void**)&qkv1, g_qkv1);
    cudaGetSymbolAddress((void**)&qkv2, g_qkv2);
    cudaGetSymbolAddress((void**)&ao,   g_ao);

    cudaFuncSetAttribute(attn_tf32, cudaFuncAttributeMaxDynamicSharedMemorySize, ATTN_SMEM);

    const int BIG = 1 << 30;

    // 1) QKV projections (split-tf32 GEMM)
    gemm_tf32<<<dim3(3 * DI / 128, BATCH * N1 / 128), 256>>>(
        x1, Wqkv1, qkv1, BATCH * N1, D1, 3 * DI, BIG, 0, 0);
    gemm_tf32<<<dim3(3 * DI / 128, BATCH * N2 / 128), 256>>>(
        x2, Wqkv2, qkv2, BATCH * N2, D2, 3 * DI, BIG, 0, 0);

    // 2) RMSNorm + scatter (q scale folded)
    rmsnorm_scatter<<<BATCH * HEADS * NTOT / 4, 128>>>(gq1, gk1, gq2, gk2);

    // 3) attention -> g_ao
    attn_tf32<<<dim3(NTOT / 64, HEADS, BATCH), 128, ATTN_SMEM>>>(ao);

    // 4) output projections (row-remapped reads of the concat buffer)
    gemm_tf32<<<dim3(D1 / 128, BATCH * N1 / 128), 256>>>(
        ao, Wout1, out, BATCH * N1, DI, D1, 2048, 512, 0);
    gemm_tf32<<<dim3(D2 / 128, BATCH * N2 / 128), 256>>>(
        ao, Wout2, out + (size_t)BATCH * N1 * D1, BATCH * N2, DI, D2, 512, 2048, 2048);
}

// round 4
// speedup vs baseline: 3.0529x; 3.0529x over previous
#include <cuda_runtime.h>
#include <cuda_bf16.h>
#include <cstdint>
#include <math.h>

#define BATCH 2
#define N1 2048
#define N2 512
#define NTOT 2560
#define D1 1024
#define D2 768
#define HEADS 16
#define DH 64
#define DI 1024
#define BH (BATCH * HEADS)

// ===================== scratch (device globals) =====================
__device__ __align__(256) __nv_bfloat16 g_x1h[BATCH*N1*D1], g_x1l[BATCH*N1*D1];
__device__ __align__(256) __nv_bfloat16 g_x2h[BATCH*N2*D2], g_x2l[BATCH*N2*D2];
__device__ __align__(256) __nv_bfloat16 g_w1h[3*DI*D1],  g_w1l[3*DI*D1];    // Wqkv1^T [3072][1024]
__device__ __align__(256) __nv_bfloat16 g_w2h[3*DI*D2],  g_w2l[3*DI*D2];    // Wqkv2^T [3072][768]
__device__ __align__(256) __nv_bfloat16 g_wo1h[D1*DI],   g_wo1l[D1*DI];     // Wout1^T [1024][1024]
__device__ __align__(256) __nv_bfloat16 g_wo2h[D2*DI],   g_wo2l[D2*DI];     // Wout2^T [768][1024]
__device__ __align__(256) float g_qkv1[BATCH*N1*3*DI];
__device__ __align__(256) float g_qkv2[BATCH*N2*3*DI];
__device__ __align__(256) __nv_bfloat16 g_qh[BH*NTOT*DH], g_ql[BH*NTOT*DH];
__device__ __align__(256) __nv_bfloat16 g_kh[BH*NTOT*DH], g_kl[BH*NTOT*DH];
__device__ __align__(256) float g_vf[BH*NTOT*DH];
__device__ __align__(256) __nv_bfloat16 g_vth[BH*DH*NTOT], g_vtl[BH*DH*NTOT]; // [bh][d][n]
__device__ __align__(256) __nv_bfloat16 g_aoh[BATCH*NTOT*DI], g_aol[BATCH*NTOT*DI];

// ===================== helpers =====================
__device__ __forceinline__ uint32_t smem_u32(const void* p) {
    uint32_t a;
    asm("{ .reg .u64 t; cvta.to.shared.u64 t, %1; cvt.u32.u64 %0, t; }" : "=r"(a) : "l"(p));
    return a;
}
__device__ __forceinline__ uint32_t pack_bf2(__nv_bfloat16 a, __nv_bfloat16 b) {
    return (uint32_t)__bfloat16_as_ushort(a) | ((uint32_t)__bfloat16_as_ushort(b) << 16);
}
// tile: [rows][64] bf16, 128B rows, 16B chunks swizzled c ^ (r&7)
__device__ __forceinline__ uint32_t chunk_off(int r, int c) {
    return (uint32_t)(((r << 3) + (c ^ (r & 7))) << 4);
}
__device__ __forceinline__ void ldsm4(uint32_t (&d)[4], uint32_t a) {
    asm volatile("ldmatrix.sync.aligned.m8n8.x4.shared.b16 {%0,%1,%2,%3}, [%4];"
        : "=r"(d[0]), "=r"(d[1]), "=r"(d[2]), "=r"(d[3]) : "r"(a));
}
// A m16k16 frag at (row0,k0): mats (mLo,kLo),(mHi,kLo),(mLo,kHi),(mHi,kHi)
__device__ __forceinline__ void ldsmA(uint32_t (&d)[4], uint32_t tile, int row0, int k0, int lane) {
    int g = lane >> 3;
    int r = row0 + (lane & 7) + ((g & 1) << 3);
    int c = (k0 >> 3) + (g >> 1);
    ldsm4(d, tile + chunk_off(r, c));
}
// B: two n8 frags (n16 at (n0,k0)): mats (nLo,kLo),(nLo,kHi),(nHi,kLo),(nHi,kHi)
__device__ __forceinline__ void ldsmB(uint32_t (&d)[4], uint32_t tile, int n0, int k0, int lane) {
    int g = lane >> 3;
    int r = n0 + (lane & 7) + ((g >> 1) << 3);
    int c = (k0 >> 3) + (g & 1);
    ldsm4(d, tile + chunk_off(r, c));
}
__device__ __forceinline__ void mma16816(float (&c)[4], const uint32_t (&a)[4], const uint32_t* b) {
    asm volatile("mma.sync.aligned.m16n8k16.row.col.f32.bf16.bf16.f32 "
        "{%0,%1,%2,%3}, {%4,%5,%6,%7}, {%8,%9}, {%0,%1,%2,%3};"
        : "+f"(c[0]), "+f"(c[1]), "+f"(c[2]), "+f"(c[3])
        : "r"(a[0]), "r"(a[1]), "r"(a[2]), "r"(a[3]), "r"(b[0]), "r"(b[1]));
}
// exp(50*tanh(s/50) - 8) with |s|<=8.5, FMA-only (no MUFU)
__device__ __forceinline__ float softclamp_exp(float s) {
    float u2 = s * s * 4.0e-4f;
    float cl = s * fmaf(u2, fmaf(u2, 0.13333334f, -0.33333334f), 1.0f);
    float y = fmaf(cl, 1.44269504f, -11.54156036f);   // (cl-8)*log2e
    float r = y + 12582912.0f;                         // round-to-nearest int
    int n = __float_as_int(r) - 0x4B400000;
    float f = y - (r - 12582912.0f);
    float p = fmaf(f, fmaf(f, fmaf(f, fmaf(f, fmaf(f, 1.3333558e-3f, 9.6181291e-3f),
                 5.5504109e-2f), 2.4022651e-1f), 6.9314718e-1f), 1.0f);
    return __int_as_float(__float_as_int(p) + (n << 23));
}

// ===================== pre-pass: split f32 -> bf16 hi/lo =====================
__global__ __launch_bounds__(256) void split_rows(const float* __restrict__ in,
    __nv_bfloat16* __restrict__ hi, __nv_bfloat16* __restrict__ lo, int n)
{
    int i = (blockIdx.x * 256 + threadIdx.x) * 4;
    if (i >= n) return;
    float4 v = *(const float4*)(in + i);
    __nv_bfloat16 h0 = __float2bfloat16_rn(v.x), h1 = __float2bfloat16_rn(v.y);
    __nv_bfloat16 h2 = __float2bfloat16_rn(v.z), h3 = __float2bfloat16_rn(v.w);
    uint2 wh = make_uint2(pack_bf2(h0, h1), pack_bf2(h2, h3));
    uint2 wl = make_uint2(
        pack_bf2(__float2bfloat16_rn(v.x - __bfloat162float(h0)), __float2bfloat16_rn(v.y - __bfloat162float(h1))),
        pack_bf2(__float2bfloat16_rn(v.z - __bfloat162float(h2)), __float2bfloat16_rn(v.w - __bfloat162float(h3))));
    *(uint2*)(hi + i) = wh;
    *(uint2*)(lo + i) = wl;
}

// ===================== pre-pass: transpose + split W[K][N] -> T[N][K] =======
__global__ __launch_bounds__(256) void wtrans(const float* __restrict__ W,
    __nv_bfloat16* __restrict__ th, __nv_bfloat16* __restrict__ tl, int K, int N)
{
    __shared__ float t[32][33];
    int tx = threadIdx.x, ty = threadIdx.y;
    int n0 = blockIdx.x * 32, k0 = blockIdx.y * 32;
#pragma unroll
    for (int i = ty; i < 32; i += 8)
        t[i][tx] = W[(size_t)(k0 + i) * N + n0 + tx];
    __syncthreads();
#pragma unroll
    for (int i = ty; i < 32; i += 8) {
        float v = t[tx][i];
        __nv_bfloat16 h = __float2bfloat16_rn(v);
        size_t o = (size_t)(n0 + i) * K + k0 + tx;
        th[o] = h;
        tl[o] = __float2bfloat16_rn(v - __bfloat162float(h));
    }
}

// ===================== split-bf16 HMMA GEMM =====================
// C[M,N] = A[M,K] @ Bt[N,K]^T, A row remap r -> r + off + (r/chunk)*pad.
// 128x128 block (256 thr, 8 warps 4m x 2n), k-tiles of 64.
#define GO_AH 0
#define GO_AL 16384
#define GO_BH 32768
#define GO_BL 49152
#define GEMM_SMEM 65536

__global__ __launch_bounds__(256) void gemm_mma(
    const __nv_bfloat16* __restrict__ Ah, const __nv_bfloat16* __restrict__ Al,
    const __nv_bfloat16* __restrict__ Bh, const __nv_bfloat16* __restrict__ Bl,
    float* __restrict__ C, int M, int K, int N, int chunk, int pad, int off)
{
    extern __shared__ char sm[];
    const uint32_t sb = smem_u32(sm);
    const int tid = threadIdx.x;
    const int lane = tid & 31;
    const int w = tid >> 5;
    const int wm = w & 3, wn = w >> 2;
    const int bx = blockIdx.x, by = blockIdx.y;

    float acc[2][8][4];
#pragma unroll
    for (int i = 0; i < 2; i++)
#pragma unroll
        for (int j = 0; j < 8; j++)
#pragma unroll
            for (int q = 0; q < 4; q++) acc[i][j][q] = 0.0f;

    const int ktiles = K >> 6;
    for (int kt = 0; kt < ktiles; kt++) {
#pragma unroll
        for (int i = 0; i < 4; i++) {
            int idx = i * 256 + tid;
            int r = idx >> 3, c = idx & 7;
            uint32_t so = chunk_off(r, c);
            int gr = by * 128 + r;
            gr = gr + off + (gr / chunk) * pad;
            size_t ao = (size_t)gr * K + kt * 64 + c * 8;
            *(uint4*)(sm + GO_AH + so) = *(const uint4*)(Ah + ao);
            *(uint4*)(sm + GO_AL + so) = *(const uint4*)(Al + ao);
            size_t bo = (size_t)(bx * 128 + r) * K + kt * 64 + c * 8;
            *(uint4*)(sm + GO_BH + so) = *(const uint4*)(Bh + bo);
            *(uint4*)(sm + GO_BL + so) = *(const uint4*)(Bl + bo);
        }
        __syncthreads();
#pragma unroll
        for (int ks = 0; ks < 4; ks++) {
            int k0 = ks * 16;
            uint32_t ahf[2][4], alf[2][4];
            ldsmA(ahf[0], sb + GO_AH, wm * 32, k0, lane);
            ldsmA(ahf[1], sb + GO_AH, wm * 32 + 16, k0, lane);
            ldsmA(alf[0], sb + GO_AL, wm * 32, k0, lane);
            ldsmA(alf[1], sb + GO_AL, wm * 32 + 16, k0, lane);
#pragma unroll
            for (int nb = 0; nb < 4; nb++) {
                uint32_t bhf[4], blf[4];
                ldsmB(bhf, sb + GO_BH, wn * 64 + nb * 16, k0, lane);
                ldsmB(blf, sb + GO_BL, wn * 64 + nb * 16, k0, lane);
#pragma unroll
                for (int mi = 0; mi < 2; mi++) {
                    mma16816(acc[mi][2 * nb],     ahf[mi], bhf);
                    mma16816(acc[mi][2 * nb + 1], ahf[mi], bhf + 2);
                    mma16816(acc[mi][2 * nb],     ahf[mi], blf);
                    mma16816(acc[mi][2 * nb + 1], ahf[mi], blf + 2);
                    mma16816(acc[mi][2 * nb],     alf[mi], bhf);
                    mma16816(acc[mi][2 * nb + 1], alf[mi], bhf + 2);
                }
            }
        }
        __syncthreads();
    }

#pragma unroll
    for (int mi = 0; mi < 2; mi++)
#pragma unroll
        for (int nf = 0; nf < 8; nf++) {
            int row = by * 128 + wm * 32 + mi * 16 + (lane >> 2);
            int col = bx * 128 + wn * 64 + nf * 8 + ((lane & 3) << 1);
            *(float2*)(C + (size_t)row * N + col) = make_float2(acc[mi][nf][0], acc[mi][nf][1]);
            *(float2*)(C + (size_t)(row + 8) * N + col) = make_float2(acc[mi][nf][2], acc[mi][nf][3]);
        }
}

// ===================== RMSNorm + scatter (bf16 splits) =====================
__global__ __launch_bounds__(128) void rmsnorm_scatter(
    const float* __restrict__ gq1, const float* __restrict__ gk1,
    const float* __restrict__ gq2, const float* __restrict__ gk2)
{
    int warp = (blockIdx.x * blockDim.x + threadIdx.x) >> 5;
    int lane = threadIdx.x & 31;
    if (warp >= BH * NTOT) return;
    int n = warp % NTOT;
    int bh = warp / NTOT;
    int h = bh % HEADS;
    int b = bh / HEADS;

    const float* src;
    const float *gq, *gk;
    if (n < N1) { src = g_qkv1 + (size_t)(b * N1 + n) * (3 * DI); gq = gq1; gk = gk1; }
    else        { src = g_qkv2 + (size_t)(b * N2 + (n - N1)) * (3 * DI); gq = gq2; gk = gk2; }

    size_t dst = ((size_t)bh * NTOT + n) * DH;
    int c0 = h * DH + lane;
    int c1 = c0 + 32;

    float q0 = src[c0], q1 = src[c1];
    float ss = q0 * q0 + q1 * q1;
#pragma unroll
    for (int o = 16; o > 0; o >>= 1) ss += __shfl_xor_sync(0xffffffffu, ss, o);
    float rq = __fdividef(1.0f, fmaxf(sqrtf(ss), 1e-12f));   // ||q||=1 (1/8 scale folded)
    float qa = q0 * rq * gq[c0], qb = q1 * rq * gq[c1];
    {
        __nv_bfloat16 h0 = __float2bfloat16_rn(qa), h1 = __float2bfloat16_rn(qb);
        g_qh[dst + lane] = h0; g_qh[dst + lane + 32] = h1;
        g_ql[dst + lane]      = __float2bfloat16_rn(qa - __bfloat162float(h0));
        g_ql[dst + lane + 32] = __float2bfloat16_rn(qb - __bfloat162float(h1));
    }

    float k0 = src[DI + c0], k1 = src[DI + c1];
    float sk = k0 * k0 + k1 * k1;
#pragma unroll
    for (int o = 16; o > 0; o >>= 1) sk += __shfl_xor_sync(0xffffffffu, sk, o);
    float rk = __fdividef(8.0f, fmaxf(sqrtf(sk), 1e-12f));   // ||k||=8
    float ka = k0 * rk * gk[c0], kb = k1 * rk * gk[c1];
    {
        __nv_bfloat16 h0 = __float2bfloat16_rn(ka), h1 = __float2bfloat16_rn(kb);
        g_kh[dst + lane] = h0; g_kh[dst + lane + 32] = h1;
        g_kl[dst + lane]      = __float2bfloat16_rn(ka - __bfloat162float(h0));
        g_kl[dst + lane + 32] = __float2bfloat16_rn(kb - __bfloat162float(h1));
    }

    g_vf[dst + lane]      = src[2 * DI + c0];
    g_vf[dst + lane + 32] = src[2 * DI + c1];
}

// ===================== V transpose: [bh][n][d] f32 -> [bh][d][n] bf16 hi/lo =
__global__ __launch_bounds__(256) void vtrans()
{
    __shared__ float t[32][33];
    int tx = threadIdx.x, ty = threadIdx.y;
    int n0 = blockIdx.x * 32, d0 = blockIdx.y * 32, bh = blockIdx.z;
    const float* in = g_vf + (size_t)bh * NTOT * DH;
#pragma unroll
    for (int i = ty; i < 32; i += 8)
        t[i][tx] = in[(size_t)(n0 + i) * DH + d0 + tx];
    __syncthreads();
    size_t ob = (size_t)bh * DH * NTOT;
#pragma unroll
    for (int i = ty; i < 32; i += 8) {
        float v = t[tx][i];
        __nv_bfloat16 h = __float2bfloat16_rn(v);
        size_t o = ob + (size_t)(d0 + i) * NTOT + n0 + tx;
        g_vth[o] = h;
        g_vtl[o] = __float2bfloat16_rn(v - __bfloat162float(h));
    }
}

// ===================== HMMA flash attention =====================
// 256 thr (8 warps), 128 q rows x 128 key tile, DH=64. Warp owns 16 q rows.
// Fixed softmax max = 8 (norms folded) -> no online rescale.
// smem: KH/KL: [128 keys][64 dh]; VH/VL: two subtiles [64 d][64 k] each.
#define AO_KH 0
#define AO_KL 16384
#define AO_VH 32768
#define AO_VL 49152
#define ATT_SMEM 65536

__global__ __launch_bounds__(256) void attn_mma()
{
    extern __shared__ char sm[];
    const uint32_t sb = smem_u32(sm);
    const int tid = threadIdx.x;
    const int lane = tid & 31;
    const int w = tid >> 5;
    const int qt = blockIdx.x, h = blockIdx.y, b = blockIdx.z;
    const int bh = b * HEADS + h;

    // ---- stage Q into KH/KL, extract frags to registers ----
    uint32_t qhf[4][4], qlf[4][4];
    {
        const __nv_bfloat16* qh = g_qh + ((size_t)bh * NTOT + qt * 128) * DH;
        const __nv_bfloat16* ql = g_ql + ((size_t)bh * NTOT + qt * 128) * DH;
#pragma unroll
        for (int i = 0; i < 4; i++) {
            int idx = i * 256 + tid;
            int r = idx >> 3, c = idx & 7;
            uint32_t so = chunk_off(r, c);
            size_t go = (size_t)r * DH + c * 8;
            *(uint4*)(sm + AO_KH + so) = *(const uint4*)(qh + go);
            *(uint4*)(sm + AO_KL + so) = *(const uint4*)(ql + go);
        }
        __syncthreads();
#pragma unroll
        for (int ks = 0; ks < 4; ks++) {
            ldsmA(qhf[ks], sb + AO_KH, w * 16, ks * 16, lane);
            ldsmA(qlf[ks], sb + AO_KL, w * 16, ks * 16, lane);
        }
        __syncthreads();
    }

    float O[8][4];
#pragma unroll
    for (int j = 0; j < 8; j++)
#pragma unroll
        for (int q = 0; q < 4; q++) O[j][q] = 0.0f;
    float lsum0 = 0.0f, lsum1 = 0.0f;

    const size_t kbase = (size_t)bh * NTOT * DH;
    const size_t vbase = (size_t)bh * DH * NTOT;

    for (int kt = 0; kt < NTOT / 128; kt++) {
        // ---- load K tile + Vt tile ----
        const __nv_bfloat16* kh = g_kh + kbase + (size_t)kt * 128 * DH;
        const __nv_bfloat16* kl = g_kl + kbase + (size_t)kt * 128 * DH;
#pragma unroll
        for (int i = 0; i < 4; i++) {
            int idx = i * 256 + tid;
            int r = idx >> 3, c = idx & 7;
            uint32_t so = chunk_off(r, c);
            size_t go = (size_t)r * DH + c * 8;
            *(uint4*)(sm + AO_KH + so) = *(const uint4*)(kh + go);
            *(uint4*)(sm + AO_KL + so) = *(const uint4*)(kl + go);
            // Vt: d rows 64, 16 k-chunks -> two [64][64] subtiles
            int d = idx >> 4, ch = idx & 15;
            uint32_t vo = (uint32_t)((ch >> 3) * 8192) + chunk_off(d, ch & 7);
            size_t vg = vbase + (size_t)d * NTOT + kt * 128 + ch * 8;
            *(uint4*)(sm + AO_VH + vo) = *(const uint4*)(g_vth + vg);
            *(uint4*)(sm + AO_VL + vo) = *(const uint4*)(g_vtl + vg);
        }
        __syncthreads();

        // ---- S = Q K^T (split-3) ----
        float S[16][4];
#pragma unroll
        for (int j = 0; j < 16; j++)
#pragma unroll
            for (int q = 0; q < 4; q++) S[j][q] = 0.0f;
#pragma unroll
        for (int ks = 0; ks < 4; ks++) {
            int k0 = ks * 16;
#pragma unroll
            for (int nb = 0; nb < 8; nb++) {
                uint32_t bhf[4], blf[4];
                ldsmB(bhf, sb + AO_KH, nb * 16, k0, lane);
                ldsmB(blf, sb + AO_KL, nb * 16, k0, lane);
                mma16816(S[2 * nb],     qhf[ks], bhf);
                mma16816(S[2 * nb + 1], qhf[ks], bhf + 2);
                mma16816(S[2 * nb],     qhf[ks], blf);
                mma16816(S[2 * nb + 1], qhf[ks], blf + 2);
                mma16816(S[2 * nb],     qlf[ks], bhf);
                mma16816(S[2 * nb + 1], qlf[ks], bhf + 2);
            }
        }

        // ---- softclamp + exp (fixed max 8), row sums ----
        float rs0 = 0.0f, rs1 = 0.0f;
#pragma unroll
        for (int j = 0; j < 16; j++) {
            S[j][0] = softclamp_exp(S[j][0]); rs0 += S[j][0];
            S[j][1] = softclamp_exp(S[j][1]); rs0 += S[j][1];
            S[j][2] = softclamp_exp(S[j][2]); rs1 += S[j][2];
            S[j][3] = softclamp_exp(S[j][3]); rs1 += S[j][3];
        }
        rs0 += __shfl_xor_sync(0xffffffffu, rs0, 1);
        rs0 += __shfl_xor_sync(0xffffffffu, rs0, 2);
        rs1 += __shfl_xor_sync(0xffffffffu, rs1, 1);
        rs1 += __shfl_xor_sync(0xffffffffu, rs1, 2);
        lsum0 += rs0;
        lsum1 += rs1;

        // ---- O += P V (split-3): convert P acc->A frags per k16 ----
#pragma unroll
        for (int kk = 0; kk < 8; kk++) {
            uint32_t ah4[4], al4[4];
#pragma unroll
            for (int q = 0; q < 4; q++) {
                float p0 = S[2 * kk + (q >> 1)][(q & 1) * 2];
                float p1 = S[2 * kk + (q >> 1)][(q & 1) * 2 + 1];
                __nv_bfloat16 h0 = __float2bfloat16_rn(p0);
                __nv_bfloat16 h1 = __float2bfloat16_rn(p1);
                ah4[q] = pack_bf2(h0, h1);
                al4[q] = pack_bf2(__float2bfloat16_rn(p0 - __bfloat162float(h0)),
                                  __float2bfloat16_rn(p1 - __bfloat162float(h1)));
            }
            int k0 = kk * 16;
            uint32_t vth_t = sb + AO_VH + ((k0 >> 6) * 8192);
            uint32_t vtl_t = sb + AO_VL + ((k0 >> 6) * 8192);
            int k0e = k0 & 63;
#pragma unroll
            for (int nb = 0; nb < 4; nb++) {
                uint32_t vh4[4], vl4[4];
                ldsmB(vh4, vth_t, nb * 16, k0e, lane);
                ldsmB(vl4, vtl_t, nb * 16, k0e, lane);
                mma16816(O[2 * nb],     ah4, vh4);
                mma16816(O[2 * nb + 1], ah4, vh4 + 2);
                mma16816(O[2 * nb],     ah4, vl4);
                mma16816(O[2 * nb + 1], ah4, vl4 + 2);
                mma16816(O[2 * nb],     al4, vh4);
                mma16816(O[2 * nb + 1], al4, vh4 + 2);
            }
        }
        __syncthreads();
    }

    // ---- epilogue: normalize, write split-bf16 to g_ao ----
    float inv0 = __fdividef(1.0f, lsum0);
    float inv1 = __fdividef(1.0f, lsum1);
    int rlo = qt * 128 + w * 16 + (lane >> 2);
    int colb = h * DH + ((lane & 3) << 1);
    size_t o_lo = ((size_t)(b * NTOT + rlo)) * DI + colb;
    size_t o_hi = ((size_t)(b * NTOT + rlo + 8)) * DI + colb;
#pragma unroll
    for (int nf = 0; nf < 8; nf++) {
        float v0 = O[nf][0] * inv0, v1 = O[nf][1] * inv0;
        __nv_bfloat16 h0 = __float2bfloat16_rn(v0), h1 = __float2bfloat16_rn(v1);
        *(uint32_t*)(g_aoh + o_lo + nf * 8) = pack_bf2(h0, h1);
        *(uint32_t*)(g_aol + o_lo + nf * 8) = pack_bf2(
            __float2bfloat16_rn(v0 - __bfloat162float(h0)),
            __float2bfloat16_rn(v1 - __bfloat162float(h1)));
        float v2 = O[nf][2] * inv1, v3 = O[nf][3] * inv1;
        __nv_bfloat16 h2 = __float2bfloat16_rn(v2), h3 = __float2bfloat16_rn(v3);
        *(uint32_t*)(g_aoh + o_hi + nf * 8) = pack_bf2(h2, h3);
        *(uint32_t*)(g_aol + o_hi + nf * 8) = pack_bf2(
            __float2bfloat16_rn(v2 - __bfloat162float(h2)),
            __float2bfloat16_rn(v3 - __bfloat162float(h3)));
    }
}

// ===================== launcher =====================
extern "C" void kernel_launch(void* const* d_in, const int* in_sizes, int n_in,
                              void* d_out, int out_size)
{
    (void)in_sizes; (void)n_in; (void)out_size;
    const float* x1    = (const float*)d_in[0];
    const float* x2    = (const float*)d_in[1];
    const float* Wqkv1 = (const float*)d_in[4];
    const float* Wqkv2 = (const float*)d_in[5];
    const float* gq1   = (const float*)d_in[6];
    const float* gk1   = (const float*)d_in[7];
    const float* gq2   = (const float*)d_in[8];
    const float* gk2   = (const float*)d_in[9];
    const float* Wout1 = (const float*)d_in[10];
    const float* Wout2 = (const float*)d_in[11];
    float* out = (float*)d_out;

    cudaFuncSetAttribute(gemm_mma, cudaFuncAttributeMaxDynamicSharedMemorySize, GEMM_SMEM);
    cudaFuncSetAttribute(attn_mma, cudaFuncAttributeMaxDynamicSharedMemorySize, ATT_SMEM);

    void* p;
    cudaGetSymbolAddress(&p, g_x1h);  __nv_bfloat16* x1h = (__nv_bfloat16*)p;
    cudaGetSymbolAddress(&p, g_x1l);  __nv_bfloat16* x1l = (__nv_bfloat16*)p;
    cudaGetSymbolAddress(&p, g_x2h);  __nv_bfloat16* x2h = (__nv_bfloat16*)p;
    cudaGetSymbolAddress(&p, g_x2l);  __nv_bfloat16* x2l = (__nv_bfloat16*)p;
    cudaGetSymbolAddress(&p, g_w1h);  __nv_bfloat16* w1h = (__nv_bfloat16*)p;
    cudaGetSymbolAddress(&p, g_w1l);  __nv_bfloat16* w1l = (__nv_bfloat16*)p;
    cudaGetSymbolAddress(&p, g_w2h);  __nv_bfloat16* w2h = (__nv_bfloat16*)p;
    cudaGetSymbolAddress(&p, g_w2l);  __nv_bfloat16* w2l = (__nv_bfloat16*)p;
    cudaGetSymbolAddress(&p, g_wo1h); __nv_bfloat16* wo1h = (__nv_bfloat16*)p;
    cudaGetSymbolAddress(&p, g_wo1l); __nv_bfloat16* wo1l = (__nv_bfloat16*)p;
    cudaGetSymbolAddress(&p, g_wo2h); __nv_bfloat16* wo2h = (__nv_bfloat16*)p;
    cudaGetSymbolAddress(&p, g_wo2l); __nv_bfloat16* wo2l = (__nv_bfloat16*)p;
    cudaGetSymbolAddress(&p, g_qkv1); float* qkv1 = (float*)p;
    cudaGetSymbolAddress(&p, g_qkv2); float* qkv2 = (float*)p;
    cudaGetSymbolAddress(&p, g_aoh);  __nv_bfloat16* aoh = (__nv_bfloat16*)p;
    cudaGetSymbolAddress(&p, g_aol);  __nv_bfloat16* aol = (__nv_bfloat16*)p;

    const int BIG = 1 << 30;

    // 0) splits + weight transposes
    split_rows<<<(BATCH * N1 * D1) / 1024, 256>>>(x1, x1h, x1l, BATCH * N1 * D1);
    split_rows<<<(BATCH * N2 * D2) / 1024, 256>>>(x2, x2h, x2l, BATCH * N2 * D2);
    wtrans<<<dim3(3 * DI / 32, D1 / 32), dim3(32, 8)>>>(Wqkv1, w1h, w1l, D1, 3 * DI);
    wtrans<<<dim3(3 * DI / 32, D2 / 32), dim3(32, 8)>>>(Wqkv2, w2h, w2l, D2, 3 * DI);
    wtrans<<<dim3(D1 / 32, DI / 32), dim3(32, 8)>>>(Wout1, wo1h, wo1l, DI, D1);
    wtrans<<<dim3(D2 / 32, DI / 32), dim3(32, 8)>>>(Wout2, wo2h, wo2l, DI, D2);

    // 1) QKV projections
    gemm_mma<<<dim3(3 * DI / 128, BATCH * N1 / 128), 256, GEMM_SMEM>>>(
        x1h, x1l, w1h, w1l, qkv1, BATCH * N1, D1, 3 * DI, BIG, 0, 0);
    gemm_mma<<<dim3(3 * DI / 128, BATCH * N2 / 128), 256, GEMM_SMEM>>>(
        x2h, x2l, w2h, w2l, qkv2, BATCH * N2, D2, 3 * DI, BIG, 0, 0);

    // 2) RMSNorm + scatter; V transpose
    rmsnorm_scatter<<<BH * NTOT / 4, 128>>>(gq1, gk1, gq2, gk2);
    vtrans<<<dim3(NTOT / 32, DH / 32, BH), dim3(32, 8)>>>();

    // 3) attention -> g_ao (split bf16)
    attn_mma<<<dim3(NTOT / 128, HEADS, BATCH), 256, ATT_SMEM>>>();

    // 4) output projections (row-remapped reads of concat ao)
    gemm_mma<<<dim3(D1 / 128, BATCH * N1 / 128), 256, GEMM_SMEM>>>(
        aoh, aol, wo1h, wo1l, out, BATCH * N1, DI, D1, 2048, 512, 0);
    gemm_mma<<<dim3(D2 / 128, BATCH * N2 / 128), 256, GEMM_SMEM>>>(
        aoh, aol, wo2h, wo2l, out + (size_t)BATCH * N1 * D1, BATCH * N2, DI, D2, 512, 2048, 2048);
}

// round 5
// speedup vs baseline: 3.6325x; 1.1898x over previous
#include <cuda_runtime.h>
#include <cuda_bf16.h>
#include <cstdint>
#include <math.h>

#define BATCH 2
#define N1 2048
#define N2 512
#define NTOT 2560
#define D1 1024
#define D2 768
#define HEADS 16
#define DH 64
#define DI 1024
#define BH (BATCH * HEADS)

// ===================== scratch (device globals) =====================
__device__ __align__(256) __nv_bfloat16 g_x1h[BATCH*N1*D1], g_x1l[BATCH*N1*D1];
__device__ __align__(256) __nv_bfloat16 g_x2h[BATCH*N2*D2], g_x2l[BATCH*N2*D2];
__device__ __align__(256) __nv_bfloat16 g_w1h[3*DI*D1],  g_w1l[3*DI*D1];
__device__ __align__(256) __nv_bfloat16 g_w2h[3*DI*D2],  g_w2l[3*DI*D2];
__device__ __align__(256) __nv_bfloat16 g_wo1h[D1*DI],   g_wo1l[D1*DI];
__device__ __align__(256) __nv_bfloat16 g_wo2h[D2*DI],   g_wo2l[D2*DI];
__device__ __align__(256) float g_qkv1[BATCH*N1*3*DI];
__device__ __align__(256) float g_qkv2[BATCH*N2*3*DI];
__device__ __align__(256) __nv_bfloat16 g_qh[BH*NTOT*DH], g_ql[BH*NTOT*DH];
__device__ __align__(256) __nv_bfloat16 g_kh[BH*NTOT*DH], g_kl[BH*NTOT*DH];
__device__ __align__(256) float g_vf[BH*NTOT*DH];
__device__ __align__(256) __nv_bfloat16 g_vth[BH*DH*NTOT], g_vtl[BH*DH*NTOT]; // [bh][d][n]
__device__ __align__(256) __nv_bfloat16 g_aoh[BATCH*NTOT*DI], g_aol[BATCH*NTOT*DI];

// ===================== helpers =====================
__device__ __forceinline__ uint32_t smem_u32(const void* p) {
    uint32_t a;
    asm("{ .reg .u64 t; cvta.to.shared.u64 t, %1; cvt.u32.u64 %0, t; }" : "=r"(a) : "l"(p));
    return a;
}
__device__ __forceinline__ uint32_t pack_bf2(__nv_bfloat16 a, __nv_bfloat16 b) {
    return (uint32_t)__bfloat16_as_ushort(a) | ((uint32_t)__bfloat16_as_ushort(b) << 16);
}
// tile: [rows][64] bf16, 128B rows, 16B chunks swizzled c ^ (r&7)
__device__ __forceinline__ uint32_t chunk_off(int r, int c) {
    return (uint32_t)(((r << 3) + (c ^ (r & 7))) << 4);
}
__device__ __forceinline__ void ldsm4(uint32_t (&d)[4], uint32_t a) {
    asm volatile("ldmatrix.sync.aligned.m8n8.x4.shared.b16 {%0,%1,%2,%3}, [%4];"
        : "=r"(d[0]), "=r"(d[1]), "=r"(d[2]), "=r"(d[3]) : "r"(a));
}
__device__ __forceinline__ void ldsmA(uint32_t (&d)[4], uint32_t tile, int row0, int k0, int lane) {
    int g = lane >> 3;
    int r = row0 + (lane & 7) + ((g & 1) << 3);
    int c = (k0 >> 3) + (g >> 1);
    ldsm4(d, tile + chunk_off(r, c));
}
__device__ __forceinline__ void ldsmB(uint32_t (&d)[4], uint32_t tile, int n0, int k0, int lane) {
    int g = lane >> 3;
    int r = n0 + (lane & 7) + ((g >> 1) << 3);
    int c = (k0 >> 3) + (g & 1);
    ldsm4(d, tile + chunk_off(r, c));
}
__device__ __forceinline__ void mma16816(float (&c)[4], const uint32_t (&a)[4], const uint32_t* b) {
    asm volatile("mma.sync.aligned.m16n8k16.row.col.f32.bf16.bf16.f32 "
        "{%0,%1,%2,%3}, {%4,%5,%6,%7}, {%8,%9}, {%0,%1,%2,%3};"
        : "+f"(c[0]), "+f"(c[1]), "+f"(c[2]), "+f"(c[3])
        : "r"(a[0]), "r"(a[1]), "r"(a[2]), "r"(a[3]), "r"(b[0]), "r"(b[1]));
}
// exp(50*tanh(s/50) - 8) with |s|<=8.5, FMA-only (no MUFU)
__device__ __forceinline__ float softclamp_exp(float s) {
    float u2 = s * s * 4.0e-4f;
    float cl = s * fmaf(u2, fmaf(u2, 0.13333334f, -0.33333334f), 1.0f);
    float y = fmaf(cl, 1.44269504f, -11.54156036f);
    float r = y + 12582912.0f;
    int n = __float_as_int(r) - 0x4B400000;
    float f = y - (r - 12582912.0f);
    float p = fmaf(f, fmaf(f, fmaf(f, fmaf(f, fmaf(f, 1.3333558e-3f, 9.6181291e-3f),
                 5.5504109e-2f), 2.4022651e-1f), 6.9314718e-1f), 1.0f);
    return __int_as_float(__float_as_int(p) + (n << 23));
}
// cp.async 16B
#define CP16(dst, src) asm volatile("cp.async.cg.shared.global [%0], [%1], 16;" :: "r"(dst), "l"(src))
#define CP_COMMIT()    asm volatile("cp.async.commit_group;" ::: "memory")
#define CP_WAIT1()     asm volatile("cp.async.wait_group 1;" ::: "memory")
#define CP_WAIT0()     asm volatile("cp.async.wait_group 0;" ::: "memory")

// ===================== pre-pass: split f32 -> bf16 hi/lo =====================
__global__ __launch_bounds__(256) void split_rows(const float* __restrict__ in,
    __nv_bfloat16* __restrict__ hi, __nv_bfloat16* __restrict__ lo, int n)
{
    int i = (blockIdx.x * 256 + threadIdx.x) * 4;
    if (i >= n) return;
    float4 v = *(const float4*)(in + i);
    __nv_bfloat16 h0 = __float2bfloat16_rn(v.x), h1 = __float2bfloat16_rn(v.y);
    __nv_bfloat16 h2 = __float2bfloat16_rn(v.z), h3 = __float2bfloat16_rn(v.w);
    uint2 wh = make_uint2(pack_bf2(h0, h1), pack_bf2(h2, h3));
    uint2 wl = make_uint2(
        pack_bf2(__float2bfloat16_rn(v.x - __bfloat162float(h0)), __float2bfloat16_rn(v.y - __bfloat162float(h1))),
        pack_bf2(__float2bfloat16_rn(v.z - __bfloat162float(h2)), __float2bfloat16_rn(v.w - __bfloat162float(h3))));
    *(uint2*)(hi + i) = wh;
    *(uint2*)(lo + i) = wl;
}

// ===================== pre-pass: transpose + split W[K][N] -> T[N][K] =======
__global__ __launch_bounds__(256) void wtrans(const float* __restrict__ W,
    __nv_bfloat16* __restrict__ th, __nv_bfloat16* __restrict__ tl, int K, int N)
{
    __shared__ float t[32][33];
    int tx = threadIdx.x, ty = threadIdx.y;
    int n0 = blockIdx.x * 32, k0 = blockIdx.y * 32;
#pragma unroll
    for (int i = ty; i < 32; i += 8)
        t[i][tx] = W[(size_t)(k0 + i) * N + n0 + tx];
    __syncthreads();
#pragma unroll
    for (int i = ty; i < 32; i += 8) {
        float v = t[tx][i];
        __nv_bfloat16 h = __float2bfloat16_rn(v);
        size_t o = (size_t)(n0 + i) * K + k0 + tx;
        th[o] = h;
        tl[o] = __float2bfloat16_rn(v - __bfloat162float(h));
    }
}

// ===================== split-bf16 HMMA GEMM (2-stage cp.async) =====================
// C[M,N] = A[M,K] @ Bt[N,K]^T, A row remap r -> r + off + (r/chunk)*pad.
// 128x128 block (256 thr, 8 warps 4m x 2n), k-tiles of 64, 2 smem stages.
#define GO_AH 0
#define GO_AL 16384
#define GO_BH 32768
#define GO_BL 49152
#define G_STAGE 65536
#define GEMM_SMEM (2 * G_STAGE)

__global__ __launch_bounds__(256) void gemm_mma(
    const __nv_bfloat16* __restrict__ Ah, const __nv_bfloat16* __restrict__ Al,
    const __nv_bfloat16* __restrict__ Bh, const __nv_bfloat16* __restrict__ Bl,
    float* __restrict__ C, int M, int K, int N, int chunk, int pad, int off)
{
    extern __shared__ char sm[];
    const uint32_t sb = smem_u32(sm);
    const int tid = threadIdx.x;
    const int lane = tid & 31;
    const int w = tid >> 5;
    const int wm = w & 3, wn = w >> 2;
    const int bx = blockIdx.x, by = blockIdx.y;

    // per-thread fixed load coords
    const int lr = tid >> 3;          // row 0..31 (+32*i)
    const int lc = tid & 7;           // chunk 0..7

    auto issue = [&](int kt, int stage) {
        uint32_t base = sb + stage * G_STAGE;
#pragma unroll
        for (int i = 0; i < 4; i++) {
            int r = lr + i * 32;
            uint32_t so = chunk_off(r, lc);
            int gr = by * 128 + r;
            gr = gr + off + (gr / chunk) * pad;
            size_t ao = (size_t)gr * K + kt * 64 + lc * 8;
            CP16(base + GO_AH + so, Ah + ao);
            CP16(base + GO_AL + so, Al + ao);
            size_t bo = (size_t)(bx * 128 + r) * K + kt * 64 + lc * 8;
            CP16(base + GO_BH + so, Bh + bo);
            CP16(base + GO_BL + so, Bl + bo);
        }
        CP_COMMIT();
    };

    float acc[2][8][4];
#pragma unroll
    for (int i = 0; i < 2; i++)
#pragma unroll
        for (int j = 0; j < 8; j++)
#pragma unroll
            for (int q = 0; q < 4; q++) acc[i][j][q] = 0.0f;

    const int ktiles = K >> 6;
    issue(0, 0);

    for (int kt = 0; kt < ktiles; kt++) {
        int cur = kt & 1;
        if (kt + 1 < ktiles) { issue(kt + 1, cur ^ 1); CP_WAIT1(); }
        else CP_WAIT0();
        __syncthreads();

        uint32_t tAH = sb + cur * G_STAGE + GO_AH;
        uint32_t tAL = sb + cur * G_STAGE + GO_AL;
        uint32_t tBH = sb + cur * G_STAGE + GO_BH;
        uint32_t tBL = sb + cur * G_STAGE + GO_BL;
#pragma unroll
        for (int ks = 0; ks < 4; ks++) {
            int k0 = ks * 16;
            uint32_t ahf[2][4], alf[2][4];
            ldsmA(ahf[0], tAH, wm * 32, k0, lane);
            ldsmA(ahf[1], tAH, wm * 32 + 16, k0, lane);
            ldsmA(alf[0], tAL, wm * 32, k0, lane);
            ldsmA(alf[1], tAL, wm * 32 + 16, k0, lane);
#pragma unroll
            for (int nb = 0; nb < 4; nb++) {
                uint32_t bhf[4], blf[4];
                ldsmB(bhf, tBH, wn * 64 + nb * 16, k0, lane);
                ldsmB(blf, tBL, wn * 64 + nb * 16, k0, lane);
#pragma unroll
                for (int mi = 0; mi < 2; mi++) {
                    mma16816(acc[mi][2 * nb],     ahf[mi], bhf);
                    mma16816(acc[mi][2 * nb + 1], ahf[mi], bhf + 2);
                    mma16816(acc[mi][2 * nb],     ahf[mi], blf);
                    mma16816(acc[mi][2 * nb + 1], ahf[mi], blf + 2);
                    mma16816(acc[mi][2 * nb],     alf[mi], bhf);
                    mma16816(acc[mi][2 * nb + 1], alf[mi], bhf + 2);
                }
            }
        }
        __syncthreads();
    }

#pragma unroll
    for (int mi = 0; mi < 2; mi++)
#pragma unroll
        for (int nf = 0; nf < 8; nf++) {
            int row = by * 128 + wm * 32 + mi * 16 + (lane >> 2);
            int col = bx * 128 + wn * 64 + nf * 8 + ((lane & 3) << 1);
            *(float2*)(C + (size_t)row * N + col) = make_float2(acc[mi][nf][0], acc[mi][nf][1]);
            *(float2*)(C + (size_t)(row + 8) * N + col) = make_float2(acc[mi][nf][2], acc[mi][nf][3]);
        }
}

// ===================== RMSNorm + scatter (bf16 splits) =====================
__global__ __launch_bounds__(128) void rmsnorm_scatter(
    const float* __restrict__ gq1, const float* __restrict__ gk1,
    const float* __restrict__ gq2, const float* __restrict__ gk2)
{
    int warp = (blockIdx.x * blockDim.x + threadIdx.x) >> 5;
    int lane = threadIdx.x & 31;
    if (warp >= BH * NTOT) return;
    int n = warp % NTOT;
    int bh = warp / NTOT;
    int h = bh % HEADS;
    int b = bh / HEADS;

    const float* src;
    const float *gq, *gk;
    if (n < N1) { src = g_qkv1 + (size_t)(b * N1 + n) * (3 * DI); gq = gq1; gk = gk1; }
    else        { src = g_qkv2 + (size_t)(b * N2 + (n - N1)) * (3 * DI); gq = gq2; gk = gk2; }

    size_t dst = ((size_t)bh * NTOT + n) * DH;
    int c0 = h * DH + lane;
    int c1 = c0 + 32;

    float q0 = src[c0], q1 = src[c1];
    float ss = q0 * q0 + q1 * q1;
#pragma unroll
    for (int o = 16; o > 0; o >>= 1) ss += __shfl_xor_sync(0xffffffffu, ss, o);
    float rq = __fdividef(1.0f, fmaxf(sqrtf(ss), 1e-12f));
    float qa = q0 * rq * gq[c0], qb = q1 * rq * gq[c1];
    {
        __nv_bfloat16 h0 = __float2bfloat16_rn(qa), h1 = __float2bfloat16_rn(qb);
        g_qh[dst + lane] = h0; g_qh[dst + lane + 32] = h1;
        g_ql[dst + lane]      = __float2bfloat16_rn(qa - __bfloat162float(h0));
        g_ql[dst + lane + 32] = __float2bfloat16_rn(qb - __bfloat162float(h1));
    }

    float k0 = src[DI + c0], k1 = src[DI + c1];
    float sk = k0 * k0 + k1 * k1;
#pragma unroll
    for (int o = 16; o > 0; o >>= 1) sk += __shfl_xor_sync(0xffffffffu, sk, o);
    float rk = __fdividef(8.0f, fmaxf(sqrtf(sk), 1e-12f));
    float ka = k0 * rk * gk[c0], kb = k1 * rk * gk[c1];
    {
        __nv_bfloat16 h0 = __float2bfloat16_rn(ka), h1 = __float2bfloat16_rn(kb);
        g_kh[dst + lane] = h0; g_kh[dst + lane + 32] = h1;
        g_kl[dst + lane]      = __float2bfloat16_rn(ka - __bfloat162float(h0));
        g_kl[dst + lane + 32] = __float2bfloat16_rn(kb - __bfloat162float(h1));
    }

    g_vf[dst + lane]      = src[2 * DI + c0];
    g_vf[dst + lane + 32] = src[2 * DI + c1];
}

// ===================== V transpose: [bh][n][d] f32 -> [bh][d][n] bf16 hi/lo =
__global__ __launch_bounds__(256) void vtrans()
{
    __shared__ float t[32][33];
    int tx = threadIdx.x, ty = threadIdx.y;
    int n0 = blockIdx.x * 32, d0 = blockIdx.y * 32, bh = blockIdx.z;
    const float* in = g_vf + (size_t)bh * NTOT * DH;
#pragma unroll
    for (int i = ty; i < 32; i += 8)
        t[i][tx] = in[(size_t)(n0 + i) * DH + d0 + tx];
    __syncthreads();
    size_t ob = (size_t)bh * DH * NTOT;
#pragma unroll
    for (int i = ty; i < 32; i += 8) {
        float v = t[tx][i];
        __nv_bfloat16 h = __float2bfloat16_rn(v);
        size_t o = ob + (size_t)(d0 + i) * NTOT + n0 + tx;
        g_vth[o] = h;
        g_vtl[o] = __float2bfloat16_rn(v - __bfloat162float(h));
    }
}

// ===================== HMMA flash attention (2-stage cp.async) ==============
// 256 thr (8 warps), 128 q rows x 128 key tile, DH=64. Warp owns 16 q rows.
// Fixed softmax max = 8 (norms folded) -> no online rescale.
#define AO_KH 0
#define AO_KL 16384
#define AO_VH 32768
#define AO_VL 49152
#define A_STAGE 65536
#define ATT_SMEM (2 * A_STAGE)

__global__ __launch_bounds__(256) void attn_mma()
{
    extern __shared__ char sm[];
    const uint32_t sb = smem_u32(sm);
    const int tid = threadIdx.x;
    const int lane = tid & 31;
    const int w = tid >> 5;
    const int qt = blockIdx.x, h = blockIdx.y, b = blockIdx.z;
    const int bh = b * HEADS + h;

    const size_t kbase = (size_t)bh * NTOT * DH;
    const size_t vbase = (size_t)bh * DH * NTOT;

    // ---- stage Q into stage-0 KH/KL, extract frags to registers ----
    uint32_t qhf[4][4], qlf[4][4];
    {
        const __nv_bfloat16* qh = g_qh + ((size_t)bh * NTOT + qt * 128) * DH;
        const __nv_bfloat16* ql = g_ql + ((size_t)bh * NTOT + qt * 128) * DH;
#pragma unroll
        for (int i = 0; i < 4; i++) {
            int idx = i * 256 + tid;
            int r = idx >> 3, c = idx & 7;
            uint32_t so = chunk_off(r, c);
            size_t go = (size_t)r * DH + c * 8;
            *(uint4*)(sm + AO_KH + so) = *(const uint4*)(qh + go);
            *(uint4*)(sm + AO_KL + so) = *(const uint4*)(ql + go);
        }
        __syncthreads();
#pragma unroll
        for (int ks = 0; ks < 4; ks++) {
            ldsmA(qhf[ks], sb + AO_KH, w * 16, ks * 16, lane);
            ldsmA(qlf[ks], sb + AO_KL, w * 16, ks * 16, lane);
        }
        __syncthreads();
    }

    // per-thread fixed load coords
    const int lr = tid >> 3, lc = tid & 7;       // K tile
    const int vd = tid >> 4, vch = tid & 15;     // V tile

    auto issue = [&](int kt, int stage) {
        uint32_t base = sb + stage * A_STAGE;
#pragma unroll
        for (int i = 0; i < 4; i++) {
            int r = lr + i * 32;
            uint32_t so = chunk_off(r, lc);
            size_t go = kbase + (size_t)(kt * 128 + r) * DH + lc * 8;
            CP16(base + AO_KH + so, g_kh + go);
            CP16(base + AO_KL + so, g_kl + go);
            int d = vd + i * 16;
            uint32_t vo = (uint32_t)((vch >> 3) * 8192) + chunk_off(d, vch & 7);
            size_t vg = vbase + (size_t)d * NTOT + kt * 128 + vch * 8;
            CP16(base + AO_VH + vo, g_vth + vg);
            CP16(base + AO_VL + vo, g_vtl + vg);
        }
        CP_COMMIT();
    };

    float O[8][4];
#pragma unroll
    for (int j = 0; j < 8; j++)
#pragma unroll
        for (int q = 0; q < 4; q++) O[j][q] = 0.0f;
    float lsum0 = 0.0f, lsum1 = 0.0f;

    const int ktiles = NTOT / 128;
    issue(0, 0);

    for (int kt = 0; kt < ktiles; kt++) {
        int cur = kt & 1;
        if (kt + 1 < ktiles) { issue(kt + 1, cur ^ 1); CP_WAIT1(); }
        else CP_WAIT0();
        __syncthreads();

        uint32_t tKH = sb + cur * A_STAGE + AO_KH;
        uint32_t tKL = sb + cur * A_STAGE + AO_KL;
        uint32_t tVH = sb + cur * A_STAGE + AO_VH;
        uint32_t tVL = sb + cur * A_STAGE + AO_VL;

        // ---- S = Q K^T (split-3) ----
        float S[16][4];
#pragma unroll
        for (int j = 0; j < 16; j++)
#pragma unroll
            for (int q = 0; q < 4; q++) S[j][q] = 0.0f;
#pragma unroll
        for (int ks = 0; ks < 4; ks++) {
            int k0 = ks * 16;
#pragma unroll
            for (int nb = 0; nb < 8; nb++) {
                uint32_t bhf[4], blf[4];
                ldsmB(bhf, tKH, nb * 16, k0, lane);
                ldsmB(blf, tKL, nb * 16, k0, lane);
                mma16816(S[2 * nb],     qhf[ks], bhf);
                mma16816(S[2 * nb + 1], qhf[ks], bhf + 2);
                mma16816(S[2 * nb],     qhf[ks], blf);
                mma16816(S[2 * nb + 1], qhf[ks], blf + 2);
                mma16816(S[2 * nb],     qlf[ks], bhf);
                mma16816(S[2 * nb + 1], qlf[ks], bhf + 2);
            }
        }

        // ---- softclamp + exp (fixed max 8), row sums ----
        float rs0 = 0.0f, rs1 = 0.0f;
#pragma unroll
        for (int j = 0; j < 16; j++) {
            S[j][0] = softclamp_exp(S[j][0]); rs0 += S[j][0];
            S[j][1] = softclamp_exp(S[j][1]); rs0 += S[j][1];
            S[j][2] = softclamp_exp(S[j][2]); rs1 += S[j][2];
            S[j][3] = softclamp_exp(S[j][3]); rs1 += S[j][3];
        }
        rs0 += __shfl_xor_sync(0xffffffffu, rs0, 1);
        rs0 += __shfl_xor_sync(0xffffffffu, rs0, 2);
        rs1 += __shfl_xor_sync(0xffffffffu, rs1, 1);
        rs1 += __shfl_xor_sync(0xffffffffu, rs1, 2);
        lsum0 += rs0;
        lsum1 += rs1;

        // ---- O += P V (split-3): convert P acc->A frags per k16 ----
#pragma unroll
        for (int kk = 0; kk < 8; kk++) {
            uint32_t ah4[4], al4[4];
#pragma unroll
            for (int q = 0; q < 4; q++) {
                float p0 = S[2 * kk + (q >> 1)][(q & 1) * 2];
                float p1 = S[2 * kk + (q >> 1)][(q & 1) * 2 + 1];
                __nv_bfloat16 h0 = __float2bfloat16_rn(p0);
                __nv_bfloat16 h1 = __float2bfloat16_rn(p1);
                ah4[q] = pack_bf2(h0, h1);
                al4[q] = pack_bf2(__float2bfloat16_rn(p0 - __bfloat162float(h0)),
                                  __float2bfloat16_rn(p1 - __bfloat162float(h1)));
            }
            int k0 = kk * 16;
            uint32_t vth_t = tVH + ((k0 >> 6) * 8192);
            uint32_t vtl_t = tVL + ((k0 >> 6) * 8192);
            int k0e = k0 & 63;
#pragma unroll
            for (int nb = 0; nb < 4; nb++) {
                uint32_t vh4[4], vl4[4];
                ldsmB(vh4, vth_t, nb * 16, k0e, lane);
                ldsmB(vl4, vtl_t, nb * 16, k0e, lane);
                mma16816(O[2 * nb],     ah4, vh4);
                mma16816(O[2 * nb + 1], ah4, vh4 + 2);
                mma16816(O[2 * nb],     ah4, vl4);
                mma16816(O[2 * nb + 1], ah4, vl4 + 2);
                mma16816(O[2 * nb],     al4, vh4);
                mma16816(O[2 * nb + 1], al4, vh4 + 2);
            }
        }
        __syncthreads();
    }

    // ---- epilogue: normalize, write split-bf16 to g_ao ----
    float inv0 = __fdividef(1.0f, lsum0);
    float inv1 = __fdividef(1.0f, lsum1);
    int rlo = qt * 128 + w * 16 + (lane >> 2);
    int colb = h * DH + ((lane & 3) << 1);
    size_t o_lo = ((size_t)(b * NTOT + rlo)) * DI + colb;
    size_t o_hi = ((size_t)(b * NTOT + rlo + 8)) * DI + colb;
#pragma unroll
    for (int nf = 0; nf < 8; nf++) {
        float v0 = O[nf][0] * inv0, v1 = O[nf][1] * inv0;
        __nv_bfloat16 h0 = __float2bfloat16_rn(v0), h1 = __float2bfloat16_rn(v1);
        *(uint32_t*)(g_aoh + o_lo + nf * 8) = pack_bf2(h0, h1);
        *(uint32_t*)(g_aol + o_lo + nf * 8) = pack_bf2(
            __float2bfloat16_rn(v0 - __bfloat162float(h0)),
            __float2bfloat16_rn(v1 - __bfloat162float(h1)));
        float v2 = O[nf][2] * inv1, v3 = O[nf][3] * inv1;
        __nv_bfloat16 h2 = __float2bfloat16_rn(v2), h3 = __float2bfloat16_rn(v3);
        *(uint32_t*)(g_aoh + o_hi + nf * 8) = pack_bf2(h2, h3);
        *(uint32_t*)(g_aol + o_hi + nf * 8) = pack_bf2(
            __float2bfloat16_rn(v2 - __bfloat162float(h2)),
            __float2bfloat16_rn(v3 - __bfloat162float(h3)));
    }
}

// ===================== launcher =====================
extern "C" void kernel_launch(void* const* d_in, const int* in_sizes, int n_in,
                              void* d_out, int out_size)
{
    (void)in_sizes; (void)n_in; (void)out_size;
    const float* x1    = (const float*)d_in[0];
    const float* x2    = (const float*)d_in[1];
    const float* Wqkv1 = (const float*)d_in[4];
    const float* Wqkv2 = (const float*)d_in[5];
    const float* gq1   = (const float*)d_in[6];
    const float* gk1   = (const float*)d_in[7];
    const float* gq2   = (const float*)d_in[8];
    const float* gk2   = (const float*)d_in[9];
    const float* Wout1 = (const float*)d_in[10];
    const float* Wout2 = (const float*)d_in[11];
    float* out = (float*)d_out;

    cudaFuncSetAttribute(gemm_mma, cudaFuncAttributeMaxDynamicSharedMemorySize, GEMM_SMEM);
    cudaFuncSetAttribute(attn_mma, cudaFuncAttributeMaxDynamicSharedMemorySize, ATT_SMEM);

    void* p;
    cudaGetSymbolAddress(&p, g_x1h);  __nv_bfloat16* x1h = (__nv_bfloat16*)p;
    cudaGetSymbolAddress(&p, g_x1l);  __nv_bfloat16* x1l = (__nv_bfloat16*)p;
    cudaGetSymbolAddress(&p, g_x2h);  __nv_bfloat16* x2h = (__nv_bfloat16*)p;
    cudaGetSymbolAddress(&p, g_x2l);  __nv_bfloat16* x2l = (__nv_bfloat16*)p;
    cudaGetSymbolAddress(&p, g_w1h);  __nv_bfloat16* w1h = (__nv_bfloat16*)p;
    cudaGetSymbolAddress(&p, g_w1l);  __nv_bfloat16* w1l = (__nv_bfloat16*)p;
    cudaGetSymbolAddress(&p, g_w2h);  __nv_bfloat16* w2h = (__nv_bfloat16*)p;
    cudaGetSymbolAddress(&p, g_w2l);  __nv_bfloat16* w2l = (__nv_bfloat16*)p;
    cudaGetSymbolAddress(&p, g_wo1h); __nv_bfloat16* wo1h = (__nv_bfloat16*)p;
    cudaGetSymbolAddress(&p, g_wo1l); __nv_bfloat16* wo1l = (__nv_bfloat16*)p;
    cudaGetSymbolAddress(&p, g_wo2h); __nv_bfloat16* wo2h = (__nv_bfloat16*)p;
    cudaGetSymbolAddress(&p, g_wo2l); __nv_bfloat16* wo2l = (__nv_bfloat16*)p;
    cudaGetSymbolAddress(&p, g_qkv1); float* qkv1 = (float*)p;
    cudaGetSymbolAddress(&p, g_qkv2); float* qkv2 = (float*)p;
    cudaGetSymbolAddress(&p, g_aoh);  __nv_bfloat16* aoh = (__nv_bfloat16*)p;
    cudaGetSymbolAddress(&p, g_aol);  __nv_bfloat16* aol = (__nv_bfloat16*)p;

    const int BIG = 1 << 30;

    // 0) splits + weight transposes
    split_rows<<<(BATCH * N1 * D1) / 1024, 256>>>(x1, x1h, x1l, BATCH * N1 * D1);
    split_rows<<<(BATCH * N2 * D2) / 1024, 256>>>(x2, x2h, x2l, BATCH * N2 * D2);
    wtrans<<<dim3(3 * DI / 32, D1 / 32), dim3(32, 8)>>>(Wqkv1, w1h, w1l, D1, 3 * DI);
    wtrans<<<dim3(3 * DI / 32, D2 / 32), dim3(32, 8)>>>(Wqkv2, w2h, w2l, D2, 3 * DI);
    wtrans<<<dim3(D1 / 32, DI / 32), dim3(32, 8)>>>(Wout1, wo1h, wo1l, DI, D1);
    wtrans<<<dim3(D2 / 32, DI / 32), dim3(32, 8)>>>(Wout2, wo2h, wo2l, DI, D2);

    // 1) QKV projections
    gemm_mma<<<dim3(3 * DI / 128, BATCH * N1 / 128), 256, GEMM_SMEM>>>(
        x1h, x1l, w1h, w1l, qkv1, BATCH * N1, D1, 3 * DI, BIG, 0, 0);
    gemm_mma<<<dim3(3 * DI / 128, BATCH * N2 / 128), 256, GEMM_SMEM>>>(
        x2h, x2l, w2h, w2l, qkv2, BATCH * N2, D2, 3 * DI, BIG, 0, 0);

    // 2) RMSNorm + scatter; V transpose
    rmsnorm_scatter<<<BH * NTOT / 4, 128>>>(gq1, gk1, gq2, gk2);
    vtrans<<<dim3(NTOT / 32, DH / 32, BH), dim3(32, 8)>>>();

    // 3) attention -> g_ao (split bf16)
    attn_mma<<<dim3(NTOT / 128, HEADS, BATCH), 256, ATT_SMEM>>>();

    // 4) output projections (row-remapped reads of concat ao)
    gemm_mma<<<dim3(D1 / 128, BATCH * N1 / 128), 256, GEMM_SMEM>>>(
        aoh, aol, wo1h, wo1l, out, BATCH * N1, DI, D1, 2048, 512, 0);
    gemm_mma<<<dim3(D2 / 128, BATCH * N2 / 128), 256, GEMM_SMEM>>>(
        aoh, aol, wo2h, wo2l, out + (size_t)BATCH * N1 * D1, BATCH * N2, DI, D2, 512, 2048, 2048);
}

// round 6
// speedup vs baseline: 4.8818x; 1.3439x over previous
#include <cuda_runtime.h>
#include <cuda_bf16.h>
#include <cuda_fp16.h>
#include <cstdint>
#include <math.h>

#define BATCH 2
#define N1 2048
#define N2 512
#define NTOT 2560
#define D1 1024
#define D2 768
#define HEADS 16
#define DH 64
#define DI 1024
#define BH (BATCH * HEADS)

// ===================== scratch (device globals) =====================
__device__ __align__(256) __nv_bfloat16 g_x1h[BATCH*N1*D1], g_x1l[BATCH*N1*D1];
__device__ __align__(256) __nv_bfloat16 g_x2h[BATCH*N2*D2], g_x2l[BATCH*N2*D2];
__device__ __align__(256) __nv_bfloat16 g_w1h[3*DI*D1],  g_w1l[3*DI*D1];
__device__ __align__(256) __nv_bfloat16 g_w2h[3*DI*D2],  g_w2l[3*DI*D2];
__device__ __align__(256) __nv_bfloat16 g_wo1h[D1*DI],   g_wo1l[D1*DI];
__device__ __align__(256) __nv_bfloat16 g_wo2h[D2*DI],   g_wo2l[D2*DI];
__device__ __align__(256) float g_qkv1[BATCH*N1*3*DI];
__device__ __align__(256) float g_qkv2[BATCH*N2*3*DI];
__device__ __align__(256) __nv_bfloat16 g_qh[BH*NTOT*DH], g_ql[BH*NTOT*DH];
__device__ __align__(256) __nv_bfloat16 g_kh[BH*NTOT*DH], g_kl[BH*NTOT*DH];
__device__ __align__(256) __half g_vh[BH*NTOT*DH];                 // fp16, row-major
__device__ __align__(256) __nv_bfloat16 g_aoh[BATCH*NTOT*DI], g_aol[BATCH*NTOT*DI];

// ===================== helpers =====================
__device__ __forceinline__ uint32_t smem_u32(const void* p) {
    uint32_t a;
    asm("{ .reg .u64 t; cvta.to.shared.u64 t, %1; cvt.u32.u64 %0, t; }" : "=r"(a) : "l"(p));
    return a;
}
__device__ __forceinline__ uint32_t pack_bf2(__nv_bfloat16 a, __nv_bfloat16 b) {
    return (uint32_t)__bfloat16_as_ushort(a) | ((uint32_t)__bfloat16_as_ushort(b) << 16);
}
__device__ __forceinline__ uint32_t pack_h2(float a, float b) {
    __half2 h = __floats2half2_rn(a, b);
    return *(uint32_t*)&h;
}
// tile: [rows][64] 16-bit elems, 128B rows, 16B chunks swizzled c ^ (r&7)
__device__ __forceinline__ uint32_t chunk_off(int r, int c) {
    return (uint32_t)(((r << 3) + (c ^ (r & 7))) << 4);
}
__device__ __forceinline__ void ldsm4(uint32_t (&d)[4], uint32_t a) {
    asm volatile("ldmatrix.sync.aligned.m8n8.x4.shared.b16 {%0,%1,%2,%3}, [%4];"
        : "=r"(d[0]), "=r"(d[1]), "=r"(d[2]), "=r"(d[3]) : "r"(a));
}
__device__ __forceinline__ void ldsm4t(uint32_t (&d)[4], uint32_t a) {
    asm volatile("ldmatrix.sync.aligned.m8n8.x4.trans.shared.b16 {%0,%1,%2,%3}, [%4];"
        : "=r"(d[0]), "=r"(d[1]), "=r"(d[2]), "=r"(d[3]) : "r"(a));
}
__device__ __forceinline__ void ldsmA(uint32_t (&d)[4], uint32_t tile, int row0, int k0, int lane) {
    int g = lane >> 3;
    int r = row0 + (lane & 7) + ((g & 1) << 3);
    int c = (k0 >> 3) + (g >> 1);
    ldsm4(d, tile + chunk_off(r, c));
}
__device__ __forceinline__ void ldsmB(uint32_t (&d)[4], uint32_t tile, int n0, int k0, int lane) {
    int g = lane >> 3;
    int r = n0 + (lane & 7) + ((g >> 1) << 3);
    int c = (k0 >> 3) + (g & 1);
    ldsm4(d, tile + chunk_off(r, c));
}
// B frags from a row-major [k][n] tile via ldmatrix.trans (V path)
__device__ __forceinline__ void ldsmBT(uint32_t (&d)[4], uint32_t tile, int n0, int k0, int lane) {
    int g = lane >> 3;
    int r = k0 + (lane & 7) + ((g & 1) << 3);
    int c = (n0 >> 3) + (g >> 1);
    ldsm4t(d, tile + chunk_off(r, c));
}
__device__ __forceinline__ void mma16816(float (&c)[4], const uint32_t (&a)[4], const uint32_t* b) {
    asm volatile("mma.sync.aligned.m16n8k16.row.col.f32.bf16.bf16.f32 "
        "{%0,%1,%2,%3}, {%4,%5,%6,%7}, {%8,%9}, {%0,%1,%2,%3};"
        : "+f"(c[0]), "+f"(c[1]), "+f"(c[2]), "+f"(c[3])
        : "r"(a[0]), "r"(a[1]), "r"(a[2]), "r"(a[3]), "r"(b[0]), "r"(b[1]));
}
__device__ __forceinline__ void mma16816h(float (&c)[4], const uint32_t (&a)[4], const uint32_t* b) {
    asm volatile("mma.sync.aligned.m16n8k16.row.col.f32.f16.f16.f32 "
        "{%0,%1,%2,%3}, {%4,%5,%6,%7}, {%8,%9}, {%0,%1,%2,%3};"
        : "+f"(c[0]), "+f"(c[1]), "+f"(c[2]), "+f"(c[3])
        : "r"(a[0]), "r"(a[1]), "r"(a[2]), "r"(a[3]), "r"(b[0]), "r"(b[1]));
}
// exp(50*tanh(s/50) - 8), |s| <= 8.5; poly tanh (FMA) + MUFU exp
__device__ __forceinline__ float softclamp_exp(float s) {
    float u2 = s * s * 4.0e-4f;
    float cl = s * fmaf(u2, fmaf(u2, 0.13333334f, -0.33333334f), 1.0f);
    return __expf(cl - 8.0f);
}
// cp.async 16B
#define CP16(dst, src) asm volatile("cp.async.cg.shared.global [%0], [%1], 16;" :: "r"(dst), "l"(src))
#define CP_COMMIT()    asm volatile("cp.async.commit_group;" ::: "memory")
#define CP_WAIT2()     asm volatile("cp.async.wait_group 2;" ::: "memory")
#define CP_WAIT1()     asm volatile("cp.async.wait_group 1;" ::: "memory")
#define CP_WAIT0()     asm volatile("cp.async.wait_group 0;" ::: "memory")

// ===================== fused pre-pass: split x1 & x2 -> bf16 hi/lo ==========
#define SPLIT_B1 ((BATCH * N1 * D1) / 1024)
#define SPLIT_B2 ((BATCH * N2 * D2) / 1024)
__global__ __launch_bounds__(256) void split_all(
    const float* __restrict__ x1, __nv_bfloat16* __restrict__ h1, __nv_bfloat16* __restrict__ l1,
    const float* __restrict__ x2, __nv_bfloat16* __restrict__ h2, __nv_bfloat16* __restrict__ l2)
{
    int bid = blockIdx.x;
    const float* in; __nv_bfloat16 *hi, *lo; int i;
    if (bid < SPLIT_B1) { in = x1; hi = h1; lo = l1; i = (bid * 256 + threadIdx.x) * 4; }
    else { in = x2; hi = h2; lo = l2; i = ((bid - SPLIT_B1) * 256 + threadIdx.x) * 4; }
    float4 v = *(const float4*)(in + i);
    __nv_bfloat16 h0 = __float2bfloat16_rn(v.x), hb1 = __float2bfloat16_rn(v.y);
    __nv_bfloat16 h2b = __float2bfloat16_rn(v.z), h3 = __float2bfloat16_rn(v.w);
    uint2 wh = make_uint2(pack_bf2(h0, hb1), pack_bf2(h2b, h3));
    uint2 wl = make_uint2(
        pack_bf2(__float2bfloat16_rn(v.x - __bfloat162float(h0)), __float2bfloat16_rn(v.y - __bfloat162float(hb1))),
        pack_bf2(__float2bfloat16_rn(v.z - __bfloat162float(h2b)), __float2bfloat16_rn(v.w - __bfloat162float(h3))));
    *(uint2*)(hi + i) = wh;
    *(uint2*)(lo + i) = wl;
}

// ===================== fused pre-pass: all 4 weight transposes ==============
// seg0 Wqkv1 (K=1024,N=3072): 3072 blocks; seg1 Wqkv2 (768,3072): 2304;
// seg2 Wout1 (1024,1024): 1024; seg3 Wout2 (1024,768): 768. total 7168.
__global__ __launch_bounds__(256) void wtrans_all(
    const float* __restrict__ W0, __nv_bfloat16* __restrict__ h0, __nv_bfloat16* __restrict__ l0,
    const float* __restrict__ W1, __nv_bfloat16* __restrict__ h1, __nv_bfloat16* __restrict__ l1,
    const float* __restrict__ W2, __nv_bfloat16* __restrict__ h2, __nv_bfloat16* __restrict__ l2,
    const float* __restrict__ W3, __nv_bfloat16* __restrict__ h3, __nv_bfloat16* __restrict__ l3)
{
    __shared__ float t[32][33];
    int bid = blockIdx.x;
    const float* W; __nv_bfloat16 *th, *tl; int K, N, nbx, local;
    if (bid < 3072)      { W = W0; th = h0; tl = l0; K = D1; N = 3 * DI; nbx = 96; local = bid; }
    else if (bid < 5376) { W = W1; th = h1; tl = l1; K = D2; N = 3 * DI; nbx = 96; local = bid - 3072; }
    else if (bid < 6400) { W = W2; th = h2; tl = l2; K = DI; N = D1;     nbx = 32; local = bid - 5376; }
    else                 { W = W3; th = h3; tl = l3; K = DI; N = D2;     nbx = 24; local = bid - 6400; }
    int n0 = (local % nbx) * 32, k0 = (local / nbx) * 32;
    int tx = threadIdx.x & 31, ty = threadIdx.x >> 5;
#pragma unroll
    for (int i = ty; i < 32; i += 8)
        t[i][tx] = W[(size_t)(k0 + i) * N + n0 + tx];
    __syncthreads();
#pragma unroll
    for (int i = ty; i < 32; i += 8) {
        float v = t[tx][i];
        __nv_bfloat16 h = __float2bfloat16_rn(v);
        size_t o = (size_t)(n0 + i) * K + k0 + tx;
        th[o] = h;
        tl[o] = __float2bfloat16_rn(v - __bfloat162float(h));
    }
}

// ===================== split-bf16 HMMA GEMM (3-stage cp.async) ==============
#define GO_AH 0
#define GO_AL 16384
#define GO_BH 32768
#define GO_BL 49152
#define G_STAGE 65536
#define GEMM_SMEM (3 * G_STAGE)

__global__ __launch_bounds__(256) void gemm_mma(
    const __nv_bfloat16* __restrict__ Ah, const __nv_bfloat16* __restrict__ Al,
    const __nv_bfloat16* __restrict__ Bh, const __nv_bfloat16* __restrict__ Bl,
    float* __restrict__ C, int M, int K, int N, int chunk, int pad, int off)
{
    extern __shared__ char sm[];
    const uint32_t sb = smem_u32(sm);
    const int tid = threadIdx.x;
    const int lane = tid & 31;
    const int w = tid >> 5;
    const int wm = w & 3, wn = w >> 2;
    const int bx = blockIdx.x, by = blockIdx.y;

    const int lr = tid >> 3;
    const int lc = tid & 7;

    auto issue = [&](int kt, int stage) {
        uint32_t base = sb + stage * G_STAGE;
#pragma unroll
        for (int i = 0; i < 4; i++) {
            int r = lr + i * 32;
            uint32_t so = chunk_off(r, lc);
            int gr = by * 128 + r;
            gr = gr + off + (gr / chunk) * pad;
            size_t ao = (size_t)gr * K + kt * 64 + lc * 8;
            CP16(base + GO_AH + so, Ah + ao);
            CP16(base + GO_AL + so, Al + ao);
            size_t bo = (size_t)(bx * 128 + r) * K + kt * 64 + lc * 8;
            CP16(base + GO_BH + so, Bh + bo);
            CP16(base + GO_BL + so, Bl + bo);
        }
        CP_COMMIT();
    };

    float acc[2][8][4];
#pragma unroll
    for (int i = 0; i < 2; i++)
#pragma unroll
        for (int j = 0; j < 8; j++)
#pragma unroll
            for (int q = 0; q < 4; q++) acc[i][j][q] = 0.0f;

    const int ktiles = K >> 6;
    issue(0, 0);
    issue(1, 1);

    for (int kt = 0; kt < ktiles; kt++) {
        int cur = kt - (kt / 3) * 3;
        if (kt + 2 < ktiles) { issue(kt + 2, (kt + 2) % 3); CP_WAIT2(); }
        else if (kt + 1 < ktiles) CP_WAIT1();
        else CP_WAIT0();
        __syncthreads();

        uint32_t tAH = sb + cur * G_STAGE + GO_AH;
        uint32_t tAL = sb + cur * G_STAGE + GO_AL;
        uint32_t tBH = sb + cur * G_STAGE + GO_BH;
        uint32_t tBL = sb + cur * G_STAGE + GO_BL;
#pragma unroll
        for (int ks = 0; ks < 4; ks++) {
            int k0 = ks * 16;
            uint32_t ahf[2][4], alf[2][4];
            ldsmA(ahf[0], tAH, wm * 32, k0, lane);
            ldsmA(ahf[1], tAH, wm * 32 + 16, k0, lane);
            ldsmA(alf[0], tAL, wm * 32, k0, lane);
            ldsmA(alf[1], tAL, wm * 32 + 16, k0, lane);
#pragma unroll
            for (int nb = 0; nb < 4; nb++) {
                uint32_t bhf[4], blf[4];
                ldsmB(bhf, tBH, wn * 64 + nb * 16, k0, lane);
                ldsmB(blf, tBL, wn * 64 + nb * 16, k0, lane);
#pragma unroll
                for (int mi = 0; mi < 2; mi++) {
                    mma16816(acc[mi][2 * nb],     ahf[mi], bhf);
                    mma16816(acc[mi][2 * nb + 1], ahf[mi], bhf + 2);
                    mma16816(acc[mi][2 * nb],     ahf[mi], blf);
                    mma16816(acc[mi][2 * nb + 1], ahf[mi], blf + 2);
                    mma16816(acc[mi][2 * nb],     alf[mi], bhf);
                    mma16816(acc[mi][2 * nb + 1], alf[mi], bhf + 2);
                }
            }
        }
        __syncthreads();
    }

#pragma unroll
    for (int mi = 0; mi < 2; mi++)
#pragma unroll
        for (int nf = 0; nf < 8; nf++) {
            int row = by * 128 + wm * 32 + mi * 16 + (lane >> 2);
            int col = bx * 128 + wn * 64 + nf * 8 + ((lane & 3) << 1);
            *(float2*)(C + (size_t)row * N + col) = make_float2(acc[mi][nf][0], acc[mi][nf][1]);
            *(float2*)(C + (size_t)(row + 8) * N + col) = make_float2(acc[mi][nf][2], acc[mi][nf][3]);
        }
}

// ===================== RMSNorm + scatter (q/k bf16 splits, v fp16) ==========
__global__ __launch_bounds__(128) void rmsnorm_scatter(
    const float* __restrict__ gq1, const float* __restrict__ gk1,
    const float* __restrict__ gq2, const float* __restrict__ gk2)
{
    int warp = (blockIdx.x * blockDim.x + threadIdx.x) >> 5;
    int lane = threadIdx.x & 31;
    if (warp >= BH * NTOT) return;
    int n = warp % NTOT;
    int bh = warp / NTOT;
    int h = bh % HEADS;
    int b = bh / HEADS;

    const float* src;
    const float *gq, *gk;
    if (n < N1) { src = g_qkv1 + (size_t)(b * N1 + n) * (3 * DI); gq = gq1; gk = gk1; }
    else        { src = g_qkv2 + (size_t)(b * N2 + (n - N1)) * (3 * DI); gq = gq2; gk = gk2; }

    size_t dst = ((size_t)bh * NTOT + n) * DH;
    int c0 = h * DH + lane;
    int c1 = c0 + 32;

    float q0 = src[c0], q1 = src[c1];
    float ss = q0 * q0 + q1 * q1;
#pragma unroll
    for (int o = 16; o > 0; o >>= 1) ss += __shfl_xor_sync(0xffffffffu, ss, o);
    float rq = __fdividef(1.0f, fmaxf(sqrtf(ss), 1e-12f));   // ||q||=1 (1/8 scale folded)
    float qa = q0 * rq * gq[c0], qb = q1 * rq * gq[c1];
    {
        __nv_bfloat16 h0 = __float2bfloat16_rn(qa), h1 = __float2bfloat16_rn(qb);
        g_qh[dst + lane] = h0; g_qh[dst + lane + 32] = h1;
        g_ql[dst + lane]      = __float2bfloat16_rn(qa - __bfloat162float(h0));
        g_ql[dst + lane + 32] = __float2bfloat16_rn(qb - __bfloat162float(h1));
    }

    float k0 = src[DI + c0], k1 = src[DI + c1];
    float sk = k0 * k0 + k1 * k1;
#pragma unroll
    for (int o = 16; o > 0; o >>= 1) sk += __shfl_xor_sync(0xffffffffu, sk, o);
    float rk = __fdividef(8.0f, fmaxf(sqrtf(sk), 1e-12f));   // ||k||=8
    float ka = k0 * rk * gk[c0], kb = k1 * rk * gk[c1];
    {
        __nv_bfloat16 h0 = __float2bfloat16_rn(ka), h1 = __float2bfloat16_rn(kb);
        g_kh[dst + lane] = h0; g_kh[dst + lane + 32] = h1;
        g_kl[dst + lane]      = __float2bfloat16_rn(ka - __bfloat162float(h0));
        g_kl[dst + lane + 32] = __float2bfloat16_rn(kb - __bfloat162float(h1));
    }

    g_vh[dst + lane]      = __float2half_rn(src[2 * DI + c0]);
    g_vh[dst + lane + 32] = __float2half_rn(src[2 * DI + c1]);
}

// ===================== HMMA flash attention (3-stage cp.async) ==============
// 256 thr (8 warps), 128 q x 128 k, DH=64. QK split-3 bf16; PV plain fp16
// (V row-major in smem, B-frags via ldmatrix.trans). Fixed softmax max = 8.
#define AO_KH 0
#define AO_KL 16384
#define AO_V  32768
#define A_STAGE 49152
#define ATT_SMEM (3 * A_STAGE)

__global__ __launch_bounds__(256) void attn_mma()
{
    extern __shared__ char sm[];
    const uint32_t sb = smem_u32(sm);
    const int tid = threadIdx.x;
    const int lane = tid & 31;
    const int w = tid >> 5;
    const int qt = blockIdx.x, h = blockIdx.y, b = blockIdx.z;
    const int bh = b * HEADS + h;

    const size_t kbase = (size_t)bh * NTOT * DH;

    // ---- stage Q into stage-0 KH/KL, extract frags to registers ----
    uint32_t qhf[4][4], qlf[4][4];
    {
        const __nv_bfloat16* qh = g_qh + kbase + (size_t)qt * 128 * DH;
        const __nv_bfloat16* ql = g_ql + kbase + (size_t)qt * 128 * DH;
#pragma unroll
        for (int i = 0; i < 4; i++) {
            int idx = i * 256 + tid;
            int r = idx >> 3, c = idx & 7;
            uint32_t so = chunk_off(r, c);
            size_t go = (size_t)r * DH + c * 8;
            *(uint4*)(sm + AO_KH + so) = *(const uint4*)(qh + go);
            *(uint4*)(sm + AO_KL + so) = *(const uint4*)(ql + go);
        }
        __syncthreads();
#pragma unroll
        for (int ks = 0; ks < 4; ks++) {
            ldsmA(qhf[ks], sb + AO_KH, w * 16, ks * 16, lane);
            ldsmA(qlf[ks], sb + AO_KL, w * 16, ks * 16, lane);
        }
        __syncthreads();
    }

    const int lr = tid >> 3, lc = tid & 7;

    auto issue = [&](int kt, int stage) {
        uint32_t base = sb + stage * A_STAGE;
#pragma unroll
        for (int i = 0; i < 4; i++) {
            int r = lr + i * 32;
            uint32_t so = chunk_off(r, lc);
            size_t go = kbase + (size_t)(kt * 128 + r) * DH + lc * 8;
            CP16(base + AO_KH + so, g_kh + go);
            CP16(base + AO_KL + so, g_kl + go);
            CP16(base + AO_V + so, g_vh + go);
        }
        CP_COMMIT();
    };

    float O[8][4];
#pragma unroll
    for (int j = 0; j < 8; j++)
#pragma unroll
        for (int q = 0; q < 4; q++) O[j][q] = 0.0f;
    float lsum0 = 0.0f, lsum1 = 0.0f;

    const int ktiles = NTOT / 128;
    issue(0, 0);
    issue(1, 1);

    for (int kt = 0; kt < ktiles; kt++) {
        int cur = kt - (kt / 3) * 3;
        if (kt + 2 < ktiles) { issue(kt + 2, (kt + 2) % 3); CP_WAIT2(); }
        else if (kt + 1 < ktiles) CP_WAIT1();
        else CP_WAIT0();
        __syncthreads();

        uint32_t tKH = sb + cur * A_STAGE + AO_KH;
        uint32_t tKL = sb + cur * A_STAGE + AO_KL;
        uint32_t tV  = sb + cur * A_STAGE + AO_V;

        // ---- S = Q K^T (split-3 bf16) ----
        float S[16][4];
#pragma unroll
        for (int j = 0; j < 16; j++)
#pragma unroll
            for (int q = 0; q < 4; q++) S[j][q] = 0.0f;
#pragma unroll
        for (int ks = 0; ks < 4; ks++) {
            int k0 = ks * 16;
#pragma unroll
            for (int nb = 0; nb < 8; nb++) {
                uint32_t bhf[4], blf[4];
                ldsmB(bhf, tKH, nb * 16, k0, lane);
                ldsmB(blf, tKL, nb * 16, k0, lane);
                mma16816(S[2 * nb],     qhf[ks], bhf);
                mma16816(S[2 * nb + 1], qhf[ks], bhf + 2);
                mma16816(S[2 * nb],     qhf[ks], blf);
                mma16816(S[2 * nb + 1], qhf[ks], blf + 2);
                mma16816(S[2 * nb],     qlf[ks], bhf);
                mma16816(S[2 * nb + 1], qlf[ks], bhf + 2);
            }
        }

        // ---- softclamp + exp (fixed max 8), row sums ----
        float rs0 = 0.0f, rs1 = 0.0f;
#pragma unroll
        for (int j = 0; j < 16; j++) {
            S[j][0] = softclamp_exp(S[j][0]); rs0 += S[j][0];
            S[j][1] = softclamp_exp(S[j][1]); rs0 += S[j][1];
            S[j][2] = softclamp_exp(S[j][2]); rs1 += S[j][2];
            S[j][3] = softclamp_exp(S[j][3]); rs1 += S[j][3];
        }
        rs0 += __shfl_xor_sync(0xffffffffu, rs0, 1);
        rs0 += __shfl_xor_sync(0xffffffffu, rs0, 2);
        rs1 += __shfl_xor_sync(0xffffffffu, rs1, 1);
        rs1 += __shfl_xor_sync(0xffffffffu, rs1, 2);
        lsum0 += rs0;
        lsum1 += rs1;

        // ---- O += P V (plain fp16, V via ldmatrix.trans) ----
#pragma unroll
        for (int kk = 0; kk < 8; kk++) {
            uint32_t pf[4];
#pragma unroll
            for (int q = 0; q < 4; q++) {
                float p0 = S[2 * kk + (q >> 1)][(q & 1) * 2];
                float p1 = S[2 * kk + (q >> 1)][(q & 1) * 2 + 1];
                pf[q] = pack_h2(p0, p1);
            }
#pragma unroll
            for (int nb = 0; nb < 4; nb++) {
                uint32_t vb[4];
                ldsmBT(vb, tV, nb * 16, kk * 16, lane);
                mma16816h(O[2 * nb],     pf, vb);
                mma16816h(O[2 * nb + 1], pf, vb + 2);
            }
        }
        __syncthreads();
    }

    // ---- epilogue: normalize, write split-bf16 to g_ao ----
    float inv0 = __fdividef(1.0f, lsum0);
    float inv1 = __fdividef(1.0f, lsum1);
    int rlo = qt * 128 + w * 16 + (lane >> 2);
    int colb = h * DH + ((lane & 3) << 1);
    size_t o_lo = ((size_t)(b * NTOT + rlo)) * DI + colb;
    size_t o_hi = ((size_t)(b * NTOT + rlo + 8)) * DI + colb;
#pragma unroll
    for (int nf = 0; nf < 8; nf++) {
        float v0 = O[nf][0] * inv0, v1 = O[nf][1] * inv0;
        __nv_bfloat16 h0 = __float2bfloat16_rn(v0), h1 = __float2bfloat16_rn(v1);
        *(uint32_t*)(g_aoh + o_lo + nf * 8) = pack_bf2(h0, h1);
        *(uint32_t*)(g_aol + o_lo + nf * 8) = pack_bf2(
            __float2bfloat16_rn(v0 - __bfloat162float(h0)),
            __float2bfloat16_rn(v1 - __bfloat162float(h1)));
        float v2 = O[nf][2] * inv1, v3 = O[nf][3] * inv1;
        __nv_bfloat16 h2 = __float2bfloat16_rn(v2), h3 = __float2bfloat16_rn(v3);
        *(uint32_t*)(g_aoh + o_hi + nf * 8) = pack_bf2(h2, h3);
        *(uint32_t*)(g_aol + o_hi + nf * 8) = pack_bf2(
            __float2bfloat16_rn(v2 - __bfloat162float(h2)),
            __float2bfloat16_rn(v3 - __bfloat162float(h3)));
    }
}

// ===================== launcher =====================
extern "C" void kernel_launch(void* const* d_in, const int* in_sizes, int n_in,
                              void* d_out, int out_size)
{
    (void)in_sizes; (void)n_in; (void)out_size;
    const float* x1    = (const float*)d_in[0];
    const float* x2    = (const float*)d_in[1];
    const float* Wqkv1 = (const float*)d_in[4];
    const float* Wqkv2 = (const float*)d_in[5];
    const float* gq1   = (const float*)d_in[6];
    const float* gk1   = (const float*)d_in[7];
    const float* gq2   = (const float*)d_in[8];
    const float* gk2   = (const float*)d_in[9];
    const float* Wout1 = (const float*)d_in[10];
    const float* Wout2 = (const float*)d_in[11];
    float* out = (float*)d_out;

    cudaFuncSetAttribute(gemm_mma, cudaFuncAttributeMaxDynamicSharedMemorySize, GEMM_SMEM);
    cudaFuncSetAttribute(attn_mma, cudaFuncAttributeMaxDynamicSharedMemorySize, ATT_SMEM);

    void* p;
    cudaGetSymbolAddress(&p, g_x1h);  __nv_bfloat16* x1h = (__nv_bfloat16*)p;
    cudaGetSymbolAddress(&p, g_x1l);  __nv_bfloat16* x1l = (__nv_bfloat16*)p;
    cudaGetSymbolAddress(&p, g_x2h);  __nv_bfloat16* x2h = (__nv_bfloat16*)p;
    cudaGetSymbolAddress(&p, g_x2l);  __nv_bfloat16* x2l = (__nv_bfloat16*)p;
    cudaGetSymbolAddress(&p, g_w1h);  __nv_bfloat16* w1h = (__nv_bfloat16*)p;
    cudaGetSymbolAddress(&p, g_w1l);  __nv_bfloat16* w1l = (__nv_bfloat16*)p;
    cudaGetSymbolAddress(&p, g_w2h);  __nv_bfloat16* w2h = (__nv_bfloat16*)p;
    cudaGetSymbolAddress(&p, g_w2l);  __nv_bfloat16* w2l = (__nv_bfloat16*)p;
    cudaGetSymbolAddress(&p, g_wo1h); __nv_bfloat16* wo1h = (__nv_bfloat16*)p;
    cudaGetSymbolAddress(&p, g_wo1l); __nv_bfloat16* wo1l = (__nv_bfloat16*)p;
    cudaGetSymbolAddress(&p, g_wo2h); __nv_bfloat16* wo2h = (__nv_bfloat16*)p;
    cudaGetSymbolAddress(&p, g_wo2l); __nv_bfloat16* wo2l = (__nv_bfloat16*)p;
    cudaGetSymbolAddress(&p, g_qkv1); float* qkv1 = (float*)p;
    cudaGetSymbolAddress(&p, g_qkv2); float* qkv2 = (float*)p;
    cudaGetSymbolAddress(&p, g_aoh);  __nv_bfloat16* aoh = (__nv_bfloat16*)p;
    cudaGetSymbolAddress(&p, g_aol);  __nv_bfloat16* aol = (__nv_bfloat16*)p;

    const int BIG = 1 << 30;

    // 1) fused split of x1/x2
    split_all<<<SPLIT_B1 + SPLIT_B2, 256>>>(x1, x1h, x1l, x2, x2h, x2l);
    // 2) fused weight transposes
    wtrans_all<<<7168, 256>>>(Wqkv1, w1h, w1l, Wqkv2, w2h, w2l,
                              Wout1, wo1h, wo1l, Wout2, wo2h, wo2l);
    // 3-4) QKV projections
    gemm_mma<<<dim3(3 * DI / 128, BATCH * N1 / 128), 256, GEMM_SMEM>>>(
        x1h, x1l, w1h, w1l, qkv1, BATCH * N1, D1, 3 * DI, BIG, 0, 0);
    gemm_mma<<<dim3(3 * DI / 128, BATCH * N2 / 128), 256, GEMM_SMEM>>>(
        x2h, x2l, w2h, w2l, qkv2, BATCH * N2, D2, 3 * DI, BIG, 0, 0);
    // 5) RMSNorm + scatter (v fp16 direct)
    rmsnorm_scatter<<<BH * NTOT / 4, 128>>>(gq1, gk1, gq2, gk2);
    // 6) attention  (launch #6 -> ncu captures this)
    attn_mma<<<dim3(NTOT / 128, HEADS, BATCH), 256, ATT_SMEM>>>();
    // 7-8) output projections (row-remapped reads of concat ao)
    gemm_mma<<<dim3(D1 / 128, BATCH * N1 / 128), 256, GEMM_SMEM>>>(
        aoh, aol, wo1h, wo1l, out, BATCH * N1, DI, D1, 2048, 512, 0);
    gemm_mma<<<dim3(D2 / 128, BATCH * N2 / 128), 256, GEMM_SMEM>>>(
        aoh, aol, wo2h, wo2l, out + (size_t)BATCH * N1 * D1, BATCH * N2, DI, D2, 512, 2048, 2048);
}

// round 7
// speedup vs baseline: 5.2571x; 1.0769x over previous
#include <cuda_runtime.h>
#include <cuda_bf16.h>
#include <cuda_fp16.h>
#include <cstdint>
#include <math.h>

#define BATCH 2
#define N1 2048
#define N2 512
#define NTOT 2560
#define D1 1024
#define D2 768
#define HEADS 16
#define DH 64
#define DI 1024
#define BH (BATCH * HEADS)

// ===================== scratch (device globals) =====================
__device__ __align__(256) __nv_bfloat16 g_x1h[BATCH*N1*D1], g_x1l[BATCH*N1*D1];
__device__ __align__(256) __nv_bfloat16 g_x2h[BATCH*N2*D2], g_x2l[BATCH*N2*D2];
__device__ __align__(256) __nv_bfloat16 g_w1h[3*DI*D1],  g_w1l[3*DI*D1];
__device__ __align__(256) __nv_bfloat16 g_w2h[3*DI*D2],  g_w2l[3*DI*D2];
__device__ __align__(256) __nv_bfloat16 g_wo1h[D1*DI],   g_wo1l[D1*DI];
__device__ __align__(256) __nv_bfloat16 g_wo2h[D2*DI],   g_wo2l[D2*DI];
__device__ __align__(256) float g_qkv1[BATCH*N1*3*DI];
__device__ __align__(256) float g_qkv2[BATCH*N2*3*DI];
__device__ __align__(256) __nv_bfloat16 g_qh[BH*NTOT*DH], g_ql[BH*NTOT*DH];
__device__ __align__(256) __nv_bfloat16 g_kh[BH*NTOT*DH], g_kl[BH*NTOT*DH];
__device__ __align__(256) __half g_vh[BH*NTOT*DH];
__device__ __align__(256) __nv_bfloat16 g_aoh[BATCH*NTOT*DI], g_aol[BATCH*NTOT*DI];

// ===================== helpers =====================
__device__ __forceinline__ uint32_t smem_u32(const void* p) {
    uint32_t a;
    asm("{ .reg .u64 t; cvta.to.shared.u64 t, %1; cvt.u32.u64 %0, t; }" : "=r"(a) : "l"(p));
    return a;
}
__device__ __forceinline__ uint32_t pack_bf2(__nv_bfloat16 a, __nv_bfloat16 b) {
    return (uint32_t)__bfloat16_as_ushort(a) | ((uint32_t)__bfloat16_as_ushort(b) << 16);
}
__device__ __forceinline__ uint32_t pack_h2(float a, float b) {
    __half2 h = __floats2half2_rn(a, b);
    return *(uint32_t*)&h;
}
__device__ __forceinline__ uint32_t chunk_off(int r, int c) {
    return (uint32_t)(((r << 3) + (c ^ (r & 7))) << 4);
}
__device__ __forceinline__ void ldsm4(uint32_t (&d)[4], uint32_t a) {
    asm volatile("ldmatrix.sync.aligned.m8n8.x4.shared.b16 {%0,%1,%2,%3}, [%4];"
        : "=r"(d[0]), "=r"(d[1]), "=r"(d[2]), "=r"(d[3]) : "r"(a));
}
__device__ __forceinline__ void ldsm4t(uint32_t (&d)[4], uint32_t a) {
    asm volatile("ldmatrix.sync.aligned.m8n8.x4.trans.shared.b16 {%0,%1,%2,%3}, [%4];"
        : "=r"(d[0]), "=r"(d[1]), "=r"(d[2]), "=r"(d[3]) : "r"(a));
}
__device__ __forceinline__ void ldsmA(uint32_t (&d)[4], uint32_t tile, int row0, int k0, int lane) {
    int g = lane >> 3;
    int r = row0 + (lane & 7) + ((g & 1) << 3);
    int c = (k0 >> 3) + (g >> 1);
    ldsm4(d, tile + chunk_off(r, c));
}
__device__ __forceinline__ void ldsmB(uint32_t (&d)[4], uint32_t tile, int n0, int k0, int lane) {
    int g = lane >> 3;
    int r = n0 + (lane & 7) + ((g >> 1) << 3);
    int c = (k0 >> 3) + (g & 1);
    ldsm4(d, tile + chunk_off(r, c));
}
__device__ __forceinline__ void ldsmBT(uint32_t (&d)[4], uint32_t tile, int n0, int k0, int lane) {
    int g = lane >> 3;
    int r = k0 + (lane & 7) + ((g & 1) << 3);
    int c = (n0 >> 3) + (g >> 1);
    ldsm4t(d, tile + chunk_off(r, c));
}
__device__ __forceinline__ void mma16816(float (&c)[4], const uint32_t (&a)[4], const uint32_t* b) {
    asm volatile("mma.sync.aligned.m16n8k16.row.col.f32.bf16.bf16.f32 "
        "{%0,%1,%2,%3}, {%4,%5,%6,%7}, {%8,%9}, {%0,%1,%2,%3};"
        : "+f"(c[0]), "+f"(c[1]), "+f"(c[2]), "+f"(c[3])
        : "r"(a[0]), "r"(a[1]), "r"(a[2]), "r"(a[3]), "r"(b[0]), "r"(b[1]));
}
__device__ __forceinline__ void mma16816h(float (&c)[4], const uint32_t (&a)[4], const uint32_t* b) {
    asm volatile("mma.sync.aligned.m16n8k16.row.col.f32.f16.f16.f32 "
        "{%0,%1,%2,%3}, {%4,%5,%6,%7}, {%8,%9}, {%0,%1,%2,%3};"
        : "+f"(c[0]), "+f"(c[1]), "+f"(c[2]), "+f"(c[3])
        : "r"(a[0]), "r"(a[1]), "r"(a[2]), "r"(a[3]), "r"(b[0]), "r"(b[1]));
}
__device__ __forceinline__ float softclamp_exp(float s) {
    float u2 = s * s * 4.0e-4f;
    float cl = s * fmaf(u2, fmaf(u2, 0.13333334f, -0.33333334f), 1.0f);
    return __expf(cl - 8.0f);
}
#define CP16(dst, src) asm volatile("cp.async.cg.shared.global [%0], [%1], 16;" :: "r"(dst), "l"(src))
#define CP_COMMIT()    asm volatile("cp.async.commit_group;" ::: "memory")
#define CP_WAIT2()     asm volatile("cp.async.wait_group 2;" ::: "memory")
#define CP_WAIT1()     asm volatile("cp.async.wait_group 1;" ::: "memory")
#define CP_WAIT0()     asm volatile("cp.async.wait_group 0;" ::: "memory")

// ===================== fused pre-pass: split x1 & x2 =====================
#define SPLIT_B1 ((BATCH * N1 * D1) / 1024)
#define SPLIT_B2 ((BATCH * N2 * D2) / 1024)
__global__ __launch_bounds__(256) void split_all(
    const float* __restrict__ x1, __nv_bfloat16* __restrict__ h1, __nv_bfloat16* __restrict__ l1,
    const float* __restrict__ x2, __nv_bfloat16* __restrict__ h2, __nv_bfloat16* __restrict__ l2)
{
    int bid = blockIdx.x;
    const float* in; __nv_bfloat16 *hi, *lo; int i;
    if (bid < SPLIT_B1) { in = x1; hi = h1; lo = l1; i = (bid * 256 + threadIdx.x) * 4; }
    else { in = x2; hi = h2; lo = l2; i = ((bid - SPLIT_B1) * 256 + threadIdx.x) * 4; }
    float4 v = *(const float4*)(in + i);
    __nv_bfloat16 h0 = __float2bfloat16_rn(v.x), hb1 = __float2bfloat16_rn(v.y);
    __nv_bfloat16 h2b = __float2bfloat16_rn(v.z), h3 = __float2bfloat16_rn(v.w);
    uint2 wh = make_uint2(pack_bf2(h0, hb1), pack_bf2(h2b, h3));
    uint2 wl = make_uint2(
        pack_bf2(__float2bfloat16_rn(v.x - __bfloat162float(h0)), __float2bfloat16_rn(v.y - __bfloat162float(hb1))),
        pack_bf2(__float2bfloat16_rn(v.z - __bfloat162float(h2b)), __float2bfloat16_rn(v.w - __bfloat162float(h3))));
    *(uint2*)(hi + i) = wh;
    *(uint2*)(lo + i) = wl;
}

// ===================== fused pre-pass: weight transposes =====================
__global__ __launch_bounds__(256) void wtrans_all(
    const float* __restrict__ W0, __nv_bfloat16* __restrict__ h0, __nv_bfloat16* __restrict__ l0,
    const float* __restrict__ W1, __nv_bfloat16* __restrict__ h1, __nv_bfloat16* __restrict__ l1,
    const float* __restrict__ W2, __nv_bfloat16* __restrict__ h2, __nv_bfloat16* __restrict__ l2,
    const float* __restrict__ W3, __nv_bfloat16* __restrict__ h3, __nv_bfloat16* __restrict__ l3)
{
    __shared__ float t[32][33];
    int bid = blockIdx.x;
    const float* W; __nv_bfloat16 *th, *tl; int K, N, nbx, local;
    if (bid < 3072)      { W = W0; th = h0; tl = l0; K = D1; N = 3 * DI; nbx = 96; local = bid; }
    else if (bid < 5376) { W = W1; th = h1; tl = l1; K = D2; N = 3 * DI; nbx = 96; local = bid - 3072; }
    else if (bid < 6400) { W = W2; th = h2; tl = l2; K = DI; N = D1;     nbx = 32; local = bid - 5376; }
    else                 { W = W3; th = h3; tl = l3; K = DI; N = D2;     nbx = 24; local = bid - 6400; }
    int n0 = (local % nbx) * 32, k0 = (local / nbx) * 32;
    int tx = threadIdx.x & 31, ty = threadIdx.x >> 5;
#pragma unroll
    for (int i = ty; i < 32; i += 8)
        t[i][tx] = W[(size_t)(k0 + i) * N + n0 + tx];
    __syncthreads();
#pragma unroll
    for (int i = ty; i < 32; i += 8) {
        float v = t[tx][i];
        __nv_bfloat16 h = __float2bfloat16_rn(v);
        size_t o = (size_t)(n0 + i) * K + k0 + tx;
        th[o] = h;
        tl[o] = __float2bfloat16_rn(v - __bfloat162float(h));
    }
}

// ===================== split-bf16 HMMA GEMM (dual-job, 3-stage) =============
struct GemmJob {
    const __nv_bfloat16 *Ah, *Al, *Bh, *Bl;
    float* C;
    int K, N, chunk, pad, off, nbx, nblocks;
};

#define GO_AH 0
#define GO_AL 16384
#define GO_BH 32768
#define GO_BL 49152
#define G_STAGE 65536
#define GEMM_SMEM (3 * G_STAGE)

__global__ __launch_bounds__(256) void gemm_mma(GemmJob j0, GemmJob j1)
{
    extern __shared__ char sm[];
    const uint32_t sb = smem_u32(sm);
    const int tid = threadIdx.x;
    const int lane = tid & 31;
    const int w = tid >> 5;
    const int wm = w & 3, wn = w >> 2;

    GemmJob j;
    int bid = blockIdx.x;
    if (bid < j0.nblocks) j = j0;
    else { j = j1; bid -= j0.nblocks; }
    const int bx = bid % j.nbx, by = bid / j.nbx;
    const int K = j.K, N = j.N;

    const int lr = tid >> 3;
    const int lc = tid & 7;

    auto issue = [&](int kt, int stage) {
        uint32_t base = sb + stage * G_STAGE;
#pragma unroll
        for (int i = 0; i < 4; i++) {
            int r = lr + i * 32;
            uint32_t so = chunk_off(r, lc);
            int gr = by * 128 + r;
            gr = gr + j.off + (gr / j.chunk) * j.pad;
            size_t ao = (size_t)gr * K + kt * 64 + lc * 8;
            CP16(base + GO_AH + so, j.Ah + ao);
            CP16(base + GO_AL + so, j.Al + ao);
            size_t bo = (size_t)(bx * 128 + r) * K + kt * 64 + lc * 8;
            CP16(base + GO_BH + so, j.Bh + bo);
            CP16(base + GO_BL + so, j.Bl + bo);
        }
        CP_COMMIT();
    };

    float acc[2][8][4];
#pragma unroll
    for (int i = 0; i < 2; i++)
#pragma unroll
        for (int jj = 0; jj < 8; jj++)
#pragma unroll
            for (int q = 0; q < 4; q++) acc[i][jj][q] = 0.0f;

    const int ktiles = K >> 6;
    issue(0, 0);
    issue(1, 1);

    for (int kt = 0; kt < ktiles; kt++) {
        int cur = kt - (kt / 3) * 3;
        if (kt + 2 < ktiles) { issue(kt + 2, (kt + 2) % 3); CP_WAIT2(); }
        else if (kt + 1 < ktiles) CP_WAIT1();
        else CP_WAIT0();
        __syncthreads();

        uint32_t tAH = sb + cur * G_STAGE + GO_AH;
        uint32_t tAL = sb + cur * G_STAGE + GO_AL;
        uint32_t tBH = sb + cur * G_STAGE + GO_BH;
        uint32_t tBL = sb + cur * G_STAGE + GO_BL;
#pragma unroll
        for (int ks = 0; ks < 4; ks++) {
            int k0 = ks * 16;
            uint32_t ahf[2][4], alf[2][4];
            ldsmA(ahf[0], tAH, wm * 32, k0, lane);
            ldsmA(ahf[1], tAH, wm * 32 + 16, k0, lane);
            ldsmA(alf[0], tAL, wm * 32, k0, lane);
            ldsmA(alf[1], tAL, wm * 32 + 16, k0, lane);
            uint32_t bhf[4][4], blf[4][4];
#pragma unroll
            for (int nb = 0; nb < 4; nb++) {
                ldsmB(bhf[nb], tBH, wn * 64 + nb * 16, k0, lane);
                ldsmB(blf[nb], tBL, wn * 64 + nb * 16, k0, lane);
            }
            // term-major: each accumulator revisited at distance 16
#pragma unroll
            for (int nb = 0; nb < 4; nb++)
#pragma unroll
                for (int mi = 0; mi < 2; mi++) {
                    mma16816(acc[mi][2 * nb],     ahf[mi], bhf[nb]);
                    mma16816(acc[mi][2 * nb + 1], ahf[mi], bhf[nb] + 2);
                }
#pragma unroll
            for (int nb = 0; nb < 4; nb++)
#pragma unroll
                for (int mi = 0; mi < 2; mi++) {
                    mma16816(acc[mi][2 * nb],     ahf[mi], blf[nb]);
                    mma16816(acc[mi][2 * nb + 1], ahf[mi], blf[nb] + 2);
                }
#pragma unroll
            for (int nb = 0; nb < 4; nb++)
#pragma unroll
                for (int mi = 0; mi < 2; mi++) {
                    mma16816(acc[mi][2 * nb],     alf[mi], bhf[nb]);
                    mma16816(acc[mi][2 * nb + 1], alf[mi], bhf[nb] + 2);
                }
        }
        __syncthreads();
    }

#pragma unroll
    for (int mi = 0; mi < 2; mi++)
#pragma unroll
        for (int nf = 0; nf < 8; nf++) {
            int row = by * 128 + wm * 32 + mi * 16 + (lane >> 2);
            int col = bx * 128 + wn * 64 + nf * 8 + ((lane & 3) << 1);
            *(float2*)(j.C + (size_t)row * N + col) = make_float2(acc[mi][nf][0], acc[mi][nf][1]);
            *(float2*)(j.C + (size_t)(row + 8) * N + col) = make_float2(acc[mi][nf][2], acc[mi][nf][3]);
        }
}

// ===================== RMSNorm + scatter =====================
__global__ __launch_bounds__(128) void rmsnorm_scatter(
    const float* __restrict__ gq1, const float* __restrict__ gk1,
    const float* __restrict__ gq2, const float* __restrict__ gk2)
{
    int warp = (blockIdx.x * blockDim.x + threadIdx.x) >> 5;
    int lane = threadIdx.x & 31;
    if (warp >= BH * NTOT) return;
    int n = warp % NTOT;
    int bh = warp / NTOT;
    int h = bh % HEADS;
    int b = bh / HEADS;

    const float* src;
    const float *gq, *gk;
    if (n < N1) { src = g_qkv1 + (size_t)(b * N1 + n) * (3 * DI); gq = gq1; gk = gk1; }
    else        { src = g_qkv2 + (size_t)(b * N2 + (n - N1)) * (3 * DI); gq = gq2; gk = gk2; }

    size_t dst = ((size_t)bh * NTOT + n) * DH;
    int c0 = h * DH + lane;
    int c1 = c0 + 32;

    float q0 = src[c0], q1 = src[c1];
    float ss = q0 * q0 + q1 * q1;
#pragma unroll
    for (int o = 16; o > 0; o >>= 1) ss += __shfl_xor_sync(0xffffffffu, ss, o);
    float rq = __fdividef(1.0f, fmaxf(sqrtf(ss), 1e-12f));
    float qa = q0 * rq * gq[c0], qb = q1 * rq * gq[c1];
    {
        __nv_bfloat16 h0 = __float2bfloat16_rn(qa), h1 = __float2bfloat16_rn(qb);
        g_qh[dst + lane] = h0; g_qh[dst + lane + 32] = h1;
        g_ql[dst + lane]      = __float2bfloat16_rn(qa - __bfloat162float(h0));
        g_ql[dst + lane + 32] = __float2bfloat16_rn(qb - __bfloat162float(h1));
    }

    float k0 = src[DI + c0], k1 = src[DI + c1];
    float sk = k0 * k0 + k1 * k1;
#pragma unroll
    for (int o = 16; o > 0; o >>= 1) sk += __shfl_xor_sync(0xffffffffu, sk, o);
    float rk = __fdividef(8.0f, fmaxf(sqrtf(sk), 1e-12f));
    float ka = k0 * rk * gk[c0], kb = k1 * rk * gk[c1];
    {
        __nv_bfloat16 h0 = __float2bfloat16_rn(ka), h1 = __float2bfloat16_rn(kb);
        g_kh[dst + lane] = h0; g_kh[dst + lane + 32] = h1;
        g_kl[dst + lane]      = __float2bfloat16_rn(ka - __bfloat162float(h0));
        g_kl[dst + lane + 32] = __float2bfloat16_rn(kb - __bfloat162float(h1));
    }

    g_vh[dst + lane]      = __float2half_rn(src[2 * DI + c0]);
    g_vh[dst + lane + 32] = __float2half_rn(src[2 * DI + c1]);
}

// ===================== HMMA flash attention (3-stage) =====================
#define AO_KH 0
#define AO_KL 16384
#define AO_V  32768
#define A_STAGE 49152
#define ATT_SMEM (3 * A_STAGE)

__global__ __launch_bounds__(256) void attn_mma()
{
    extern __shared__ char sm[];
    const uint32_t sb = smem_u32(sm);
    const int tid = threadIdx.x;
    const int lane = tid & 31;
    const int w = tid >> 5;
    const int qt = blockIdx.x, h = blockIdx.y, b = blockIdx.z;
    const int bh = b * HEADS + h;

    const size_t kbase = (size_t)bh * NTOT * DH;

    // ---- stage Q into stage-0 KH/KL, extract frags to registers ----
    uint32_t qhf[4][4], qlf[4][4];
    {
        const __nv_bfloat16* qh = g_qh + kbase + (size_t)qt * 128 * DH;
        const __nv_bfloat16* ql = g_ql + kbase + (size_t)qt * 128 * DH;
#pragma unroll
        for (int i = 0; i < 4; i++) {
            int idx = i * 256 + tid;
            int r = idx >> 3, c = idx & 7;
            uint32_t so = chunk_off(r, c);
            size_t go = (size_t)r * DH + c * 8;
            *(uint4*)(sm + AO_KH + so) = *(const uint4*)(qh + go);
            *(uint4*)(sm + AO_KL + so) = *(const uint4*)(ql + go);
        }
        __syncthreads();
#pragma unroll
        for (int ks = 0; ks < 4; ks++) {
            ldsmA(qhf[ks], sb + AO_KH, w * 16, ks * 16, lane);
            ldsmA(qlf[ks], sb + AO_KL, w * 16, ks * 16, lane);
        }
        __syncthreads();
    }

    const int lr = tid >> 3, lc = tid & 7;

    auto issue = [&](int kt, int stage) {
        uint32_t base = sb + stage * A_STAGE;
#pragma unroll
        for (int i = 0; i < 4; i++) {
            int r = lr + i * 32;
            uint32_t so = chunk_off(r, lc);
            size_t go = kbase + (size_t)(kt * 128 + r) * DH + lc * 8;
            CP16(base + AO_KH + so, g_kh + go);
            CP16(base + AO_KL + so, g_kl + go);
            CP16(base + AO_V + so, g_vh + go);
        }
        CP_COMMIT();
    };

    float O[8][4];
#pragma unroll
    for (int j = 0; j < 8; j++)
#pragma unroll
        for (int q = 0; q < 4; q++) O[j][q] = 0.0f;
    float lsum0 = 0.0f, lsum1 = 0.0f;

    const int ktiles = NTOT / 128;
    issue(0, 0);
    issue(1, 1);

    for (int kt = 0; kt < ktiles; kt++) {
        int cur = kt - (kt / 3) * 3;
        if (kt + 2 < ktiles) { issue(kt + 2, (kt + 2) % 3); CP_WAIT2(); }
        else if (kt + 1 < ktiles) CP_WAIT1();
        else CP_WAIT0();
        __syncthreads();

        uint32_t tKH = sb + cur * A_STAGE + AO_KH;
        uint32_t tKL = sb + cur * A_STAGE + AO_KL;
        uint32_t tV  = sb + cur * A_STAGE + AO_V;

        // ---- S = Q K^T (split-3 bf16), term-major in nb-pairs ----
        float S[16][4];
#pragma unroll
        for (int j = 0; j < 16; j++)
#pragma unroll
            for (int q = 0; q < 4; q++) S[j][q] = 0.0f;
#pragma unroll
        for (int ks = 0; ks < 4; ks++) {
            int k0 = ks * 16;
#pragma unroll
            for (int g = 0; g < 4; g++) {       // nb pairs: (2g, 2g+1)
                uint32_t bhf[2][4], blf[2][4];
#pragma unroll
                for (int u = 0; u < 2; u++) {
                    ldsmB(bhf[u], tKH, (2 * g + u) * 16, k0, lane);
                    ldsmB(blf[u], tKL, (2 * g + u) * 16, k0, lane);
                }
#pragma unroll
                for (int u = 0; u < 2; u++) {
                    int nb = 2 * g + u;
                    mma16816(S[2 * nb],     qhf[ks], bhf[u]);
                    mma16816(S[2 * nb + 1], qhf[ks], bhf[u] + 2);
                }
#pragma unroll
                for (int u = 0; u < 2; u++) {
                    int nb = 2 * g + u;
                    mma16816(S[2 * nb],     qhf[ks], blf[u]);
                    mma16816(S[2 * nb + 1], qhf[ks], blf[u] + 2);
                }
#pragma unroll
                for (int u = 0; u < 2; u++) {
                    int nb = 2 * g + u;
                    mma16816(S[2 * nb],     qlf[ks], bhf[u]);
                    mma16816(S[2 * nb + 1], qlf[ks], bhf[u] + 2);
                }
            }
        }

        // ---- softclamp + exp (fixed max 8), row sums ----
        float rs0 = 0.0f, rs1 = 0.0f;
#pragma unroll
        for (int j = 0; j < 16; j++) {
            S[j][0] = softclamp_exp(S[j][0]); rs0 += S[j][0];
            S[j][1] = softclamp_exp(S[j][1]); rs0 += S[j][1];
            S[j][2] = softclamp_exp(S[j][2]); rs1 += S[j][2];
            S[j][3] = softclamp_exp(S[j][3]); rs1 += S[j][3];
        }
        rs0 += __shfl_xor_sync(0xffffffffu, rs0, 1);
        rs0 += __shfl_xor_sync(0xffffffffu, rs0, 2);
        rs1 += __shfl_xor_sync(0xffffffffu, rs1, 1);
        rs1 += __shfl_xor_sync(0xffffffffu, rs1, 2);
        lsum0 += rs0;
        lsum1 += rs1;

        // ---- O += P V (plain fp16, V via ldmatrix.trans) ----
#pragma unroll
        for (int kk = 0; kk < 8; kk++) {
            uint32_t pf[4];
#pragma unroll
            for (int q = 0; q < 4; q++) {
                float p0 = S[2 * kk + (q >> 1)][(q & 1) * 2];
                float p1 = S[2 * kk + (q >> 1)][(q & 1) * 2 + 1];
                pf[q] = pack_h2(p0, p1);
            }
#pragma unroll
            for (int nb = 0; nb < 4; nb++) {
                uint32_t vb[4];
                ldsmBT(vb, tV, nb * 16, kk * 16, lane);
                mma16816h(O[2 * nb],     pf, vb);
                mma16816h(O[2 * nb + 1], pf, vb + 2);
            }
        }
        __syncthreads();
    }

    // ---- epilogue ----
    float inv0 = __fdividef(1.0f, lsum0);
    float inv1 = __fdividef(1.0f, lsum1);
    int rlo = qt * 128 + w * 16 + (lane >> 2);
    int colb = h * DH + ((lane & 3) << 1);
    size_t o_lo = ((size_t)(b * NTOT + rlo)) * DI + colb;
    size_t o_hi = ((size_t)(b * NTOT + rlo + 8)) * DI + colb;
#pragma unroll
    for (int nf = 0; nf < 8; nf++) {
        float v0 = O[nf][0] * inv0, v1 = O[nf][1] * inv0;
        __nv_bfloat16 h0 = __float2bfloat16_rn(v0), h1 = __float2bfloat16_rn(v1);
        *(uint32_t*)(g_aoh + o_lo + nf * 8) = pack_bf2(h0, h1);
        *(uint32_t*)(g_aol + o_lo + nf * 8) = pack_bf2(
            __float2bfloat16_rn(v0 - __bfloat162float(h0)),
            __float2bfloat16_rn(v1 - __bfloat162float(h1)));
        float v2 = O[nf][2] * inv1, v3 = O[nf][3] * inv1;
        __nv_bfloat16 h2 = __float2bfloat16_rn(v2), h3 = __float2bfloat16_rn(v3);
        *(uint32_t*)(g_aoh + o_hi + nf * 8) = pack_bf2(h2, h3);
        *(uint32_t*)(g_aol + o_hi + nf * 8) = pack_bf2(
            __float2bfloat16_rn(v2 - __bfloat162float(h2)),
            __float2bfloat16_rn(v3 - __bfloat162float(h3)));
    }
}

// ===================== launcher =====================
extern "C" void kernel_launch(void* const* d_in, const int* in_sizes, int n_in,
                              void* d_out, int out_size)
{
    (void)in_sizes; (void)n_in; (void)out_size;
    const float* x1    = (const float*)d_in[0];
    const float* x2    = (const float*)d_in[1];
    const float* Wqkv1 = (const float*)d_in[4];
    const float* Wqkv2 = (const float*)d_in[5];
    const float* gq1   = (const float*)d_in[6];
    const float* gk1   = (const float*)d_in[7];
    const float* gq2   = (const float*)d_in[8];
    const float* gk2   = (const float*)d_in[9];
    const float* Wout1 = (const float*)d_in[10];
    const float* Wout2 = (const float*)d_in[11];
    float* out = (float*)d_out;

    cudaFuncSetAttribute(gemm_mma, cudaFuncAttributeMaxDynamicSharedMemorySize, GEMM_SMEM);
    cudaFuncSetAttribute(attn_mma, cudaFuncAttributeMaxDynamicSharedMemorySize, ATT_SMEM);

    void* p;
    cudaGetSymbolAddress(&p, g_x1h);  __nv_bfloat16* x1h = (__nv_bfloat16*)p;
    cudaGetSymbolAddress(&p, g_x1l);  __nv_bfloat16* x1l = (__nv_bfloat16*)p;
    cudaGetSymbolAddress(&p, g_x2h);  __nv_bfloat16* x2h = (__nv_bfloat16*)p;
    cudaGetSymbolAddress(&p, g_x2l);  __nv_bfloat16* x2l = (__nv_bfloat16*)p;
    cudaGetSymbolAddress(&p, g_w1h);  __nv_bfloat16* w1h = (__nv_bfloat16*)p;
    cudaGetSymbolAddress(&p, g_w1l);  __nv_bfloat16* w1l = (__nv_bfloat16*)p;
    cudaGetSymbolAddress(&p, g_w2h);  __nv_bfloat16* w2h = (__nv_bfloat16*)p;
    cudaGetSymbolAddress(&p, g_w2l);  __nv_bfloat16* w2l = (__nv_bfloat16*)p;
    cudaGetSymbolAddress(&p, g_wo1h); __nv_bfloat16* wo1h = (__nv_bfloat16*)p;
    cudaGetSymbolAddress(&p, g_wo1l); __nv_bfloat16* wo1l = (__nv_bfloat16*)p;
    cudaGetSymbolAddress(&p, g_wo2h); __nv_bfloat16* wo2h = (__nv_bfloat16*)p;
    cudaGetSymbolAddress(&p, g_wo2l); __nv_bfloat16* wo2l = (__nv_bfloat16*)p;
    cudaGetSymbolAddress(&p, g_qkv1); float* qkv1 = (float*)p;
    cudaGetSymbolAddress(&p, g_qkv2); float* qkv2 = (float*)p;
    cudaGetSymbolAddress(&p, g_aoh);  __nv_bfloat16* aoh = (__nv_bfloat16*)p;
    cudaGetSymbolAddress(&p, g_aol);  __nv_bfloat16* aol = (__nv_bfloat16*)p;

    const int BIG = 1 << 30;

    // 1) fused split of x1/x2
    split_all<<<SPLIT_B1 + SPLIT_B2, 256>>>(x1, x1h, x1l, x2, x2h, x2l);
    // 2) fused weight transposes
    wtrans_all<<<7168, 256>>>(Wqkv1, w1h, w1l, Wqkv2, w2h, w2l,
                              Wout1, wo1h, wo1l, Wout2, wo2h, wo2l);

    // 3) fused QKV projections (one launch, 960 blocks)
    {
        GemmJob j0 = { x1h, x1l, w1h, w1l, qkv1, D1, 3 * DI, BIG, 0, 0, 24, 24 * 32 };
        GemmJob j1 = { x2h, x2l, w2h, w2l, qkv2, D2, 3 * DI, BIG, 0, 0, 24, 24 * 8 };
        gemm_mma<<<j0.nblocks + j1.nblocks, 256, GEMM_SMEM>>>(j0, j1);
    }

    // 4) RMSNorm + scatter
    rmsnorm_scatter<<<BH * NTOT / 4, 128>>>(gq1, gk1, gq2, gk2);

    // 5) attention
    attn_mma<<<dim3(NTOT / 128, HEADS, BATCH), 256, ATT_SMEM>>>();

    // 6) fused output projections (one launch, 304 blocks)
    {
        GemmJob j0 = { aoh, aol, wo1h, wo1l, out, DI, D1, 2048, 512, 0, 8, 8 * 32 };
        GemmJob j1 = { aoh, aol, wo2h, wo2l, out + (size_t)BATCH * N1 * D1,
                       DI, D2, 512, 2048, 2048, 6, 6 * 8 };
        gemm_mma<<<j0.nblocks + j1.nblocks, 256, GEMM_SMEM>>>(j0, j1);
    }
}

// round 8
// speedup vs baseline: 6.1090x; 1.1620x over previous
#include <cuda_runtime.h>
#include <cuda_bf16.h>
#include <cuda_fp16.h>
#include <cstdint>
#include <math.h>

#define BATCH 2
#define N1 2048
#define N2 512
#define NTOT 2560
#define D1 1024
#define D2 768
#define HEADS 16
#define DH 64
#define DI 1024
#define BH (BATCH * HEADS)

// ===================== scratch (device globals) =====================
__device__ __align__(256) __nv_bfloat16 g_x1h[BATCH*N1*D1], g_x1l[BATCH*N1*D1];
__device__ __align__(256) __nv_bfloat16 g_x2h[BATCH*N2*D2], g_x2l[BATCH*N2*D2];
__device__ __align__(256) __nv_bfloat16 g_w1h[3*DI*D1],  g_w1l[3*DI*D1];
__device__ __align__(256) __nv_bfloat16 g_w2h[3*DI*D2],  g_w2l[3*DI*D2];
__device__ __align__(256) __nv_bfloat16 g_wo1h[D1*DI],   g_wo1l[D1*DI];
__device__ __align__(256) __nv_bfloat16 g_wo2h[D2*DI],   g_wo2l[D2*DI];
__device__ __align__(256) __half g_qh[BH*NTOT*DH], g_ql[BH*NTOT*DH];   // q fp16 hi/lo
__device__ __align__(256) __half g_kh[BH*NTOT*DH];                      // k fp16
__device__ __align__(256) __half g_vh[BH*NTOT*DH];                      // v fp16
__device__ __align__(256) __nv_bfloat16 g_aoh[BATCH*NTOT*DI], g_aol[BATCH*NTOT*DI];

// ===================== helpers =====================
__device__ __forceinline__ uint32_t smem_u32(const void* p) {
    uint32_t a;
    asm("{ .reg .u64 t; cvta.to.shared.u64 t, %1; cvt.u32.u64 %0, t; }" : "=r"(a) : "l"(p));
    return a;
}
__device__ __forceinline__ uint32_t pack_bf2(__nv_bfloat16 a, __nv_bfloat16 b) {
    return (uint32_t)__bfloat16_as_ushort(a) | ((uint32_t)__bfloat16_as_ushort(b) << 16);
}
__device__ __forceinline__ uint32_t pack_h2(float a, float b) {
    __half2 h = __floats2half2_rn(a, b);
    return *(uint32_t*)&h;
}
__device__ __forceinline__ uint32_t chunk_off(int r, int c) {
    return (uint32_t)(((r << 3) + (c ^ (r & 7))) << 4);
}
__device__ __forceinline__ void ldsm4(uint32_t (&d)[4], uint32_t a) {
    asm volatile("ldmatrix.sync.aligned.m8n8.x4.shared.b16 {%0,%1,%2,%3}, [%4];"
        : "=r"(d[0]), "=r"(d[1]), "=r"(d[2]), "=r"(d[3]) : "r"(a));
}
__device__ __forceinline__ void ldsm4t(uint32_t (&d)[4], uint32_t a) {
    asm volatile("ldmatrix.sync.aligned.m8n8.x4.trans.shared.b16 {%0,%1,%2,%3}, [%4];"
        : "=r"(d[0]), "=r"(d[1]), "=r"(d[2]), "=r"(d[3]) : "r"(a));
}
__device__ __forceinline__ void ldsmA(uint32_t (&d)[4], uint32_t tile, int row0, int k0, int lane) {
    int g = lane >> 3;
    int r = row0 + (lane & 7) + ((g & 1) << 3);
    int c = (k0 >> 3) + (g >> 1);
    ldsm4(d, tile + chunk_off(r, c));
}
__device__ __forceinline__ void ldsmB(uint32_t (&d)[4], uint32_t tile, int n0, int k0, int lane) {
    int g = lane >> 3;
    int r = n0 + (lane & 7) + ((g >> 1) << 3);
    int c = (k0 >> 3) + (g & 1);
    ldsm4(d, tile + chunk_off(r, c));
}
__device__ __forceinline__ void ldsmBT(uint32_t (&d)[4], uint32_t tile, int n0, int k0, int lane) {
    int g = lane >> 3;
    int r = k0 + (lane & 7) + ((g & 1) << 3);
    int c = (n0 >> 3) + (g >> 1);
    ldsm4t(d, tile + chunk_off(r, c));
}
__device__ __forceinline__ void mma16816(float (&c)[4], const uint32_t (&a)[4], const uint32_t* b) {
    asm volatile("mma.sync.aligned.m16n8k16.row.col.f32.bf16.bf16.f32 "
        "{%0,%1,%2,%3}, {%4,%5,%6,%7}, {%8,%9}, {%0,%1,%2,%3};"
        : "+f"(c[0]), "+f"(c[1]), "+f"(c[2]), "+f"(c[3])
        : "r"(a[0]), "r"(a[1]), "r"(a[2]), "r"(a[3]), "r"(b[0]), "r"(b[1]));
}
__device__ __forceinline__ void mma16816h(float (&c)[4], const uint32_t (&a)[4], const uint32_t* b) {
    asm volatile("mma.sync.aligned.m16n8k16.row.col.f32.f16.f16.f32 "
        "{%0,%1,%2,%3}, {%4,%5,%6,%7}, {%8,%9}, {%0,%1,%2,%3};"
        : "+f"(c[0]), "+f"(c[1]), "+f"(c[2]), "+f"(c[3])
        : "r"(a[0]), "r"(a[1]), "r"(a[2]), "r"(a[3]), "r"(b[0]), "r"(b[1]));
}
__device__ __forceinline__ float softclamp_exp(float s) {
    float u2 = s * s * 4.0e-4f;
    float cl = s * fmaf(u2, fmaf(u2, 0.13333334f, -0.33333334f), 1.0f);
    return __expf(cl - 8.0f);
}
#define CP16(dst, src) asm volatile("cp.async.cg.shared.global [%0], [%1], 16;" :: "r"(dst), "l"(src))
#define CP_COMMIT()    asm volatile("cp.async.commit_group;" ::: "memory")
#define CP_WAIT3()     asm volatile("cp.async.wait_group 3;" ::: "memory")
#define CP_WAIT2()     asm volatile("cp.async.wait_group 2;" ::: "memory")
#define CP_WAIT1()     asm volatile("cp.async.wait_group 1;" ::: "memory")
#define CP_WAIT0()     asm volatile("cp.async.wait_group 0;" ::: "memory")

// ===================== fused pre-pass: split x1 & x2 =====================
#define SPLIT_B1 ((BATCH * N1 * D1) / 1024)
#define SPLIT_B2 ((BATCH * N2 * D2) / 1024)
__global__ __launch_bounds__(256) void split_all(
    const float* __restrict__ x1, __nv_bfloat16* __restrict__ h1, __nv_bfloat16* __restrict__ l1,
    const float* __restrict__ x2, __nv_bfloat16* __restrict__ h2, __nv_bfloat16* __restrict__ l2)
{
    int bid = blockIdx.x;
    const float* in; __nv_bfloat16 *hi, *lo; int i;
    if (bid < SPLIT_B1) { in = x1; hi = h1; lo = l1; i = (bid * 256 + threadIdx.x) * 4; }
    else { in = x2; hi = h2; lo = l2; i = ((bid - SPLIT_B1) * 256 + threadIdx.x) * 4; }
    float4 v = *(const float4*)(in + i);
    __nv_bfloat16 h0 = __float2bfloat16_rn(v.x), hb1 = __float2bfloat16_rn(v.y);
    __nv_bfloat16 h2b = __float2bfloat16_rn(v.z), h3 = __float2bfloat16_rn(v.w);
    uint2 wh = make_uint2(pack_bf2(h0, hb1), pack_bf2(h2b, h3));
    uint2 wl = make_uint2(
        pack_bf2(__float2bfloat16_rn(v.x - __bfloat162float(h0)), __float2bfloat16_rn(v.y - __bfloat162float(hb1))),
        pack_bf2(__float2bfloat16_rn(v.z - __bfloat162float(h2b)), __float2bfloat16_rn(v.w - __bfloat162float(h3))));
    *(uint2*)(hi + i) = wh;
    *(uint2*)(lo + i) = wl;
}

// ===================== fused pre-pass: weight transposes =====================
__global__ __launch_bounds__(256) void wtrans_all(
    const float* __restrict__ W0, __nv_bfloat16* __restrict__ h0, __nv_bfloat16* __restrict__ l0,
    const float* __restrict__ W1, __nv_bfloat16* __restrict__ h1, __nv_bfloat16* __restrict__ l1,
    const float* __restrict__ W2, __nv_bfloat16* __restrict__ h2, __nv_bfloat16* __restrict__ l2,
    const float* __restrict__ W3, __nv_bfloat16* __restrict__ h3, __nv_bfloat16* __restrict__ l3)
{
    __shared__ float t[32][33];
    int bid = blockIdx.x;
    const float* W; __nv_bfloat16 *th, *tl; int K, N, nbx, local;
    if (bid < 3072)      { W = W0; th = h0; tl = l0; K = D1; N = 3 * DI; nbx = 96; local = bid; }
    else if (bid < 5376) { W = W1; th = h1; tl = l1; K = D2; N = 3 * DI; nbx = 96; local = bid - 3072; }
    else if (bid < 6400) { W = W2; th = h2; tl = l2; K = DI; N = D1;     nbx = 32; local = bid - 5376; }
    else                 { W = W3; th = h3; tl = l3; K = DI; N = D2;     nbx = 24; local = bid - 6400; }
    int n0 = (local % nbx) * 32, k0 = (local / nbx) * 32;
    int tx = threadIdx.x & 31, ty = threadIdx.x >> 5;
#pragma unroll
    for (int i = ty; i < 32; i += 8)
        t[i][tx] = W[(size_t)(k0 + i) * N + n0 + tx];
    __syncthreads();
#pragma unroll
    for (int i = ty; i < 32; i += 8) {
        float v = t[tx][i];
        __nv_bfloat16 h = __float2bfloat16_rn(v);
        size_t o = (size_t)(n0 + i) * K + k0 + tx;
        th[o] = h;
        tl[o] = __float2bfloat16_rn(v - __bfloat162float(h));
    }
}

// ===================== split-bf16 HMMA GEMM (dual-job, 3-stage) =============
// mode 0: store fp32 C. mode 1: fused rmsnorm epilogue -> q/k/v (fp16).
struct GemmJob {
    const __nv_bfloat16 *Ah, *Al, *Bh, *Bl;
    float* C;
    int K, N, chunk, pad, off, nbx, nblocks;
    int mode, Nseq, n_off;
    const float *gq, *gk;
};

#define GO_AH 0
#define GO_AL 16384
#define GO_BH 32768
#define GO_BL 49152
#define G_STAGE 65536
#define GEMM_SMEM (3 * G_STAGE)

__global__ __launch_bounds__(256) void gemm_mma(GemmJob j0, GemmJob j1)
{
    extern __shared__ char sm[];
    const uint32_t sb = smem_u32(sm);
    const int tid = threadIdx.x;
    const int lane = tid & 31;
    const int w = tid >> 5;
    const int wm = w & 3, wn = w >> 2;

    GemmJob j;
    int bid = blockIdx.x;
    if (bid < j0.nblocks) j = j0;
    else { j = j1; bid -= j0.nblocks; }
    const int bx = bid % j.nbx, by = bid / j.nbx;
    const int K = j.K, N = j.N;

    const int lr = tid >> 3;
    const int lc = tid & 7;

    auto issue = [&](int kt, int stage) {
        uint32_t base = sb + stage * G_STAGE;
#pragma unroll
        for (int i = 0; i < 4; i++) {
            int r = lr + i * 32;
            uint32_t so = chunk_off(r, lc);
            int gr = by * 128 + r;
            gr = gr + j.off + (gr / j.chunk) * j.pad;
            size_t ao = (size_t)gr * K + kt * 64 + lc * 8;
            CP16(base + GO_AH + so, j.Ah + ao);
            CP16(base + GO_AL + so, j.Al + ao);
            size_t bo = (size_t)(bx * 128 + r) * K + kt * 64 + lc * 8;
            CP16(base + GO_BH + so, j.Bh + bo);
            CP16(base + GO_BL + so, j.Bl + bo);
        }
        CP_COMMIT();
    };

    float acc[2][8][4];
#pragma unroll
    for (int i = 0; i < 2; i++)
#pragma unroll
        for (int jj = 0; jj < 8; jj++)
#pragma unroll
            for (int q = 0; q < 4; q++) acc[i][jj][q] = 0.0f;

    const int ktiles = K >> 6;
    issue(0, 0);
    issue(1, 1);

    for (int kt = 0; kt < ktiles; kt++) {
        int cur = kt - (kt / 3) * 3;
        if (kt + 2 < ktiles) { issue(kt + 2, (kt + 2) % 3); CP_WAIT2(); }
        else if (kt + 1 < ktiles) CP_WAIT1();
        else CP_WAIT0();
        __syncthreads();

        uint32_t tAH = sb + cur * G_STAGE + GO_AH;
        uint32_t tAL = sb + cur * G_STAGE + GO_AL;
        uint32_t tBH = sb + cur * G_STAGE + GO_BH;
        uint32_t tBL = sb + cur * G_STAGE + GO_BL;
#pragma unroll
        for (int ks = 0; ks < 4; ks++) {
            int k0 = ks * 16;
            uint32_t ahf[2][4], alf[2][4];
            ldsmA(ahf[0], tAH, wm * 32, k0, lane);
            ldsmA(ahf[1], tAH, wm * 32 + 16, k0, lane);
            ldsmA(alf[0], tAL, wm * 32, k0, lane);
            ldsmA(alf[1], tAL, wm * 32 + 16, k0, lane);
            uint32_t bhf[4][4], blf[4][4];
#pragma unroll
            for (int nb = 0; nb < 4; nb++) {
                ldsmB(bhf[nb], tBH, wn * 64 + nb * 16, k0, lane);
                ldsmB(blf[nb], tBL, wn * 64 + nb * 16, k0, lane);
            }
#pragma unroll
            for (int nb = 0; nb < 4; nb++)
#pragma unroll
                for (int mi = 0; mi < 2; mi++) {
                    mma16816(acc[mi][2 * nb],     ahf[mi], bhf[nb]);
                    mma16816(acc[mi][2 * nb + 1], ahf[mi], bhf[nb] + 2);
                }
#pragma unroll
            for (int nb = 0; nb < 4; nb++)
#pragma unroll
                for (int mi = 0; mi < 2; mi++) {
                    mma16816(acc[mi][2 * nb],     ahf[mi], blf[nb]);
                    mma16816(acc[mi][2 * nb + 1], ahf[mi], blf[nb] + 2);
                }
#pragma unroll
            for (int nb = 0; nb < 4; nb++)
#pragma unroll
                for (int mi = 0; mi < 2; mi++) {
                    mma16816(acc[mi][2 * nb],     alf[mi], bhf[nb]);
                    mma16816(acc[mi][2 * nb + 1], alf[mi], bhf[nb] + 2);
                }
        }
        __syncthreads();
    }

    if (j.mode == 0) {
#pragma unroll
        for (int mi = 0; mi < 2; mi++)
#pragma unroll
            for (int nf = 0; nf < 8; nf++) {
                int row = by * 128 + wm * 32 + mi * 16 + (lane >> 2);
                int col = bx * 128 + wn * 64 + nf * 8 + ((lane & 3) << 1);
                *(float2*)(j.C + (size_t)row * N + col) = make_float2(acc[mi][nf][0], acc[mi][nf][1]);
                *(float2*)(j.C + (size_t)(row + 8) * N + col) = make_float2(acc[mi][nf][2], acc[mi][nf][3]);
            }
    } else {
        // fused rmsnorm epilogue: warp tile = one head (64 cols)
        const int sec = bx >> 3;               // 0:q 1:k 2:v
        const int h = ((bx & 7) << 1) + wn;
        // gamma per lane-column (hoisted)
        float g0[8], g1[8];
        if (sec != 2) {
            const float* gam = (sec == 0) ? j.gq : j.gk;
#pragma unroll
            for (int nf = 0; nf < 8; nf++) {
                int col = nf * 8 + ((lane & 3) << 1);
                g0[nf] = gam[h * DH + col];
                g1[nf] = gam[h * DH + col + 1];
            }
        }
#pragma unroll
        for (int mi = 0; mi < 2; mi++)
#pragma unroll
            for (int half = 0; half < 2; half++) {
                int r = by * 128 + wm * 32 + mi * 16 + (lane >> 2) + half * 8;
                int b = r / j.Nseq, n = r - b * j.Nseq;
                size_t dst = ((size_t)(b * HEADS + h) * NTOT + j.n_off + n) * DH;
                float v0[8], v1[8];
#pragma unroll
                for (int nf = 0; nf < 8; nf++) {
                    v0[nf] = acc[mi][nf][half * 2];
                    v1[nf] = acc[mi][nf][half * 2 + 1];
                }
                if (sec == 2) {
#pragma unroll
                    for (int nf = 0; nf < 8; nf++) {
                        int col = nf * 8 + ((lane & 3) << 1);
                        *(uint32_t*)(g_vh + dst + col) = pack_h2(v0[nf], v1[nf]);
                    }
                } else {
                    float ss = 0.0f;
#pragma unroll
                    for (int nf = 0; nf < 8; nf++) ss += v0[nf] * v0[nf] + v1[nf] * v1[nf];
                    ss += __shfl_xor_sync(0xffffffffu, ss, 1);
                    ss += __shfl_xor_sync(0xffffffffu, ss, 2);
                    float scale = ((sec == 0) ? 1.0f : 8.0f) *
                                  __fdividef(1.0f, fmaxf(sqrtf(ss), 1e-12f));
                    if (sec == 0) {
#pragma unroll
                        for (int nf = 0; nf < 8; nf++) {
                            int col = nf * 8 + ((lane & 3) << 1);
                            float a = v0[nf] * scale * g0[nf];
                            float c = v1[nf] * scale * g1[nf];
                            __half ha = __float2half_rn(a), hc = __float2half_rn(c);
                            *(uint32_t*)(g_qh + dst + col) =
                                (uint32_t)__half_as_ushort(ha) | ((uint32_t)__half_as_ushort(hc) << 16);
                            *(uint32_t*)(g_ql + dst + col) =
                                pack_h2(a - __half2float(ha), c - __half2float(hc));
                        }
                    } else {
#pragma unroll
                        for (int nf = 0; nf < 8; nf++) {
                            int col = nf * 8 + ((lane & 3) << 1);
                            *(uint32_t*)(g_kh + dst + col) =
                                pack_h2(v0[nf] * scale * g0[nf], v1[nf] * scale * g1[nf]);
                        }
                    }
                }
            }
    }
}

// ===================== HMMA flash attention (fp16, 4-stage) =================
// 256 thr (8 warps), 128 q x 128 k, DH=64. QK: q split-2 fp16 x k fp16
// (2 MMAs); PV plain fp16. Fixed softmax max = 8.
#define AO_K 0
#define AO_V 16384
#define A_STAGE 32768
#define ATT_SMEM (4 * A_STAGE)

__global__ __launch_bounds__(256) void attn_mma()
{
    extern __shared__ char sm[];
    const uint32_t sb = smem_u32(sm);
    const int tid = threadIdx.x;
    const int lane = tid & 31;
    const int w = tid >> 5;
    const int qt = blockIdx.x, h = blockIdx.y, b = blockIdx.z;
    const int bh = b * HEADS + h;

    const size_t kbase = (size_t)bh * NTOT * DH;

    // ---- stage Q (hi/lo fp16) into first 32KB, extract frags ----
    uint32_t qhf[4][4], qlf[4][4];
    {
        const __half* qh = g_qh + kbase + (size_t)qt * 128 * DH;
        const __half* ql = g_ql + kbase + (size_t)qt * 128 * DH;
#pragma unroll
        for (int i = 0; i < 4; i++) {
            int idx = i * 256 + tid;
            int r = idx >> 3, c = idx & 7;
            uint32_t so = chunk_off(r, c);
            size_t go = (size_t)r * DH + c * 8;
            *(uint4*)(sm + 0 + so)     = *(const uint4*)(qh + go);
            *(uint4*)(sm + 16384 + so) = *(const uint4*)(ql + go);
        }
        __syncthreads();
#pragma unroll
        for (int ks = 0; ks < 4; ks++) {
            ldsmA(qhf[ks], sb + 0,     w * 16, ks * 16, lane);
            ldsmA(qlf[ks], sb + 16384, w * 16, ks * 16, lane);
        }
        __syncthreads();
    }

    const int lr = tid >> 3, lc = tid & 7;

    auto issue = [&](int kt, int stage) {
        uint32_t base = sb + stage * A_STAGE;
#pragma unroll
        for (int i = 0; i < 4; i++) {
            int r = lr + i * 32;
            uint32_t so = chunk_off(r, lc);
            size_t go = kbase + (size_t)(kt * 128 + r) * DH + lc * 8;
            CP16(base + AO_K + so, g_kh + go);
            CP16(base + AO_V + so, g_vh + go);
        }
        CP_COMMIT();
    };

    float O[8][4];
#pragma unroll
    for (int j = 0; j < 8; j++)
#pragma unroll
        for (int q = 0; q < 4; q++) O[j][q] = 0.0f;
    float lsum0 = 0.0f, lsum1 = 0.0f;

    const int ktiles = NTOT / 128;
    issue(0, 0);
    issue(1, 1);
    issue(2, 2);

    for (int kt = 0; kt < ktiles; kt++) {
        int cur = kt & 3;
        if (kt + 3 < ktiles) { issue(kt + 3, (kt + 3) & 3); CP_WAIT3(); }
        else if (kt + 2 < ktiles) CP_WAIT2();
        else if (kt + 1 < ktiles) CP_WAIT1();
        else CP_WAIT0();
        __syncthreads();

        uint32_t tK = sb + cur * A_STAGE + AO_K;
        uint32_t tV = sb + cur * A_STAGE + AO_V;

        // ---- S = Q K^T: (qh + ql) x k_fp16, term-major ----
        float S[16][4];
#pragma unroll
        for (int j = 0; j < 16; j++)
#pragma unroll
            for (int q = 0; q < 4; q++) S[j][q] = 0.0f;
#pragma unroll
        for (int ks = 0; ks < 4; ks++) {
            int k0 = ks * 16;
            uint32_t kf[8][4];
#pragma unroll
            for (int nb = 0; nb < 8; nb++)
                ldsmB(kf[nb], tK, nb * 16, k0, lane);
#pragma unroll
            for (int nb = 0; nb < 8; nb++) {
                mma16816h(S[2 * nb],     qhf[ks], kf[nb]);
                mma16816h(S[2 * nb + 1], qhf[ks], kf[nb] + 2);
            }
#pragma unroll
            for (int nb = 0; nb < 8; nb++) {
                mma16816h(S[2 * nb],     qlf[ks], kf[nb]);
                mma16816h(S[2 * nb + 1], qlf[ks], kf[nb] + 2);
            }
        }

        // ---- softclamp + exp (fixed max 8), row sums ----
        float rs0 = 0.0f, rs1 = 0.0f;
#pragma unroll
        for (int j = 0; j < 16; j++) {
            S[j][0] = softclamp_exp(S[j][0]); rs0 += S[j][0];
            S[j][1] = softclamp_exp(S[j][1]); rs0 += S[j][1];
            S[j][2] = softclamp_exp(S[j][2]); rs1 += S[j][2];
            S[j][3] = softclamp_exp(S[j][3]); rs1 += S[j][3];
        }
        rs0 += __shfl_xor_sync(0xffffffffu, rs0, 1);
        rs0 += __shfl_xor_sync(0xffffffffu, rs0, 2);
        rs1 += __shfl_xor_sync(0xffffffffu, rs1, 1);
        rs1 += __shfl_xor_sync(0xffffffffu, rs1, 2);
        lsum0 += rs0;
        lsum1 += rs1;

        // ---- O += P V (plain fp16, V via ldmatrix.trans) ----
#pragma unroll
        for (int kk = 0; kk < 8; kk++) {
            uint32_t pf[4];
#pragma unroll
            for (int q = 0; q < 4; q++) {
                float p0 = S[2 * kk + (q >> 1)][(q & 1) * 2];
                float p1 = S[2 * kk + (q >> 1)][(q & 1) * 2 + 1];
                pf[q] = pack_h2(p0, p1);
            }
#pragma unroll
            for (int nb = 0; nb < 4; nb++) {
                uint32_t vb[4];
                ldsmBT(vb, tV, nb * 16, kk * 16, lane);
                mma16816h(O[2 * nb],     pf, vb);
                mma16816h(O[2 * nb + 1], pf, vb + 2);
            }
        }
        __syncthreads();
    }

    // ---- epilogue: normalize, write split-bf16 to g_ao ----
    float inv0 = __fdividef(1.0f, lsum0);
    float inv1 = __fdividef(1.0f, lsum1);
    int rlo = qt * 128 + w * 16 + (lane >> 2);
    int colb = h * DH + ((lane & 3) << 1);
    size_t o_lo = ((size_t)(b * NTOT + rlo)) * DI + colb;
    size_t o_hi = ((size_t)(b * NTOT + rlo + 8)) * DI + colb;
#pragma unroll
    for (int nf = 0; nf < 8; nf++) {
        float v0 = O[nf][0] * inv0, v1 = O[nf][1] * inv0;
        __nv_bfloat16 h0 = __float2bfloat16_rn(v0), h1 = __float2bfloat16_rn(v1);
        *(uint32_t*)(g_aoh + o_lo + nf * 8) = pack_bf2(h0, h1);
        *(uint32_t*)(g_aol + o_lo + nf * 8) = pack_bf2(
            __float2bfloat16_rn(v0 - __bfloat162float(h0)),
            __float2bfloat16_rn(v1 - __bfloat162float(h1)));
        float v2 = O[nf][2] * inv1, v3 = O[nf][3] * inv1;
        __nv_bfloat16 h2 = __float2bfloat16_rn(v2), h3 = __float2bfloat16_rn(v3);
        *(uint32_t*)(g_aoh + o_hi + nf * 8) = pack_bf2(h2, h3);
        *(uint32_t*)(g_aol + o_hi + nf * 8) = pack_bf2(
            __float2bfloat16_rn(v2 - __bfloat162float(h2)),
            __float2bfloat16_rn(v3 - __bfloat162float(h3)));
    }
}

// ===================== launcher =====================
extern "C" void kernel_launch(void* const* d_in, const int* in_sizes, int n_in,
                              void* d_out, int out_size)
{
    (void)in_sizes; (void)n_in; (void)out_size;
    const float* x1    = (const float*)d_in[0];
    const float* x2    = (const float*)d_in[1];
    const float* Wqkv1 = (const float*)d_in[4];
    const float* Wqkv2 = (const float*)d_in[5];
    const float* gq1   = (const float*)d_in[6];
    const float* gk1   = (const float*)d_in[7];
    const float* gq2   = (const float*)d_in[8];
    const float* gk2   = (const float*)d_in[9];
    const float* Wout1 = (const float*)d_in[10];
    const float* Wout2 = (const float*)d_in[11];
    float* out = (float*)d_out;

    cudaFuncSetAttribute(gemm_mma, cudaFuncAttributeMaxDynamicSharedMemorySize, GEMM_SMEM);
    cudaFuncSetAttribute(attn_mma, cudaFuncAttributeMaxDynamicSharedMemorySize, ATT_SMEM);

    void* p;
    cudaGetSymbolAddress(&p, g_x1h);  __nv_bfloat16* x1h = (__nv_bfloat16*)p;
    cudaGetSymbolAddress(&p, g_x1l);  __nv_bfloat16* x1l = (__nv_bfloat16*)p;
    cudaGetSymbolAddress(&p, g_x2h);  __nv_bfloat16* x2h = (__nv_bfloat16*)p;
    cudaGetSymbolAddress(&p, g_x2l);  __nv_bfloat16* x2l = (__nv_bfloat16*)p;
    cudaGetSymbolAddress(&p, g_w1h);  __nv_bfloat16* w1h = (__nv_bfloat16*)p;
    cudaGetSymbolAddress(&p, g_w1l);  __nv_bfloat16* w1l = (__nv_bfloat16*)p;
    cudaGetSymbolAddress(&p, g_w2h);  __nv_bfloat16* w2h = (__nv_bfloat16*)p;
    cudaGetSymbolAddress(&p, g_w2l);  __nv_bfloat16* w2l = (__nv_bfloat16*)p;
    cudaGetSymbolAddress(&p, g_wo1h); __nv_bfloat16* wo1h = (__nv_bfloat16*)p;
    cudaGetSymbolAddress(&p, g_wo1l); __nv_bfloat16* wo1l = (__nv_bfloat16*)p;
    cudaGetSymbolAddress(&p, g_wo2h); __nv_bfloat16* wo2h = (__nv_bfloat16*)p;
    cudaGetSymbolAddress(&p, g_wo2l); __nv_bfloat16* wo2l = (__nv_bfloat16*)p;
    cudaGetSymbolAddress(&p, g_aoh);  __nv_bfloat16* aoh = (__nv_bfloat16*)p;
    cudaGetSymbolAddress(&p, g_aol);  __nv_bfloat16* aol = (__nv_bfloat16*)p;

    const int BIG = 1 << 30;

    // 1) fused split of x1/x2
    split_all<<<SPLIT_B1 + SPLIT_B2, 256>>>(x1, x1h, x1l, x2, x2h, x2l);
    // 2) fused weight transposes
    wtrans_all<<<7168, 256>>>(Wqkv1, w1h, w1l, Wqkv2, w2h, w2l,
                              Wout1, wo1h, wo1l, Wout2, wo2h, wo2l);

    // 3) fused QKV projections + rmsnorm epilogue (one launch, 960 blocks)
    {
        GemmJob j0 = { x1h, x1l, w1h, w1l, nullptr, D1, 3 * DI, BIG, 0, 0, 24, 24 * 32,
                       1, N1, 0, gq1, gk1 };
        GemmJob j1 = { x2h, x2l, w2h, w2l, nullptr, D2, 3 * DI, BIG, 0, 0, 24, 24 * 8,
                       1, N2, N1, gq2, gk2 };
        gemm_mma<<<j0.nblocks + j1.nblocks, 256, GEMM_SMEM>>>(j0, j1);
    }

    // 4) attention
    attn_mma<<<dim3(NTOT / 128, HEADS, BATCH), 256, ATT_SMEM>>>();

    // 5) fused output projections (one launch, 304 blocks)
    {
        GemmJob j0 = { aoh, aol, wo1h, wo1l, out, DI, D1, 2048, 512, 0, 8, 8 * 32,
                       0, 0, 0, nullptr, nullptr };
        GemmJob j1 = { aoh, aol, wo2h, wo2l, out + (size_t)BATCH * N1 * D1,
                       DI, D2, 512, 2048, 2048, 6, 6 * 8,
                       0, 0, 0, nullptr, nullptr };
        gemm_mma<<<j0.nblocks + j1.nblocks, 256, GEMM_SMEM>>>(j0, j1);
    }
}

// round 9
// speedup vs baseline: 7.8553x; 1.2859x over previous
#include <cuda_runtime.h>
#include <cuda_fp16.h>
#include <cstdint>
#include <math.h>

#define BATCH 2
#define N1 2048
#define N2 512
#define NTOT 2560
#define D1 1024
#define D2 768
#define HEADS 16
#define DH 64
#define DI 1024
#define BH (BATCH * HEADS)

// ===================== scratch (device globals, all fp16) =====================
__device__ __align__(256) __half g_x1h[BATCH*N1*D1], g_x1l[BATCH*N1*D1];
__device__ __align__(256) __half g_x2h[BATCH*N2*D2], g_x2l[BATCH*N2*D2];
__device__ __align__(256) __half g_w1[3*DI*D1];      // Wqkv1^T [3072][1024]
__device__ __align__(256) __half g_w2[3*DI*D2];      // Wqkv2^T [3072][768]
__device__ __align__(256) __half g_wo1[D1*DI];       // Wout1^T [1024][1024]
__device__ __align__(256) __half g_wo2[D2*DI];       // Wout2^T [768][1024]
__device__ __align__(256) __half g_qh[BH*NTOT*DH];   // q fp16 (norm+gamma+1/8)
__device__ __align__(256) __half g_kh[BH*NTOT*DH];   // k fp16 (norm*8+gamma)
__device__ __align__(256) __half g_vh[BH*NTOT*DH];   // v fp16
__device__ __align__(256) __half g_aoh[BATCH*NTOT*DI], g_aol[BATCH*NTOT*DI];

// ===================== helpers =====================
__device__ __forceinline__ uint32_t smem_u32(const void* p) {
    uint32_t a;
    asm("{ .reg .u64 t; cvta.to.shared.u64 t, %1; cvt.u32.u64 %0, t; }" : "=r"(a) : "l"(p));
    return a;
}
__device__ __forceinline__ uint32_t pack_h2(float a, float b) {
    __half2 h = __floats2half2_rn(a, b);
    return *(uint32_t*)&h;
}
__device__ __forceinline__ uint32_t chunk_off(int r, int c) {
    return (uint32_t)(((r << 3) + (c ^ (r & 7))) << 4);
}
__device__ __forceinline__ void ldsm4(uint32_t (&d)[4], uint32_t a) {
    asm volatile("ldmatrix.sync.aligned.m8n8.x4.shared.b16 {%0,%1,%2,%3}, [%4];"
        : "=r"(d[0]), "=r"(d[1]), "=r"(d[2]), "=r"(d[3]) : "r"(a));
}
__device__ __forceinline__ void ldsm4t(uint32_t (&d)[4], uint32_t a) {
    asm volatile("ldmatrix.sync.aligned.m8n8.x4.trans.shared.b16 {%0,%1,%2,%3}, [%4];"
        : "=r"(d[0]), "=r"(d[1]), "=r"(d[2]), "=r"(d[3]) : "r"(a));
}
__device__ __forceinline__ void ldsmA(uint32_t (&d)[4], uint32_t tile, int row0, int k0, int lane) {
    int g = lane >> 3;
    int r = row0 + (lane & 7) + ((g & 1) << 3);
    int c = (k0 >> 3) + (g >> 1);
    ldsm4(d, tile + chunk_off(r, c));
}
__device__ __forceinline__ void ldsmB(uint32_t (&d)[4], uint32_t tile, int n0, int k0, int lane) {
    int g = lane >> 3;
    int r = n0 + (lane & 7) + ((g >> 1) << 3);
    int c = (k0 >> 3) + (g & 1);
    ldsm4(d, tile + chunk_off(r, c));
}
__device__ __forceinline__ void ldsmBT(uint32_t (&d)[4], uint32_t tile, int n0, int k0, int lane) {
    int g = lane >> 3;
    int r = k0 + (lane & 7) + ((g & 1) << 3);
    int c = (n0 >> 3) + (g >> 1);
    ldsm4t(d, tile + chunk_off(r, c));
}
__device__ __forceinline__ void mma16816h(float (&c)[4], const uint32_t (&a)[4], const uint32_t* b) {
    asm volatile("mma.sync.aligned.m16n8k16.row.col.f32.f16.f16.f32 "
        "{%0,%1,%2,%3}, {%4,%5,%6,%7}, {%8,%9}, {%0,%1,%2,%3};"
        : "+f"(c[0]), "+f"(c[1]), "+f"(c[2]), "+f"(c[3])
        : "r"(a[0]), "r"(a[1]), "r"(a[2]), "r"(a[3]), "r"(b[0]), "r"(b[1]));
}
__device__ __forceinline__ float softclamp_exp(float s) {
    float u2 = s * s * 4.0e-4f;
    float cl = s * fmaf(u2, fmaf(u2, 0.13333334f, -0.33333334f), 1.0f);
    return __expf(cl - 8.0f);
}
#define CP16(dst, src) asm volatile("cp.async.cg.shared.global [%0], [%1], 16;" :: "r"(dst), "l"(src))
#define CP_COMMIT()    asm volatile("cp.async.commit_group;" ::: "memory")
#define CP_WAIT3()     asm volatile("cp.async.wait_group 3;" ::: "memory")
#define CP_WAIT2()     asm volatile("cp.async.wait_group 2;" ::: "memory")
#define CP_WAIT1()     asm volatile("cp.async.wait_group 1;" ::: "memory")
#define CP_WAIT0()     asm volatile("cp.async.wait_group 0;" ::: "memory")

// ===================== fused pre-pass: split x1 & x2 -> fp16 hi/lo ==========
#define SPLIT_B1 ((BATCH * N1 * D1) / 1024)
#define SPLIT_B2 ((BATCH * N2 * D2) / 1024)
__global__ __launch_bounds__(256) void split_all(
    const float* __restrict__ x1, __half* __restrict__ h1, __half* __restrict__ l1,
    const float* __restrict__ x2, __half* __restrict__ h2, __half* __restrict__ l2)
{
    int bid = blockIdx.x;
    const float* in; __half *hi, *lo; int i;
    if (bid < SPLIT_B1) { in = x1; hi = h1; lo = l1; i = (bid * 256 + threadIdx.x) * 4; }
    else { in = x2; hi = h2; lo = l2; i = ((bid - SPLIT_B1) * 256 + threadIdx.x) * 4; }
    float4 v = *(const float4*)(in + i);
    __half a0 = __float2half_rn(v.x), a1 = __float2half_rn(v.y);
    __half a2 = __float2half_rn(v.z), a3 = __float2half_rn(v.w);
    uint2 wh, wl;
    wh.x = (uint32_t)__half_as_ushort(a0) | ((uint32_t)__half_as_ushort(a1) << 16);
    wh.y = (uint32_t)__half_as_ushort(a2) | ((uint32_t)__half_as_ushort(a3) << 16);
    wl.x = pack_h2(v.x - __half2float(a0), v.y - __half2float(a1));
    wl.y = pack_h2(v.z - __half2float(a2), v.w - __half2float(a3));
    *(uint2*)(hi + i) = wh;
    *(uint2*)(lo + i) = wl;
}

// ===================== fused pre-pass: weight transposes -> fp16 ============
__global__ __launch_bounds__(256) void wtrans_all(
    const float* __restrict__ W0, __half* __restrict__ t0,
    const float* __restrict__ W1, __half* __restrict__ t1,
    const float* __restrict__ W2, __half* __restrict__ t2,
    const float* __restrict__ W3, __half* __restrict__ t3)
{
    __shared__ float t[32][33];
    int bid = blockIdx.x;
    const float* W; __half* th; int K, N, nbx, local;
    if (bid < 3072)      { W = W0; th = t0; K = D1; N = 3 * DI; nbx = 96; local = bid; }
    else if (bid < 5376) { W = W1; th = t1; K = D2; N = 3 * DI; nbx = 96; local = bid - 3072; }
    else if (bid < 6400) { W = W2; th = t2; K = DI; N = D1;     nbx = 32; local = bid - 5376; }
    else                 { W = W3; th = t3; K = DI; N = D2;     nbx = 24; local = bid - 6400; }
    int n0 = (local % nbx) * 32, k0 = (local / nbx) * 32;
    int tx = threadIdx.x & 31, ty = threadIdx.x >> 5;
#pragma unroll
    for (int i = ty; i < 32; i += 8)
        t[i][tx] = W[(size_t)(k0 + i) * N + n0 + tx];
    __syncthreads();
#pragma unroll
    for (int i = ty; i < 32; i += 8)
        th[(size_t)(n0 + i) * K + k0 + tx] = __float2half_rn(t[tx][i]);
}

// ===================== fp16 HMMA GEMM (A split-2, dual-job, 4-stage) ========
// mode 0: store fp32 C. mode 1: fused rmsnorm epilogue -> q/k/v (fp16).
struct GemmJob {
    const __half *Ah, *Al, *B;
    float* C;
    int K, N, chunk, pad, off, nbx, nblocks;
    int mode, Nseq, n_off;
    const float *gq, *gk;
};

#define GO_AH 0
#define GO_AL 16384
#define GO_B  32768
#define G_STAGE 49152
#define GEMM_SMEM (4 * G_STAGE)

__global__ __launch_bounds__(256) void gemm_mma(GemmJob j0, GemmJob j1)
{
    extern __shared__ char sm[];
    const uint32_t sb = smem_u32(sm);
    const int tid = threadIdx.x;
    const int lane = tid & 31;
    const int w = tid >> 5;
    const int wm = w & 3, wn = w >> 2;

    GemmJob j;
    int bid = blockIdx.x;
    if (bid < j0.nblocks) j = j0;
    else { j = j1; bid -= j0.nblocks; }
    const int bx = bid % j.nbx, by = bid / j.nbx;
    const int K = j.K, N = j.N;

    const int lr = tid >> 3;
    const int lc = tid & 7;

    auto issue = [&](int kt, int stage) {
        uint32_t base = sb + stage * G_STAGE;
#pragma unroll
        for (int i = 0; i < 4; i++) {
            int r = lr + i * 32;
            uint32_t so = chunk_off(r, lc);
            int gr = by * 128 + r;
            gr = gr + j.off + (gr / j.chunk) * j.pad;
            size_t ao = (size_t)gr * K + kt * 64 + lc * 8;
            CP16(base + GO_AH + so, j.Ah + ao);
            CP16(base + GO_AL + so, j.Al + ao);
            size_t bo = (size_t)(bx * 128 + r) * K + kt * 64 + lc * 8;
            CP16(base + GO_B + so, j.B + bo);
        }
        CP_COMMIT();
    };

    float acc[2][8][4];
#pragma unroll
    for (int i = 0; i < 2; i++)
#pragma unroll
        for (int jj = 0; jj < 8; jj++)
#pragma unroll
            for (int q = 0; q < 4; q++) acc[i][jj][q] = 0.0f;

    const int ktiles = K >> 6;
    issue(0, 0);
    issue(1, 1);
    issue(2, 2);

    for (int kt = 0; kt < ktiles; kt++) {
        int cur = kt & 3;
        if (kt + 3 < ktiles) { issue(kt + 3, (kt + 3) & 3); CP_WAIT3(); }
        else if (kt + 2 < ktiles) CP_WAIT2();
        else if (kt + 1 < ktiles) CP_WAIT1();
        else CP_WAIT0();
        __syncthreads();

        uint32_t tAH = sb + cur * G_STAGE + GO_AH;
        uint32_t tAL = sb + cur * G_STAGE + GO_AL;
        uint32_t tB  = sb + cur * G_STAGE + GO_B;
#pragma unroll
        for (int ks = 0; ks < 4; ks++) {
            int k0 = ks * 16;
            uint32_t ahf[2][4], alf[2][4];
            ldsmA(ahf[0], tAH, wm * 32, k0, lane);
            ldsmA(ahf[1], tAH, wm * 32 + 16, k0, lane);
            ldsmA(alf[0], tAL, wm * 32, k0, lane);
            ldsmA(alf[1], tAL, wm * 32 + 16, k0, lane);
            uint32_t bf[4][4];
#pragma unroll
            for (int nb = 0; nb < 4; nb++)
                ldsmB(bf[nb], tB, wn * 64 + nb * 16, k0, lane);
            // term-major: hi sweep then lo sweep (acc reuse distance 16)
#pragma unroll
            for (int nb = 0; nb < 4; nb++)
#pragma unroll
                for (int mi = 0; mi < 2; mi++) {
                    mma16816h(acc[mi][2 * nb],     ahf[mi], bf[nb]);
                    mma16816h(acc[mi][2 * nb + 1], ahf[mi], bf[nb] + 2);
                }
#pragma unroll
            for (int nb = 0; nb < 4; nb++)
#pragma unroll
                for (int mi = 0; mi < 2; mi++) {
                    mma16816h(acc[mi][2 * nb],     alf[mi], bf[nb]);
                    mma16816h(acc[mi][2 * nb + 1], alf[mi], bf[nb] + 2);
                }
        }
        __syncthreads();
    }

    if (j.mode == 0) {
#pragma unroll
        for (int mi = 0; mi < 2; mi++)
#pragma unroll
            for (int nf = 0; nf < 8; nf++) {
                int row = by * 128 + wm * 32 + mi * 16 + (lane >> 2);
                int col = bx * 128 + wn * 64 + nf * 8 + ((lane & 3) << 1);
                *(float2*)(j.C + (size_t)row * N + col) = make_float2(acc[mi][nf][0], acc[mi][nf][1]);
                *(float2*)(j.C + (size_t)(row + 8) * N + col) = make_float2(acc[mi][nf][2], acc[mi][nf][3]);
            }
    } else {
        // fused rmsnorm epilogue: warp tile = one head (64 cols)
        const int sec = bx >> 3;               // 0:q 1:k 2:v
        const int h = ((bx & 7) << 1) + wn;
        float g0[8], g1[8];
        if (sec != 2) {
            const float* gam = (sec == 0) ? j.gq : j.gk;
#pragma unroll
            for (int nf = 0; nf < 8; nf++) {
                int col = nf * 8 + ((lane & 3) << 1);
                g0[nf] = gam[h * DH + col];
                g1[nf] = gam[h * DH + col + 1];
            }
        }
#pragma unroll
        for (int mi = 0; mi < 2; mi++)
#pragma unroll
            for (int half = 0; half < 2; half++) {
                int r = by * 128 + wm * 32 + mi * 16 + (lane >> 2) + half * 8;
                int b = r / j.Nseq, n = r - b * j.Nseq;
                size_t dst = ((size_t)(b * HEADS + h) * NTOT + j.n_off + n) * DH;
                float v0[8], v1[8];
#pragma unroll
                for (int nf = 0; nf < 8; nf++) {
                    v0[nf] = acc[mi][nf][half * 2];
                    v1[nf] = acc[mi][nf][half * 2 + 1];
                }
                if (sec == 2) {
#pragma unroll
                    for (int nf = 0; nf < 8; nf++) {
                        int col = nf * 8 + ((lane & 3) << 1);
                        *(uint32_t*)(g_vh + dst + col) = pack_h2(v0[nf], v1[nf]);
                    }
                } else {
                    float ss = 0.0f;
#pragma unroll
                    for (int nf = 0; nf < 8; nf++) ss += v0[nf] * v0[nf] + v1[nf] * v1[nf];
                    ss += __shfl_xor_sync(0xffffffffu, ss, 1);
                    ss += __shfl_xor_sync(0xffffffffu, ss, 2);
                    float scale = ((sec == 0) ? 1.0f : 8.0f) *
                                  __fdividef(1.0f, fmaxf(sqrtf(ss), 1e-12f));
                    __half* dstp = (sec == 0) ? g_qh : g_kh;
#pragma unroll
                    for (int nf = 0; nf < 8; nf++) {
                        int col = nf * 8 + ((lane & 3) << 1);
                        *(uint32_t*)(dstp + dst + col) =
                            pack_h2(v0[nf] * scale * g0[nf], v1[nf] * scale * g1[nf]);
                    }
                }
            }
    }
}

// ===================== HMMA flash attention (fp16, 4-stage) =================
// 256 thr (8 warps), 128 q x 128 k, DH=64. QK plain fp16 (1 MMA term);
// PV plain fp16. Fixed softmax max = 8 (norms folded).
#define AO_K 0
#define AO_V 16384
#define A_STAGE 32768
#define ATT_SMEM (4 * A_STAGE)

__global__ __launch_bounds__(256) void attn_mma()
{
    extern __shared__ char sm[];
    const uint32_t sb = smem_u32(sm);
    const int tid = threadIdx.x;
    const int lane = tid & 31;
    const int w = tid >> 5;
    const int qt = blockIdx.x, h = blockIdx.y, b = blockIdx.z;
    const int bh = b * HEADS + h;

    const size_t kbase = (size_t)bh * NTOT * DH;

    // ---- stage Q into first 16KB, extract frags ----
    uint32_t qf[4][4];
    {
        const __half* qh = g_qh + kbase + (size_t)qt * 128 * DH;
#pragma unroll
        for (int i = 0; i < 4; i++) {
            int idx = i * 256 + tid;
            int r = idx >> 3, c = idx & 7;
            uint32_t so = chunk_off(r, c);
            *(uint4*)(sm + so) = *(const uint4*)(qh + (size_t)r * DH + c * 8);
        }
        __syncthreads();
#pragma unroll
        for (int ks = 0; ks < 4; ks++)
            ldsmA(qf[ks], sb, w * 16, ks * 16, lane);
        __syncthreads();
    }

    const int lr = tid >> 3, lc = tid & 7;

    auto issue = [&](int kt, int stage) {
        uint32_t base = sb + stage * A_STAGE;
#pragma unroll
        for (int i = 0; i < 4; i++) {
            int r = lr + i * 32;
            uint32_t so = chunk_off(r, lc);
            size_t go = kbase + (size_t)(kt * 128 + r) * DH + lc * 8;
            CP16(base + AO_K + so, g_kh + go);
            CP16(base + AO_V + so, g_vh + go);
        }
        CP_COMMIT();
    };

    float O[8][4];
#pragma unroll
    for (int j = 0; j < 8; j++)
#pragma unroll
        for (int q = 0; q < 4; q++) O[j][q] = 0.0f;
    float lsum0 = 0.0f, lsum1 = 0.0f;

    const int ktiles = NTOT / 128;
    issue(0, 0);
    issue(1, 1);
    issue(2, 2);

    for (int kt = 0; kt < ktiles; kt++) {
        int cur = kt & 3;
        if (kt + 3 < ktiles) { issue(kt + 3, (kt + 3) & 3); CP_WAIT3(); }
        else if (kt + 2 < ktiles) CP_WAIT2();
        else if (kt + 1 < ktiles) CP_WAIT1();
        else CP_WAIT0();
        __syncthreads();

        uint32_t tK = sb + cur * A_STAGE + AO_K;
        uint32_t tV = sb + cur * A_STAGE + AO_V;

        // ---- S = Q K^T (plain fp16) ----
        float S[16][4];
#pragma unroll
        for (int j = 0; j < 16; j++)
#pragma unroll
            for (int q = 0; q < 4; q++) S[j][q] = 0.0f;
#pragma unroll
        for (int ks = 0; ks < 4; ks++) {
            int k0 = ks * 16;
            uint32_t kf[8][4];
#pragma unroll
            for (int nb = 0; nb < 8; nb++)
                ldsmB(kf[nb], tK, nb * 16, k0, lane);
#pragma unroll
            for (int nb = 0; nb < 8; nb++) {
                mma16816h(S[2 * nb],     qf[ks], kf[nb]);
                mma16816h(S[2 * nb + 1], qf[ks], kf[nb] + 2);
            }
        }

        // ---- softclamp + exp (fixed max 8), row sums ----
        float rs0 = 0.0f, rs1 = 0.0f;
#pragma unroll
        for (int j = 0; j < 16; j++) {
            S[j][0] = softclamp_exp(S[j][0]); rs0 += S[j][0];
            S[j][1] = softclamp_exp(S[j][1]); rs0 += S[j][1];
            S[j][2] = softclamp_exp(S[j][2]); rs1 += S[j][2];
            S[j][3] = softclamp_exp(S[j][3]); rs1 += S[j][3];
        }
        rs0 += __shfl_xor_sync(0xffffffffu, rs0, 1);
        rs0 += __shfl_xor_sync(0xffffffffu, rs0, 2);
        rs1 += __shfl_xor_sync(0xffffffffu, rs1, 1);
        rs1 += __shfl_xor_sync(0xffffffffu, rs1, 2);
        lsum0 += rs0;
        lsum1 += rs1;

        // ---- O += P V (plain fp16, V via ldmatrix.trans) ----
#pragma unroll
        for (int kk = 0; kk < 8; kk++) {
            uint32_t pf[4];
#pragma unroll
            for (int q = 0; q < 4; q++) {
                float p0 = S[2 * kk + (q >> 1)][(q & 1) * 2];
                float p1 = S[2 * kk + (q >> 1)][(q & 1) * 2 + 1];
                pf[q] = pack_h2(p0, p1);
            }
#pragma unroll
            for (int nb = 0; nb < 4; nb++) {
                uint32_t vb[4];
                ldsmBT(vb, tV, nb * 16, kk * 16, lane);
                mma16816h(O[2 * nb],     pf, vb);
                mma16816h(O[2 * nb + 1], pf, vb + 2);
            }
        }
        __syncthreads();
    }

    // ---- epilogue: normalize, write fp16 hi/lo to g_ao ----
    float inv0 = __fdividef(1.0f, lsum0);
    float inv1 = __fdividef(1.0f, lsum1);
    int rlo = qt * 128 + w * 16 + (lane >> 2);
    int colb = h * DH + ((lane & 3) << 1);
    size_t o_lo = ((size_t)(b * NTOT + rlo)) * DI + colb;
    size_t o_hi = ((size_t)(b * NTOT + rlo + 8)) * DI + colb;
#pragma unroll
    for (int nf = 0; nf < 8; nf++) {
        float v0 = O[nf][0] * inv0, v1 = O[nf][1] * inv0;
        __half a0 = __float2half_rn(v0), a1 = __float2half_rn(v1);
        *(uint32_t*)(g_aoh + o_lo + nf * 8) =
            (uint32_t)__half_as_ushort(a0) | ((uint32_t)__half_as_ushort(a1) << 16);
        *(uint32_t*)(g_aol + o_lo + nf * 8) =
            pack_h2(v0 - __half2float(a0), v1 - __half2float(a1));
        float v2 = O[nf][2] * inv1, v3 = O[nf][3] * inv1;
        __half a2 = __float2half_rn(v2), a3 = __float2half_rn(v3);
        *(uint32_t*)(g_aoh + o_hi + nf * 8) =
            (uint32_t)__half_as_ushort(a2) | ((uint32_t)__half_as_ushort(a3) << 16);
        *(uint32_t*)(g_aol + o_hi + nf * 8) =
            pack_h2(v2 - __half2float(a2), v3 - __half2float(a3));
    }
}

// ===================== launcher =====================
extern "C" void kernel_launch(void* const* d_in, const int* in_sizes, int n_in,
                              void* d_out, int out_size)
{
    (void)in_sizes; (void)n_in; (void)out_size;
    const float* x1    = (const float*)d_in[0];
    const float* x2    = (const float*)d_in[1];
    const float* Wqkv1 = (const float*)d_in[4];
    const float* Wqkv2 = (const float*)d_in[5];
    const float* gq1   = (const float*)d_in[6];
    const float* gk1   = (const float*)d_in[7];
    const float* gq2   = (const float*)d_in[8];
    const float* gk2   = (const float*)d_in[9];
    const float* Wout1 = (const float*)d_in[10];
    const float* Wout2 = (const float*)d_in[11];
    float* out = (float*)d_out;

    cudaFuncSetAttribute(gemm_mma, cudaFuncAttributeMaxDynamicSharedMemorySize, GEMM_SMEM);
    cudaFuncSetAttribute(attn_mma, cudaFuncAttributeMaxDynamicSharedMemorySize, ATT_SMEM);

    void* p;
    cudaGetSymbolAddress(&p, g_x1h); __half* x1h = (__half*)p;
    cudaGetSymbolAddress(&p, g_x1l); __half* x1l = (__half*)p;
    cudaGetSymbolAddress(&p, g_x2h); __half* x2h = (__half*)p;
    cudaGetSymbolAddress(&p, g_x2l); __half* x2l = (__half*)p;
    cudaGetSymbolAddress(&p, g_w1);  __half* w1  = (__half*)p;
    cudaGetSymbolAddress(&p, g_w2);  __half* w2  = (__half*)p;
    cudaGetSymbolAddress(&p, g_wo1); __half* wo1 = (__half*)p;
    cudaGetSymbolAddress(&p, g_wo2); __half* wo2 = (__half*)p;
    cudaGetSymbolAddress(&p, g_aoh); __half* aoh = (__half*)p;
    cudaGetSymbolAddress(&p, g_aol); __half* aol = (__half*)p;

    const int BIG = 1 << 30;

    // 1) fused split of x1/x2 (fp16 hi/lo)
    split_all<<<SPLIT_B1 + SPLIT_B2, 256>>>(x1, x1h, x1l, x2, x2h, x2l);
    // 2) fused weight transposes (fp16)
    wtrans_all<<<7168, 256>>>(Wqkv1, w1, Wqkv2, w2, Wout1, wo1, Wout2, wo2);

    // 3) fused QKV projections + rmsnorm epilogue (one launch, 960 blocks)
    {
        GemmJob j0 = { x1h, x1l, w1, nullptr, D1, 3 * DI, BIG, 0, 0, 24, 24 * 32,
                       1, N1, 0, gq1, gk1 };
        GemmJob j1 = { x2h, x2l, w2, nullptr, D2, 3 * DI, BIG, 0, 0, 24, 24 * 8,
                       1, N2, N1, gq2, gk2 };
        gemm_mma<<<j0.nblocks + j1.nblocks, 256, GEMM_SMEM>>>(j0, j1);
    }

    // 4) attention
    attn_mma<<<dim3(NTOT / 128, HEADS, BATCH), 256, ATT_SMEM>>>();

    // 5) fused output projections (one launch, 304 blocks)
    {
        GemmJob j0 = { aoh, aol, wo1, out, DI, D1, 2048, 512, 0, 8, 8 * 32,
                       0, 0, 0, nullptr, nullptr };
        GemmJob j1 = { aoh, aol, wo2, out + (size_t)BATCH * N1 * D1,
                       DI, D2, 512, 2048, 2048, 6, 6 * 8,
                       0, 0, 0, nullptr, nullptr };
        gemm_mma<<<j0.nblocks + j1.nblocks, 256, GEMM_SMEM>>>(j0, j1);
    }
}

// round 10
// speedup vs baseline: 8.8843x; 1.1310x over previous
#include <cuda_runtime.h>
#include <cuda_fp16.h>
#include <cstdint>
#include <math.h>

#define BATCH 2
#define N1 2048
#define N2 512
#define NTOT 2560
#define D1 1024
#define D2 768
#define HEADS 16
#define DH 64
#define DI 1024
#define BH (BATCH * HEADS)

// ===================== scratch (device globals, all fp16) =====================
__device__ __align__(256) __half g_x1h[BATCH*N1*D1], g_x1l[BATCH*N1*D1];
__device__ __align__(256) __half g_x2h[BATCH*N2*D2], g_x2l[BATCH*N2*D2];
__device__ __align__(256) __half g_w1[3*DI*D1];
__device__ __align__(256) __half g_w2[3*DI*D2];
__device__ __align__(256) __half g_wo1[D1*DI];
__device__ __align__(256) __half g_wo2[D2*DI];
__device__ __align__(256) __half g_qh[BH*NTOT*DH];
__device__ __align__(256) __half g_kh[BH*NTOT*DH];
__device__ __align__(256) __half g_vh[BH*NTOT*DH];
__device__ __align__(256) __half g_aoh[BATCH*NTOT*DI], g_aol[BATCH*NTOT*DI];

// ===================== helpers =====================
__device__ __forceinline__ uint32_t smem_u32(const void* p) {
    uint32_t a;
    asm("{ .reg .u64 t; cvta.to.shared.u64 t, %1; cvt.u32.u64 %0, t; }" : "=r"(a) : "l"(p));
    return a;
}
__device__ __forceinline__ uint32_t pack_h2(float a, float b) {
    __half2 h = __floats2half2_rn(a, b);
    return *(uint32_t*)&h;
}
__device__ __forceinline__ uint32_t chunk_off(int r, int c) {
    return (uint32_t)(((r << 3) + (c ^ (r & 7))) << 4);
}
__device__ __forceinline__ void ldsm4(uint32_t (&d)[4], uint32_t a) {
    asm volatile("ldmatrix.sync.aligned.m8n8.x4.shared.b16 {%0,%1,%2,%3}, [%4];"
        : "=r"(d[0]), "=r"(d[1]), "=r"(d[2]), "=r"(d[3]) : "r"(a));
}
__device__ __forceinline__ void ldsm4t(uint32_t (&d)[4], uint32_t a) {
    asm volatile("ldmatrix.sync.aligned.m8n8.x4.trans.shared.b16 {%0,%1,%2,%3}, [%4];"
        : "=r"(d[0]), "=r"(d[1]), "=r"(d[2]), "=r"(d[3]) : "r"(a));
}
__device__ __forceinline__ void ldsmA(uint32_t (&d)[4], uint32_t tile, int row0, int k0, int lane) {
    int g = lane >> 3;
    int r = row0 + (lane & 7) + ((g & 1) << 3);
    int c = (k0 >> 3) + (g >> 1);
    ldsm4(d, tile + chunk_off(r, c));
}
__device__ __forceinline__ void ldsmB(uint32_t (&d)[4], uint32_t tile, int n0, int k0, int lane) {
    int g = lane >> 3;
    int r = n0 + (lane & 7) + ((g >> 1) << 3);
    int c = (k0 >> 3) + (g & 1);
    ldsm4(d, tile + chunk_off(r, c));
}
__device__ __forceinline__ void ldsmBT(uint32_t (&d)[4], uint32_t tile, int n0, int k0, int lane) {
    int g = lane >> 3;
    int r = k0 + (lane & 7) + ((g & 1) << 3);
    int c = (n0 >> 3) + (g >> 1);
    ldsm4t(d, tile + chunk_off(r, c));
}
__device__ __forceinline__ void mma16816h(float (&c)[4], const uint32_t (&a)[4], const uint32_t* b) {
    asm volatile("mma.sync.aligned.m16n8k16.row.col.f32.f16.f16.f32 "
        "{%0,%1,%2,%3}, {%4,%5,%6,%7}, {%8,%9}, {%0,%1,%2,%3};"
        : "+f"(c[0]), "+f"(c[1]), "+f"(c[2]), "+f"(c[3])
        : "r"(a[0]), "r"(a[1]), "r"(a[2]), "r"(a[3]), "r"(b[0]), "r"(b[1]));
}
// exp(50*tanh(s/50) - 8) with |s|<=8.5.
// y = s*(c2*s^4' + ...) folded: p = ex2( fma(s, fma(s2, fma(s2, A, B), C), D) )
// A = (2/15)*log2e*(4e-4)^2, B = -(1/3)*log2e*4e-4, C = log2e, D = -8*log2e
__device__ __forceinline__ float clexp(float s) {
    float s2 = s * s;
    float y = fmaf(s, fmaf(s2, fmaf(s2, 3.0777387e-8f, -1.9235934e-4f), 1.44269504f),
                   -11.54156036f);
    float r;
    asm("ex2.approx.f32 %0, %1;" : "=f"(r) : "f"(y));
    return r;
}
#define CP16(dst, src) asm volatile("cp.async.cg.shared.global [%0], [%1], 16;" :: "r"(dst), "l"(src))
#define CP_COMMIT()    asm volatile("cp.async.commit_group;" ::: "memory")
#define CP_WAIT2()     asm volatile("cp.async.wait_group 2;" ::: "memory")
#define CP_WAIT1()     asm volatile("cp.async.wait_group 1;" ::: "memory")
#define CP_WAIT0()     asm volatile("cp.async.wait_group 0;" ::: "memory")

// ===================== fused pre-pass: split x1 & x2 -> fp16 hi/lo ==========
#define SPLIT_B1 ((BATCH * N1 * D1) / 1024)
#define SPLIT_B2 ((BATCH * N2 * D2) / 1024)
__global__ __launch_bounds__(256) void split_all(
    const float* __restrict__ x1, __half* __restrict__ h1, __half* __restrict__ l1,
    const float* __restrict__ x2, __half* __restrict__ h2, __half* __restrict__ l2)
{
    int bid = blockIdx.x;
    const float* in; __half *hi, *lo; int i;
    if (bid < SPLIT_B1) { in = x1; hi = h1; lo = l1; i = (bid * 256 + threadIdx.x) * 4; }
    else { in = x2; hi = h2; lo = l2; i = ((bid - SPLIT_B1) * 256 + threadIdx.x) * 4; }
    float4 v = *(const float4*)(in + i);
    __half a0 = __float2half_rn(v.x), a1 = __float2half_rn(v.y);
    __half a2 = __float2half_rn(v.z), a3 = __float2half_rn(v.w);
    uint2 wh, wl;
    wh.x = (uint32_t)__half_as_ushort(a0) | ((uint32_t)__half_as_ushort(a1) << 16);
    wh.y = (uint32_t)__half_as_ushort(a2) | ((uint32_t)__half_as_ushort(a3) << 16);
    wl.x = pack_h2(v.x - __half2float(a0), v.y - __half2float(a1));
    wl.y = pack_h2(v.z - __half2float(a2), v.w - __half2float(a3));
    *(uint2*)(hi + i) = wh;
    *(uint2*)(lo + i) = wl;
}

// ===================== fused pre-pass: weight transposes -> fp16 ============
__global__ __launch_bounds__(256) void wtrans_all(
    const float* __restrict__ W0, __half* __restrict__ t0,
    const float* __restrict__ W1, __half* __restrict__ t1,
    const float* __restrict__ W2, __half* __restrict__ t2,
    const float* __restrict__ W3, __half* __restrict__ t3)
{
    __shared__ float t[32][33];
    int bid = blockIdx.x;
    const float* W; __half* th; int K, N, nbx, local;
    if (bid < 3072)      { W = W0; th = t0; K = D1; N = 3 * DI; nbx = 96; local = bid; }
    else if (bid < 5376) { W = W1; th = t1; K = D2; N = 3 * DI; nbx = 96; local = bid - 3072; }
    else if (bid < 6400) { W = W2; th = t2; K = DI; N = D1;     nbx = 32; local = bid - 5376; }
    else                 { W = W3; th = t3; K = DI; N = D2;     nbx = 24; local = bid - 6400; }
    int n0 = (local % nbx) * 32, k0 = (local / nbx) * 32;
    int tx = threadIdx.x & 31, ty = threadIdx.x >> 5;
#pragma unroll
    for (int i = ty; i < 32; i += 8)
        t[i][tx] = W[(size_t)(k0 + i) * N + n0 + tx];
    __syncthreads();
#pragma unroll
    for (int i = ty; i < 32; i += 8)
        th[(size_t)(n0 + i) * K + k0 + tx] = __float2half_rn(t[tx][i]);
}

// ===================== fp16 HMMA GEMM (A split-2, dual-job, 2-stage, 2 CTA/SM)
struct GemmJob {
    const __half *Ah, *Al, *B;
    float* C;
    int K, N, chunk, pad, off, nbx, nblocks;
    int mode, Nseq, n_off;
    const float *gq, *gk;
};

#define GO_AH 0
#define GO_AL 16384
#define GO_B  32768
#define G_STAGE 49152
#define GEMM_SMEM (2 * G_STAGE)

__global__ __launch_bounds__(256, 2) void gemm_mma(GemmJob j0, GemmJob j1)
{
    extern __shared__ char sm[];
    const uint32_t sb = smem_u32(sm);
    const int tid = threadIdx.x;
    const int lane = tid & 31;
    const int w = tid >> 5;
    const int wm = w & 3, wn = w >> 2;

    GemmJob j;
    int bid = blockIdx.x;
    if (bid < j0.nblocks) j = j0;
    else { j = j1; bid -= j0.nblocks; }
    const int bx = bid % j.nbx, by = bid / j.nbx;
    const int K = j.K, N = j.N;

    const int lr = tid >> 3;
    const int lc = tid & 7;

    auto issue = [&](int kt, int stage) {
        uint32_t base = sb + stage * G_STAGE;
#pragma unroll
        for (int i = 0; i < 4; i++) {
            int r = lr + i * 32;
            uint32_t so = chunk_off(r, lc);
            int gr = by * 128 + r;
            gr = gr + j.off + (gr / j.chunk) * j.pad;
            size_t ao = (size_t)gr * K + kt * 64 + lc * 8;
            CP16(base + GO_AH + so, j.Ah + ao);
            CP16(base + GO_AL + so, j.Al + ao);
            size_t bo = (size_t)(bx * 128 + r) * K + kt * 64 + lc * 8;
            CP16(base + GO_B + so, j.B + bo);
        }
        CP_COMMIT();
    };

    float acc[2][8][4];
#pragma unroll
    for (int i = 0; i < 2; i++)
#pragma unroll
        for (int jj = 0; jj < 8; jj++)
#pragma unroll
            for (int q = 0; q < 4; q++) acc[i][jj][q] = 0.0f;

    const int ktiles = K >> 6;
    issue(0, 0);
    issue(1, 1);

    for (int kt = 0; kt < ktiles; kt++) {
        int cur = kt & 1;
        if (kt + 1 < ktiles) CP_WAIT1();
        else CP_WAIT0();
        __syncthreads();

        uint32_t tAH = sb + cur * G_STAGE + GO_AH;
        uint32_t tAL = sb + cur * G_STAGE + GO_AL;
        uint32_t tB  = sb + cur * G_STAGE + GO_B;
#pragma unroll
        for (int ks = 0; ks < 4; ks++) {
            int k0 = ks * 16;
            uint32_t ahf[2][4], alf[2][4];
            ldsmA(ahf[0], tAH, wm * 32, k0, lane);
            ldsmA(ahf[1], tAH, wm * 32 + 16, k0, lane);
            ldsmA(alf[0], tAL, wm * 32, k0, lane);
            ldsmA(alf[1], tAL, wm * 32 + 16, k0, lane);
            uint32_t bf[4][4];
#pragma unroll
            for (int nb = 0; nb < 4; nb++)
                ldsmB(bf[nb], tB, wn * 64 + nb * 16, k0, lane);
#pragma unroll
            for (int nb = 0; nb < 4; nb++)
#pragma unroll
                for (int mi = 0; mi < 2; mi++) {
                    mma16816h(acc[mi][2 * nb],     ahf[mi], bf[nb]);
                    mma16816h(acc[mi][2 * nb + 1], ahf[mi], bf[nb] + 2);
                }
#pragma unroll
            for (int nb = 0; nb < 4; nb++)
#pragma unroll
                for (int mi = 0; mi < 2; mi++) {
                    mma16816h(acc[mi][2 * nb],     alf[mi], bf[nb]);
                    mma16816h(acc[mi][2 * nb + 1], alf[mi], bf[nb] + 2);
                }
        }
        __syncthreads();
        if (kt + 2 < ktiles) issue(kt + 2, cur);
    }

    if (j.mode == 0) {
#pragma unroll
        for (int mi = 0; mi < 2; mi++)
#pragma unroll
            for (int nf = 0; nf < 8; nf++) {
                int row = by * 128 + wm * 32 + mi * 16 + (lane >> 2);
                int col = bx * 128 + wn * 64 + nf * 8 + ((lane & 3) << 1);
                *(float2*)(j.C + (size_t)row * N + col) = make_float2(acc[mi][nf][0], acc[mi][nf][1]);
                *(float2*)(j.C + (size_t)(row + 8) * N + col) = make_float2(acc[mi][nf][2], acc[mi][nf][3]);
            }
    } else {
        // fused rmsnorm epilogue: warp tile = one head (64 cols)
        const int sec = bx >> 3;               // 0:q 1:k 2:v
        const int h = ((bx & 7) << 1) + wn;
        float g0[8], g1[8];
        if (sec != 2) {
            const float* gam = (sec == 0) ? j.gq : j.gk;
#pragma unroll
            for (int nf = 0; nf < 8; nf++) {
                int col = nf * 8 + ((lane & 3) << 1);
                g0[nf] = gam[h * DH + col];
                g1[nf] = gam[h * DH + col + 1];
            }
        }
#pragma unroll
        for (int mi = 0; mi < 2; mi++)
#pragma unroll
            for (int half = 0; half < 2; half++) {
                int r = by * 128 + wm * 32 + mi * 16 + (lane >> 2) + half * 8;
                int b = r / j.Nseq, n = r - b * j.Nseq;
                size_t dst = ((size_t)(b * HEADS + h) * NTOT + j.n_off + n) * DH;
                float v0[8], v1[8];
#pragma unroll
                for (int nf = 0; nf < 8; nf++) {
                    v0[nf] = acc[mi][nf][half * 2];
                    v1[nf] = acc[mi][nf][half * 2 + 1];
                }
                if (sec == 2) {
#pragma unroll
                    for (int nf = 0; nf < 8; nf++) {
                        int col = nf * 8 + ((lane & 3) << 1);
                        *(uint32_t*)(g_vh + dst + col) = pack_h2(v0[nf], v1[nf]);
                    }
                } else {
                    float ss = 0.0f;
#pragma unroll
                    for (int nf = 0; nf < 8; nf++) ss += v0[nf] * v0[nf] + v1[nf] * v1[nf];
                    ss += __shfl_xor_sync(0xffffffffu, ss, 1);
                    ss += __shfl_xor_sync(0xffffffffu, ss, 2);
                    float scale = ((sec == 0) ? 1.0f : 8.0f) *
                                  __fdividef(1.0f, fmaxf(sqrtf(ss), 1e-12f));
                    __half* dstp = (sec == 0) ? g_qh : g_kh;
#pragma unroll
                    for (int nf = 0; nf < 8; nf++) {
                        int col = nf * 8 + ((lane & 3) << 1);
                        *(uint32_t*)(dstp + dst + col) =
                            pack_h2(v0[nf] * scale * g0[nf], v1[nf] * scale * g1[nf]);
                    }
                }
            }
    }
}

// ===================== HMMA flash attention (fp16, 3-stage, 2 CTA/SM) =======
// 256 thr (8 warps), 128 q x 128 k, DH=64. QK plain fp16; PV plain fp16.
// Fixed softmax max = 8; row sums via ones-column MMA (no shuffles).
#define AO_K 0
#define AO_V 16384
#define A_STAGE 32768
#define ATT_SMEM (3 * A_STAGE)

__global__ __launch_bounds__(256, 2) void attn_mma()
{
    extern __shared__ char sm[];
    const uint32_t sb = smem_u32(sm);
    const int tid = threadIdx.x;
    const int lane = tid & 31;
    const int w = tid >> 5;
    const int qt = blockIdx.x, h = blockIdx.y, b = blockIdx.z;
    const int bh = b * HEADS + h;

    const size_t kbase = (size_t)bh * NTOT * DH;

    // ---- stage Q into first 16KB, extract frags ----
    uint32_t qf[4][4];
    {
        const __half* qh = g_qh + kbase + (size_t)qt * 128 * DH;
#pragma unroll
        for (int i = 0; i < 4; i++) {
            int idx = i * 256 + tid;
            int r = idx >> 3, c = idx & 7;
            uint32_t so = chunk_off(r, c);
            *(uint4*)(sm + so) = *(const uint4*)(qh + (size_t)r * DH + c * 8);
        }
        __syncthreads();
#pragma unroll
        for (int ks = 0; ks < 4; ks++)
            ldsmA(qf[ks], sb, w * 16, ks * 16, lane);
        __syncthreads();
    }

    const int lr = tid >> 3, lc = tid & 7;

    auto issue = [&](int kt, int stage) {
        uint32_t base = sb + stage * A_STAGE;
#pragma unroll
        for (int i = 0; i < 4; i++) {
            int r = lr + i * 32;
            uint32_t so = chunk_off(r, lc);
            size_t go = kbase + (size_t)(kt * 128 + r) * DH + lc * 8;
            CP16(base + AO_K + so, g_kh + go);
            CP16(base + AO_V + so, g_vh + go);
        }
        CP_COMMIT();
    };

    float O[8][4];
#pragma unroll
    for (int j = 0; j < 8; j++)
#pragma unroll
        for (int q = 0; q < 4; q++) O[j][q] = 0.0f;
    float L[4];
#pragma unroll
    for (int q = 0; q < 4; q++) L[q] = 0.0f;
    const uint32_t ones2[2] = { 0x3C003C00u, 0x3C003C00u };

    const int ktiles = NTOT / 128;
    issue(0, 0);
    issue(1, 1);

    for (int kt = 0; kt < ktiles; kt++) {
        int cur = kt - (kt / 3) * 3;
        if (kt + 2 < ktiles) { issue(kt + 2, (kt + 2) % 3); CP_WAIT2(); }
        else if (kt + 1 < ktiles) CP_WAIT1();
        else CP_WAIT0();
        __syncthreads();

        uint32_t tK = sb + cur * A_STAGE + AO_K;
        uint32_t tV = sb + cur * A_STAGE + AO_V;

        // ---- S = Q K^T (plain fp16) ----
        float S[16][4];
#pragma unroll
        for (int j = 0; j < 16; j++)
#pragma unroll
            for (int q = 0; q < 4; q++) S[j][q] = 0.0f;
#pragma unroll
        for (int ks = 0; ks < 4; ks++) {
            int k0 = ks * 16;
            uint32_t kf[8][4];
#pragma unroll
            for (int nb = 0; nb < 8; nb++)
                ldsmB(kf[nb], tK, nb * 16, k0, lane);
#pragma unroll
            for (int nb = 0; nb < 8; nb++) {
                mma16816h(S[2 * nb],     qf[ks], kf[nb]);
                mma16816h(S[2 * nb + 1], qf[ks], kf[nb] + 2);
            }
        }

        // ---- softclamp + exp (fixed max 8) ----
#pragma unroll
        for (int j = 0; j < 16; j++)
#pragma unroll
            for (int q = 0; q < 4; q++)
                S[j][q] = clexp(S[j][q]);

        // ---- O += P V; L += P @ ones (row sums, no shuffles) ----
#pragma unroll
        for (int kk = 0; kk < 8; kk++) {
            uint32_t pf[4];
#pragma unroll
            for (int q = 0; q < 4; q++) {
                float p0 = S[2 * kk + (q >> 1)][(q & 1) * 2];
                float p1 = S[2 * kk + (q >> 1)][(q & 1) * 2 + 1];
                pf[q] = pack_h2(p0, p1);
            }
            mma16816h(L, pf, ones2);
#pragma unroll
            for (int nb = 0; nb < 4; nb++) {
                uint32_t vb[4];
                ldsmBT(vb, tV, nb * 16, kk * 16, lane);
                mma16816h(O[2 * nb],     pf, vb);
                mma16816h(O[2 * nb + 1], pf, vb + 2);
            }
        }
        __syncthreads();
    }

    // ---- epilogue: normalize, write fp16 hi/lo to g_ao ----
    float inv0 = __fdividef(1.0f, L[0]);
    float inv1 = __fdividef(1.0f, L[2]);
    int rlo = qt * 128 + w * 16 + (lane >> 2);
    int colb = h * DH + ((lane & 3) << 1);
    size_t o_lo = ((size_t)(b * NTOT + rlo)) * DI + colb;
    size_t o_hi = ((size_t)(b * NTOT + rlo + 8)) * DI + colb;
#pragma unroll
    for (int nf = 0; nf < 8; nf++) {
        float v0 = O[nf][0] * inv0, v1 = O[nf][1] * inv0;
        __half a0 = __float2half_rn(v0), a1 = __float2half_rn(v1);
        *(uint32_t*)(g_aoh + o_lo + nf * 8) =
            (uint32_t)__half_as_ushort(a0) | ((uint32_t)__half_as_ushort(a1) << 16);
        *(uint32_t*)(g_aol + o_lo + nf * 8) =
            pack_h2(v0 - __half2float(a0), v1 - __half2float(a1));
        float v2 = O[nf][2] * inv1, v3 = O[nf][3] * inv1;
        __half a2 = __float2half_rn(v2), a3 = __float2half_rn(v3);
        *(uint32_t*)(g_aoh + o_hi + nf * 8) =
            (uint32_t)__half_as_ushort(a2) | ((uint32_t)__half_as_ushort(a3) << 16);
        *(uint32_t*)(g_aol + o_hi + nf * 8) =
            pack_h2(v2 - __half2float(a2), v3 - __half2float(a3));
    }
}

// ===================== launcher =====================
extern "C" void kernel_launch(void* const* d_in, const int* in_sizes, int n_in,
                              void* d_out, int out_size)
{
    (void)in_sizes; (void)n_in; (void)out_size;
    const float* x1    = (const float*)d_in[0];
    const float* x2    = (const float*)d_in[1];
    const float* Wqkv1 = (const float*)d_in[4];
    const float* Wqkv2 = (const float*)d_in[5];
    const float* gq1   = (const float*)d_in[6];
    const float* gk1   = (const float*)d_in[7];
    const float* gq2   = (const float*)d_in[8];
    const float* gk2   = (const float*)d_in[9];
    const float* Wout1 = (const float*)d_in[10];
    const float* Wout2 = (const float*)d_in[11];
    float* out = (float*)d_out;

    cudaFuncSetAttribute(gemm_mma, cudaFuncAttributeMaxDynamicSharedMemorySize, GEMM_SMEM);
    cudaFuncSetAttribute(attn_mma, cudaFuncAttributeMaxDynamicSharedMemorySize, ATT_SMEM);

    void* p;
    cudaGetSymbolAddress(&p, g_x1h); __half* x1h = (__half*)p;
    cudaGetSymbolAddress(&p, g_x1l); __half* x1l = (__half*)p;
    cudaGetSymbolAddress(&p, g_x2h); __half* x2h = (__half*)p;
    cudaGetSymbolAddress(&p, g_x2l); __half* x2l = (__half*)p;
    cudaGetSymbolAddress(&p, g_w1);  __half* w1  = (__half*)p;
    cudaGetSymbolAddress(&p, g_w2);  __half* w2  = (__half*)p;
    cudaGetSymbolAddress(&p, g_wo1); __half* wo1 = (__half*)p;
    cudaGetSymbolAddress(&p, g_wo2); __half* wo2 = (__half*)p;
    cudaGetSymbolAddress(&p, g_aoh); __half* aoh = (__half*)p;
    cudaGetSymbolAddress(&p, g_aol); __half* aol = (__half*)p;

    const int BIG = 1 << 30;

    // 1) fused split of x1/x2 (fp16 hi/lo)
    split_all<<<SPLIT_B1 + SPLIT_B2, 256>>>(x1, x1h, x1l, x2, x2h, x2l);
    // 2) fused weight transposes (fp16)
    wtrans_all<<<7168, 256>>>(Wqkv1, w1, Wqkv2, w2, Wout1, wo1, Wout2, wo2);

    // 3) fused QKV projections + rmsnorm epilogue (one launch, 960 blocks)
    {
        GemmJob j0 = { x1h, x1l, w1, nullptr, D1, 3 * DI, BIG, 0, 0, 24, 24 * 32,
                       1, N1, 0, gq1, gk1 };
        GemmJob j1 = { x2h, x2l, w2, nullptr, D2, 3 * DI, BIG, 0, 0, 24, 24 * 8,
                       1, N2, N1, gq2, gk2 };
        gemm_mma<<<j0.nblocks + j1.nblocks, 256, GEMM_SMEM>>>(j0, j1);
    }

    // 4) attention
    attn_mma<<<dim3(NTOT / 128, HEADS, BATCH), 256, ATT_SMEM>>>();

    // 5) fused output projections (one launch, 304 blocks)
    {
        GemmJob j0 = { aoh, aol, wo1, out, DI, D1, 2048, 512, 0, 8, 8 * 32,
                       0, 0, 0, nullptr, nullptr };
        GemmJob j1 = { aoh, aol, wo2, out + (size_t)BATCH * N1 * D1,
                       DI, D2, 512, 2048, 2048, 6, 6 * 8,
                       0, 0, 0, nullptr, nullptr };
        gemm_mma<<<j0.nblocks + j1.nblocks, 256, GEMM_SMEM>>>(j0, j1);
    }
}